// round 1
// baseline (speedup 1.0000x reference)
#include <cuda_runtime.h>
#include <math.h>

#define BATCH  32
#define SEQ    2048
#define DMODEL 256
#define HID    512
#define HID2   1024
#define INNER  1024
#define NTOK   (BATCH*SEQ)   // 65536
#define NC     16            // scan chunks
#define CLEN   (SEQ/NC)      // 128

// ---------------------------------------------------------------------------
// Scratch (static device globals; allocation inside kernel_launch is banned)
// ---------------------------------------------------------------------------
__device__ float g_xz   [(size_t)NTOK*HID2];   // 256 MB : [xh | z]
__device__ float g_xc   [(size_t)NTOK*HID];    // 128 MB
__device__ float g_gates[(size_t)NTOK*HID2];   // 256 MB : [rec | inp]
__device__ float g_alpha[(size_t)NTOK*HID];    // 128 MB
__device__ float g_betap[(size_t)NTOK*HID];    // 128 MB
__device__ float g_y    [(size_t)NTOK*HID];    // 128 MB : silu(z)*h
__device__ float g_out1 [(size_t)NTOK*DMODEL]; //  64 MB
__device__ float g_hs   [(size_t)NTOK*DMODEL]; //  64 MB
__device__ float g_ff1  [(size_t)NTOK*INNER];  // 256 MB
__device__ float g_ff2  [(size_t)NTOK*DMODEL]; //  64 MB
__device__ float g_cA   [BATCH*NC*HID];
__device__ float g_cB   [BATCH*NC*HID];
__device__ float g_carry[BATCH*NC*HID];

// ---------------------------------------------------------------------------
// SGEMM: C[M,N] = A[M,K] @ B[K,N] (+bias, +silu). 128x128 tile, BK=8, 8x8/thr.
// Requires M%128==0, N%128==0, K%8==0 (holds for all 5 calls).
// ---------------------------------------------------------------------------
__global__ __launch_bounds__(256)
void sgemm128(const float* __restrict__ A, const float* __restrict__ B,
              float* __restrict__ C, int M, int N, int K,
              const float* __restrict__ bias, int act)
{
    __shared__ __align__(16) float As[8][128];
    __shared__ __align__(16) float Bs[8][128];

    const int tid = threadIdx.x;
    const int tx  = tid & 15;          // 0..15 -> col group
    const int ty  = tid >> 4;          // 0..15 -> row group
    const long blockRow = (long)blockIdx.y * 128;
    const int  blockCol = blockIdx.x * 128;

    // A loader: row = tid>>1 (0..127), kcol = (tid&1)*4
    const float* Ag = A + (blockRow + (tid >> 1)) * K + ((tid & 1) << 2);
    // B loader: krow = tid>>5 (0..7), col = (tid&31)*4
    const float* Bg = B + (long)(tid >> 5) * N + blockCol + ((tid & 31) << 2);
    const int aK = (tid & 1) << 2;
    const int am = tid >> 1;
    const int bk = tid >> 5;
    const int bn = (tid & 31) << 2;

    float acc[8][8];
#pragma unroll
    for (int i = 0; i < 8; i++)
#pragma unroll
        for (int j = 0; j < 8; j++) acc[i][j] = 0.f;

    for (int k0 = 0; k0 < K; k0 += 8) {
        float4 av = *(const float4*)Ag; Ag += 8;
        float4 bv = *(const float4*)Bg; Bg += (long)8 * N;
        As[aK+0][am] = av.x; As[aK+1][am] = av.y;
        As[aK+2][am] = av.z; As[aK+3][am] = av.w;
        *(float4*)&Bs[bk][bn] = bv;
        __syncthreads();
#pragma unroll
        for (int k = 0; k < 8; k++) {
            float af[8], bf[8];
            *(float4*)(af)     = *(const float4*)&As[k][ty*8];
            *(float4*)(af + 4) = *(const float4*)&As[k][ty*8 + 4];
            *(float4*)(bf)     = *(const float4*)&Bs[k][tx*8];
            *(float4*)(bf + 4) = *(const float4*)&Bs[k][tx*8 + 4];
#pragma unroll
            for (int i = 0; i < 8; i++)
#pragma unroll
                for (int j = 0; j < 8; j++)
                    acc[i][j] = fmaf(af[i], bf[j], acc[i][j]);
        }
        __syncthreads();
    }

#pragma unroll
    for (int i = 0; i < 8; i++) {
        long row = blockRow + ty*8 + i;
        float* Crow = C + row * N + blockCol + tx*8;
        float out[8];
#pragma unroll
        for (int j = 0; j < 8; j++) {
            float v = acc[i][j];
            if (bias) v += bias[blockCol + tx*8 + j];
            if (act == 1) v = v / (1.f + expf(-v));   // silu
            out[j] = v;
        }
        *(float4*)(Crow)     = *(float4*)(out);
        *(float4*)(Crow + 4) = *(float4*)(out + 4);
    }
}

// ---------------------------------------------------------------------------
// Causal depthwise conv (K=4) + bias + silu : xh (cols 0..511 of g_xz) -> g_xc
// ---------------------------------------------------------------------------
__global__ void conv_silu_kernel(const float* __restrict__ conv_w,
                                 const float* __restrict__ conv_b)
{
    long idx = (long)blockIdx.x * blockDim.x + threadIdx.x;
    if (idx >= (long)NTOK * HID) return;
    int  h = (int)(idx % HID);
    long n = idx / HID;
    int  t = (int)(n % SEQ);
    long b = n / SEQ;
    float acc = conv_b[h];
#pragma unroll
    for (int k = 0; k < 4; k++) {
        int tt = t - 3 + k;
        if (tt >= 0)
            acc = fmaf(g_xz[((long)b*SEQ + tt)*HID2 + h], conv_w[h*4 + k], acc);
    }
    g_xc[idx] = acc / (1.f + expf(-acc));
}

// ---------------------------------------------------------------------------
// alpha / beta' from gates + xc + Lambda
// ---------------------------------------------------------------------------
__global__ void alphabeta_kernel(const float* __restrict__ Lambda)
{
    long idx = (long)blockIdx.x * blockDim.x + threadIdx.x;
    if (idx >= (long)NTOK * HID) return;
    int  h = (int)(idx % HID);
    long n = idx / HID;
    float rec = g_gates[n*HID2 + h];
    float inp = g_gates[n*HID2 + HID + h];
    float sp  = log1pf(expf(Lambda[h]));            // softplus(Lambda)
    float sr  = 1.f / (1.f + expf(-rec));
    float a   = expf(-sp * sr);
    float si  = 1.f / (1.f + expf(-inp));
    float beta = sqrtf(1.f - a*a + 1e-8f) * si;
    g_alpha[idx] = a;
    g_betap[idx] = beta * g_xc[idx];
}

// ---------------------------------------------------------------------------
// 3-phase chunked linear scan: h_t = a_t h_{t-1} + p_t
// ---------------------------------------------------------------------------
__global__ void scanA_kernel()
{
    int h = threadIdx.x;                 // 512
    int c = blockIdx.x % NC;
    int b = blockIdx.x / NC;
    long base = ((long)b*SEQ + c*CLEN)*HID + h;
    float A = 1.f, Bv = 0.f;
    for (int t = 0; t < CLEN; t++) {
        float a = g_alpha[base], p = g_betap[base];
        Bv = fmaf(a, Bv, p);
        A *= a;
        base += HID;
    }
    g_cA[(b*NC + c)*HID + h] = A;
    g_cB[(b*NC + c)*HID + h] = Bv;
}

__global__ void scanB_kernel()
{
    int h = threadIdx.x;                 // 512
    int b = blockIdx.x;                  // 32
    float carry = 0.f;
    for (int c = 0; c < NC; c++) {
        int i = (b*NC + c)*HID + h;
        g_carry[i] = carry;
        carry = fmaf(g_cA[i], carry, g_cB[i]);
    }
}

__global__ void scanC_kernel()
{
    int h = threadIdx.x;
    int c = blockIdx.x % NC;
    int b = blockIdx.x / NC;
    float hr = g_carry[(b*NC + c)*HID + h];
    long base  = ((long)b*SEQ + c*CLEN)*HID  + h;
    long zbase = ((long)b*SEQ + c*CLEN)*HID2 + HID + h;
    for (int t = 0; t < CLEN; t++) {
        float a = g_alpha[base], p = g_betap[base];
        hr = fmaf(a, hr, p);
        float z  = g_xz[zbase];
        float sz = z / (1.f + expf(-z));
        g_y[base] = sz * hr;
        base  += HID;
        zbase += HID2;
    }
}

// ---------------------------------------------------------------------------
// LayerNorm(a + r) * g + b   (D=256, one block per token)
// ---------------------------------------------------------------------------
__global__ __launch_bounds__(256)
void ln_kernel(const float* __restrict__ a, const float* __restrict__ r,
               const float* __restrict__ g, const float* __restrict__ bb,
               float* __restrict__ out)
{
    long n = blockIdx.x;
    int  h = threadIdx.x;
    float v = a[n*DMODEL + h] + r[n*DMODEL + h];

    __shared__ float sm[8];
    int lane = h & 31, wid = h >> 5;

    float s = v;
#pragma unroll
    for (int o = 16; o > 0; o >>= 1) s += __shfl_xor_sync(0xffffffffu, s, o);
    if (lane == 0) sm[wid] = s;
    __syncthreads();
    float tot = 0.f;
#pragma unroll
    for (int i = 0; i < 8; i++) tot += sm[i];
    float mean = tot * (1.f / DMODEL);
    float d = v - mean;
    __syncthreads();                       // before reusing sm

    float s2 = d * d;
#pragma unroll
    for (int o = 16; o > 0; o >>= 1) s2 += __shfl_xor_sync(0xffffffffu, s2, o);
    if (lane == 0) sm[wid] = s2;
    __syncthreads();
    float tot2 = 0.f;
#pragma unroll
    for (int i = 0; i < 8; i++) tot2 += sm[i];
    float var = tot2 * (1.f / DMODEL);

    out[n*DMODEL + h] = d * rsqrtf(var + 1e-12f) * g[h] + bb[h];
}

// ---------------------------------------------------------------------------
// Launch
// ---------------------------------------------------------------------------
extern "C" void kernel_launch(void* const* d_in, const int* in_sizes, int n_in,
                              void* d_out, int out_size)
{
    const float* x      = (const float*)d_in[0];
    const float* w_in   = (const float*)d_in[1];
    const float* conv_w = (const float*)d_in[2];
    const float* conv_b = (const float*)d_in[3];
    const float* w_gates= (const float*)d_in[4];
    const float* b_gates= (const float*)d_in[5];
    const float* Lambda = (const float*)d_in[6];
    const float* w_out  = (const float*)d_in[7];
    const float* ln1_g  = (const float*)d_in[8];
    const float* ln1_b  = (const float*)d_in[9];
    const float* ffn_w1 = (const float*)d_in[10];
    const float* ffn_b1 = (const float*)d_in[11];
    const float* ffn_w2 = (const float*)d_in[12];
    const float* ffn_b2 = (const float*)d_in[13];
    const float* ln2_g  = (const float*)d_in[14];
    const float* ln2_b  = (const float*)d_in[15];

    float *xz, *xc, *gates, *y, *out1, *hs, *ff1, *ff2;
    cudaGetSymbolAddress((void**)&xz,    g_xz);
    cudaGetSymbolAddress((void**)&xc,    g_xc);
    cudaGetSymbolAddress((void**)&gates, g_gates);
    cudaGetSymbolAddress((void**)&y,     g_y);
    cudaGetSymbolAddress((void**)&out1,  g_out1);
    cudaGetSymbolAddress((void**)&hs,    g_hs);
    cudaGetSymbolAddress((void**)&ff1,   g_ff1);
    cudaGetSymbolAddress((void**)&ff2,   g_ff2);

    const long nEH = (long)NTOK * HID;
    const int  ewBlocks = (int)((nEH + 255) / 256);

    // 1. xz = x @ w_in
    sgemm128<<<dim3(HID2/128, NTOK/128), 256>>>(x, w_in, xz, NTOK, HID2, DMODEL, nullptr, 0);
    // 2. depthwise causal conv + silu
    conv_silu_kernel<<<ewBlocks, 256>>>(conv_w, conv_b);
    // 3. gates = xc @ w_gates + b_gates
    sgemm128<<<dim3(HID2/128, NTOK/128), 256>>>(xc, w_gates, gates, NTOK, HID2, HID, b_gates, 0);
    // 4. alpha / beta'
    alphabeta_kernel<<<ewBlocks, 256>>>(Lambda);
    // 5-7. chunked scan, fused with y = silu(z) * h
    scanA_kernel<<<BATCH*NC, HID>>>();
    scanB_kernel<<<BATCH, HID>>>();
    scanC_kernel<<<BATCH*NC, HID>>>();
    // 8. out1 = y @ w_out
    sgemm128<<<dim3(DMODEL/128, NTOK/128), 256>>>(y, w_out, out1, NTOK, DMODEL, HID, nullptr, 0);
    // 9. hs = LN(out1 + x)
    ln_kernel<<<NTOK, DMODEL>>>(out1, x, ln1_g, ln1_b, hs);
    // 10. ff1 = silu(hs @ ffn_w1 + b1)
    sgemm128<<<dim3(INNER/128, NTOK/128), 256>>>(hs, ffn_w1, ff1, NTOK, INNER, DMODEL, ffn_b1, 1);
    // 11. ff2 = ff1 @ ffn_w2 + b2
    sgemm128<<<dim3(DMODEL/128, NTOK/128), 256>>>(ff1, ffn_w2, ff2, NTOK, DMODEL, INNER, ffn_b2, 0);
    // 12. out = LN(ff2 + hs)
    ln_kernel<<<NTOK, DMODEL>>>(ff2, hs, ln2_g, ln2_b, (float*)d_out);
}

// round 3
// speedup vs baseline: 2.2587x; 2.2587x over previous
#include <cuda_runtime.h>
#include <cuda_bf16.h>
#include <math.h>
#include <stdint.h>

#define BATCH  32
#define SEQ    2048
#define DMODEL 256
#define HID    512
#define HID2   1024
#define INNER  1024
#define NTOK   (BATCH*SEQ)   // 65536
#define NC     16
#define CLEN   (SEQ/NC)

// ---------------------------------------------------------------------------
// Scratch
// ---------------------------------------------------------------------------
__device__ float g_xz   [(size_t)NTOK*HID2];
__device__ float g_gates[(size_t)NTOK*HID2];
__device__ float g_alpha[(size_t)NTOK*HID];
__device__ float g_betap[(size_t)NTOK*HID];
__device__ float g_out1 [(size_t)NTOK*DMODEL];
__device__ float g_hs   [(size_t)NTOK*DMODEL];
__device__ float g_ff2  [(size_t)NTOK*DMODEL];
__device__ float g_cA   [BATCH*NC*HID];
__device__ float g_cB   [BATCH*NC*HID];
__device__ float g_carry[BATCH*NC*HID];
__device__ float g_splam[HID];

// bf16 hi/lo operand arrays
__device__ __align__(256) __nv_bfloat16 g_xh [(size_t)NTOK*DMODEL];
__device__ __align__(256) __nv_bfloat16 g_xl [(size_t)NTOK*DMODEL];
__device__ __align__(256) __nv_bfloat16 g_xch[(size_t)NTOK*HID];
__device__ __align__(256) __nv_bfloat16 g_xcl[(size_t)NTOK*HID];
__device__ __align__(256) __nv_bfloat16 g_yh [(size_t)NTOK*HID];
__device__ __align__(256) __nv_bfloat16 g_yl [(size_t)NTOK*HID];
__device__ __align__(256) __nv_bfloat16 g_hsh[(size_t)NTOK*DMODEL];
__device__ __align__(256) __nv_bfloat16 g_hsl[(size_t)NTOK*DMODEL];
__device__ __align__(256) __nv_bfloat16 g_f1h[(size_t)NTOK*INNER];
__device__ __align__(256) __nv_bfloat16 g_f1l[(size_t)NTOK*INNER];
// transposed weights [N,K]
__device__ __align__(256) __nv_bfloat16 g_wiT_h[HID2*DMODEL];
__device__ __align__(256) __nv_bfloat16 g_wiT_l[HID2*DMODEL];
__device__ __align__(256) __nv_bfloat16 g_wgT_h[HID2*HID];
__device__ __align__(256) __nv_bfloat16 g_wgT_l[HID2*HID];
__device__ __align__(256) __nv_bfloat16 g_woT_h[DMODEL*HID];
__device__ __align__(256) __nv_bfloat16 g_woT_l[DMODEL*HID];
__device__ __align__(256) __nv_bfloat16 g_f1T_h[INNER*DMODEL];
__device__ __align__(256) __nv_bfloat16 g_f1T_l[INNER*DMODEL];
__device__ __align__(256) __nv_bfloat16 g_f2T_h[DMODEL*INNER];
__device__ __align__(256) __nv_bfloat16 g_f2T_l[DMODEL*INNER];

// ---------------------------------------------------------------------------
// helpers
// ---------------------------------------------------------------------------
__device__ __forceinline__ uint32_t smem_u32(const void* p){
    uint32_t a;
    asm("{ .reg .u64 t; cvta.to.shared.u64 t, %1; cvt.u32.u64 %0, t; }"
        : "=r"(a) : "l"(p));
    return a;
}
__device__ __forceinline__ void cp_async16(uint32_t dst, const void* src){
    asm volatile("cp.async.cg.shared.global [%0], [%1], 16;" :: "r"(dst), "l"(src));
}
__device__ __forceinline__ void cp_commit(){ asm volatile("cp.async.commit_group;"); }

#define LDSM4(R, A) \
    asm volatile("ldmatrix.sync.aligned.m8n8.x4.shared.b16 {%0,%1,%2,%3}, [%4];" \
        : "=r"((R)[0]),"=r"((R)[1]),"=r"((R)[2]),"=r"((R)[3]) : "r"(A))

#define MMA_BF16(C, A, B0, B1) \
    asm volatile("mma.sync.aligned.m16n8k16.row.col.f32.bf16.bf16.f32 " \
        "{%0,%1,%2,%3},{%4,%5,%6,%7},{%8,%9},{%0,%1,%2,%3};" \
        : "+f"((C)[0]),"+f"((C)[1]),"+f"((C)[2]),"+f"((C)[3]) \
        : "r"((A)[0]),"r"((A)[1]),"r"((A)[2]),"r"((A)[3]),"r"(B0),"r"(B1))

__device__ __forceinline__ void split2(float v, __nv_bfloat16& h, __nv_bfloat16& l){
    h = __float2bfloat16(v);
    l = __float2bfloat16(v - __bfloat162float(h));
}

// ---------------------------------------------------------------------------
// bf16x3 compensated GEMM via mma.sync: C[M,N] = (Ah+Al)[M,K] @ (Bh+Bl)[N,K]^T
// block 128x128, 8 warps (2x4), warp tile 64x32, BK=32, cp.async double buffer
// ---------------------------------------------------------------------------
#define BK    32
#define PROW  80                 // padded row bytes (40 bf16)
#define SZ_T  (128*PROW)         // 10240 B per operand tile
#define OFF_AH 0
#define OFF_AL (SZ_T)
#define OFF_BH (2*SZ_T)
#define OFF_BL (3*SZ_T)
#define STAGE  (4*SZ_T)          // 40960
#define GEMM_SMEM (2*STAGE)      // 81920

__global__ __launch_bounds__(256)
void mma_gemm(const __nv_bfloat16* __restrict__ Ah, const __nv_bfloat16* __restrict__ Al,
              const __nv_bfloat16* __restrict__ Bh, const __nv_bfloat16* __restrict__ Bl,
              int M, int N, int K,
              const float* __restrict__ bias, int act,
              float* __restrict__ Cf,
              __nv_bfloat16* __restrict__ Ch, __nv_bfloat16* __restrict__ Cl)
{
    extern __shared__ __align__(128) char smem[];
    const uint32_t sb = smem_u32(smem);
    const int tid = threadIdx.x;
    const int wid = tid >> 5, lid = tid & 31;
    const long brow = (long)blockIdx.y * 128;
    const long bcol = (long)blockIdx.x * 128;

    const int wm = wid >> 2;          // 0..1 -> 64 rows
    const int wn = wid & 3;           // 0..3 -> 32 cols
    const int rowBase = wm * 64;
    const int colBase = wn * 32;

    float acc[4][4][4];
#pragma unroll
    for (int a = 0; a < 4; a++)
#pragma unroll
        for (int b = 0; b < 4; b++)
#pragma unroll
            for (int c = 0; c < 4; c++) acc[a][b][c] = 0.f;

    const int nch = K / BK;

    // stage loader
    auto load_stage = [&](int s, int cidx){
        const uint32_t base = sb + s * STAGE;
        const long kc = (long)cidx * BK;
#pragma unroll 2
        for (int i = tid; i < 512; i += 256) {
            const int row = i >> 2, ch = i & 3;
            const uint32_t d = row * PROW + ch * 16;
            const long gA = (brow + row) * (long)K + kc + ch * 8;
            const long gB = (bcol + row) * (long)K + kc + ch * 8;
            cp_async16(base + OFF_AH + d, Ah + gA);
            cp_async16(base + OFF_AL + d, Al + gA);
            cp_async16(base + OFF_BH + d, Bh + gB);
            cp_async16(base + OFF_BL + d, Bl + gB);
        }
        cp_commit();
    };

    load_stage(0, 0);

    const int g = lid >> 3, r = lid & 7;

    for (int c = 0; c < nch; c++) {
        if (c + 1 < nch) load_stage((c + 1) & 1, c + 1);
        if (c + 1 < nch) asm volatile("cp.async.wait_group 1;" ::: "memory");
        else             asm volatile("cp.async.wait_group 0;" ::: "memory");
        __syncthreads();

        const uint32_t st = sb + (c & 1) * STAGE;
#pragma unroll
        for (int ks = 0; ks < 2; ks++) {
            const int k0 = ks * 16;
            // B fragments: pair p covers ni {2p, 2p+1}
            uint32_t bh[2][4], bl[2][4];
#pragma unroll
            for (int p = 0; p < 2; p++) {
                const uint32_t boff =
                    (uint32_t)(colBase + p*16 + ((g >> 1) << 3) + r) * PROW
                    + (uint32_t)(k0 + ((g & 1) << 3)) * 2;
                LDSM4(bh[p], st + OFF_BH + boff);
                LDSM4(bl[p], st + OFF_BL + boff);
            }
#pragma unroll
            for (int mi = 0; mi < 4; mi++) {
                const uint32_t aoff =
                    (uint32_t)(rowBase + mi*16 + r + ((g & 1) << 3)) * PROW
                    + (uint32_t)(k0 + ((g >> 1) << 3)) * 2;
                uint32_t ah[4], al[4];
                LDSM4(ah, st + OFF_AH + aoff);
                LDSM4(al, st + OFF_AL + aoff);
#pragma unroll
                for (int ni = 0; ni < 4; ni++) {
                    const int p = ni >> 1, q = (ni & 1) * 2;
                    MMA_BF16(acc[mi][ni], ah, bh[p][q], bh[p][q+1]);
                    MMA_BF16(acc[mi][ni], ah, bl[p][q], bl[p][q+1]);
                    MMA_BF16(acc[mi][ni], al, bh[p][q], bh[p][q+1]);
                }
            }
        }
        __syncthreads();
    }

    // epilogue
    const int gID = lid >> 2, tig = lid & 3;
#pragma unroll
    for (int mi = 0; mi < 4; mi++) {
#pragma unroll
        for (int ni = 0; ni < 4; ni++) {
            const long col  = bcol + colBase + ni*8 + tig*2;
            float b0 = 0.f, b1 = 0.f;
            if (bias) { b0 = __ldg(&bias[col]); b1 = __ldg(&bias[col+1]); }
#pragma unroll
            for (int half = 0; half < 2; half++) {
                const long row = brow + rowBase + mi*16 + gID + half*8;
                float v0 = acc[mi][ni][half*2]   + b0;
                float v1 = acc[mi][ni][half*2+1] + b1;
                if (act == 1) {
                    v0 = v0 / (1.f + __expf(-v0));
                    v1 = v1 / (1.f + __expf(-v1));
                }
                if (Cf) *(float2*)&Cf[row * N + col] = make_float2(v0, v1);
                if (Ch) {
                    __nv_bfloat16 h0, l0, h1, l1;
                    split2(v0, h0, l0); split2(v1, h1, l1);
                    *(__nv_bfloat162*)&Ch[row * N + col] = __halves2bfloat162(h0, h1);
                    *(__nv_bfloat162*)&Cl[row * N + col] = __halves2bfloat162(l0, l1);
                }
            }
        }
    }
}

// ---------------------------------------------------------------------------
// Elementwise kernels
// ---------------------------------------------------------------------------
__global__ void splam_kernel(const float* __restrict__ Lambda)
{
    int h = threadIdx.x;
    g_splam[h] = log1pf(expf(Lambda[h]));
}

__global__ void split_kernel(const float* __restrict__ in, long n,
                             __nv_bfloat16* __restrict__ oh, __nv_bfloat16* __restrict__ ol)
{
    long i = (long)blockIdx.x * blockDim.x + threadIdx.x;
    if (i >= n) return;
    __nv_bfloat16 h, l;
    split2(in[i], h, l);
    oh[i] = h; ol[i] = l;
}

__global__ void wtsplit_kernel(const float* __restrict__ W, int K, int N,
                               __nv_bfloat16* __restrict__ Th, __nv_bfloat16* __restrict__ Tl)
{
    long i = (long)blockIdx.x * blockDim.x + threadIdx.x;
    if (i >= (long)K * N) return;
    int n = (int)(i % N);
    long k = i / N;
    __nv_bfloat16 h, l;
    split2(W[i], h, l);
    Th[(long)n * K + k] = h;
    Tl[(long)n * K + k] = l;
}

__global__ void conv_silu_kernel(const float* __restrict__ conv_w,
                                 const float* __restrict__ conv_b)
{
    long idx = (long)blockIdx.x * blockDim.x + threadIdx.x;
    if (idx >= (long)NTOK * HID) return;
    int  h = (int)(idx % HID);
    long n = idx / HID;
    int  t = (int)(n % SEQ);
    long b = n / SEQ;
    float acc = conv_b[h];
#pragma unroll
    for (int k = 0; k < 4; k++) {
        int tt = t - 3 + k;
        if (tt >= 0)
            acc = fmaf(g_xz[((long)b*SEQ + tt)*HID2 + h], conv_w[h*4 + k], acc);
    }
    float v = acc / (1.f + __expf(-acc));
    __nv_bfloat16 hh, ll;
    split2(v, hh, ll);
    g_xch[idx] = hh; g_xcl[idx] = ll;
}

__global__ void alphabeta_kernel()
{
    long i4 = (long)blockIdx.x * blockDim.x + threadIdx.x;
    if (i4 >= (long)NTOK * HID / 4) return;
    int  h4 = (int)(i4 % (HID/4)) * 4;
    long n  = i4 / (HID/4);
    float4 rec = *(const float4*)&g_gates[n*HID2 + h4];
    float4 inp = *(const float4*)&g_gates[n*HID2 + HID + h4];
    long xb = n*HID + h4;
    __nv_bfloat162 xh0 = *(const __nv_bfloat162*)&g_xch[xb];
    __nv_bfloat162 xh1 = *(const __nv_bfloat162*)&g_xch[xb+2];
    __nv_bfloat162 xl0 = *(const __nv_bfloat162*)&g_xcl[xb];
    __nv_bfloat162 xl1 = *(const __nv_bfloat162*)&g_xcl[xb+2];
    float xc[4] = {
        __bfloat162float(xh0.x) + __bfloat162float(xl0.x),
        __bfloat162float(xh0.y) + __bfloat162float(xl0.y),
        __bfloat162float(xh1.x) + __bfloat162float(xl1.x),
        __bfloat162float(xh1.y) + __bfloat162float(xl1.y)};
    float r[4] = {rec.x, rec.y, rec.z, rec.w};
    float p[4] = {inp.x, inp.y, inp.z, inp.w};
    float4 oa, ob;
    float* poa = &oa.x; float* pob = &ob.x;
#pragma unroll
    for (int j = 0; j < 4; j++) {
        float sp = g_splam[h4 + j];
        float sr = 1.f / (1.f + __expf(-r[j]));
        float a  = __expf(-sp * sr);
        float si = 1.f / (1.f + __expf(-p[j]));
        float beta = sqrtf(1.f - a*a + 1e-8f) * si;
        poa[j] = a;
        pob[j] = beta * xc[j];
    }
    *(float4*)&g_alpha[xb] = oa;
    *(float4*)&g_betap[xb] = ob;
}

__global__ void scanA_kernel()
{
    int h = threadIdx.x;
    int c = blockIdx.x % NC;
    int b = blockIdx.x / NC;
    long base = ((long)b*SEQ + c*CLEN)*HID + h;
    float A = 1.f, Bv = 0.f;
    for (int t = 0; t < CLEN; t++) {
        float a = g_alpha[base], p = g_betap[base];
        Bv = fmaf(a, Bv, p);
        A *= a;
        base += HID;
    }
    g_cA[(b*NC + c)*HID + h] = A;
    g_cB[(b*NC + c)*HID + h] = Bv;
}

__global__ void scanB_kernel()
{
    int h = threadIdx.x;
    int b = blockIdx.x;
    float carry = 0.f;
    for (int c = 0; c < NC; c++) {
        int i = (b*NC + c)*HID + h;
        g_carry[i] = carry;
        carry = fmaf(g_cA[i], carry, g_cB[i]);
    }
}

__global__ void scanC_kernel()
{
    int h = threadIdx.x;
    int c = blockIdx.x % NC;
    int b = blockIdx.x / NC;
    float hr = g_carry[(b*NC + c)*HID + h];
    long base  = ((long)b*SEQ + c*CLEN)*HID  + h;
    long zbase = ((long)b*SEQ + c*CLEN)*HID2 + HID + h;
    for (int t = 0; t < CLEN; t++) {
        float a = g_alpha[base], p = g_betap[base];
        hr = fmaf(a, hr, p);
        float z  = g_xz[zbase];
        float sz = z / (1.f + __expf(-z));
        float y  = sz * hr;
        __nv_bfloat16 hh, ll;
        split2(y, hh, ll);
        g_yh[base] = hh; g_yl[base] = ll;
        base  += HID;
        zbase += HID2;
    }
}

__global__ __launch_bounds__(256)
void ln_kernel(const float* __restrict__ a, const float* __restrict__ r,
               const float* __restrict__ g, const float* __restrict__ bb,
               float* __restrict__ out,
               __nv_bfloat16* __restrict__ oh, __nv_bfloat16* __restrict__ ol)
{
    long n = blockIdx.x;
    int  h = threadIdx.x;
    float v = a[n*DMODEL + h] + r[n*DMODEL + h];

    __shared__ float sm[8];
    int lane = h & 31, wid = h >> 5;

    float s = v;
#pragma unroll
    for (int o = 16; o > 0; o >>= 1) s += __shfl_xor_sync(0xffffffffu, s, o);
    if (lane == 0) sm[wid] = s;
    __syncthreads();
    float tot = 0.f;
#pragma unroll
    for (int i = 0; i < 8; i++) tot += sm[i];
    float mean = tot * (1.f / DMODEL);
    float d = v - mean;
    __syncthreads();

    float s2 = d * d;
#pragma unroll
    for (int o = 16; o > 0; o >>= 1) s2 += __shfl_xor_sync(0xffffffffu, s2, o);
    if (lane == 0) sm[wid] = s2;
    __syncthreads();
    float tot2 = 0.f;
#pragma unroll
    for (int i = 0; i < 8; i++) tot2 += sm[i];
    float var = tot2 * (1.f / DMODEL);

    float o_ = d * rsqrtf(var + 1e-12f) * g[h] + bb[h];
    out[n*DMODEL + h] = o_;
    if (oh) {
        __nv_bfloat16 hh, ll;
        split2(o_, hh, ll);
        oh[n*DMODEL + h] = hh;
        ol[n*DMODEL + h] = ll;
    }
}

// ---------------------------------------------------------------------------
// Launch
// ---------------------------------------------------------------------------
extern "C" void kernel_launch(void* const* d_in, const int* in_sizes, int n_in,
                              void* d_out, int out_size)
{
    const float* x      = (const float*)d_in[0];
    const float* w_in   = (const float*)d_in[1];
    const float* conv_w = (const float*)d_in[2];
    const float* conv_b = (const float*)d_in[3];
    const float* w_gates= (const float*)d_in[4];
    const float* b_gates= (const float*)d_in[5];
    const float* Lambda = (const float*)d_in[6];
    const float* w_out  = (const float*)d_in[7];
    const float* ln1_g  = (const float*)d_in[8];
    const float* ln1_b  = (const float*)d_in[9];
    const float* ffn_w1 = (const float*)d_in[10];
    const float* ffn_b1 = (const float*)d_in[11];
    const float* ffn_w2 = (const float*)d_in[12];
    const float* ffn_b2 = (const float*)d_in[13];
    const float* ln2_g  = (const float*)d_in[14];
    const float* ln2_b  = (const float*)d_in[15];

    static bool attr_set = false;
    if (!attr_set) {
        cudaFuncSetAttribute(mma_gemm, cudaFuncAttributeMaxDynamicSharedMemorySize, GEMM_SMEM);
        attr_set = true;
    }

    float *xz, *gates, *out1, *hs, *ff2;
    cudaGetSymbolAddress((void**)&xz,    g_xz);
    cudaGetSymbolAddress((void**)&gates, g_gates);
    cudaGetSymbolAddress((void**)&out1,  g_out1);
    cudaGetSymbolAddress((void**)&hs,    g_hs);
    cudaGetSymbolAddress((void**)&ff2,   g_ff2);
    __nv_bfloat16 *xh,*xl,*xch,*xcl,*yh,*yl,*hsh,*hsl,*f1h,*f1l;
    __nv_bfloat16 *wiTh,*wiTl,*wgTh,*wgTl,*woTh,*woTl,*f1Th,*f1Tl,*f2Th,*f2Tl;
    cudaGetSymbolAddress((void**)&xh,  g_xh);  cudaGetSymbolAddress((void**)&xl,  g_xl);
    cudaGetSymbolAddress((void**)&xch, g_xch); cudaGetSymbolAddress((void**)&xcl, g_xcl);
    cudaGetSymbolAddress((void**)&yh,  g_yh);  cudaGetSymbolAddress((void**)&yl,  g_yl);
    cudaGetSymbolAddress((void**)&hsh, g_hsh); cudaGetSymbolAddress((void**)&hsl, g_hsl);
    cudaGetSymbolAddress((void**)&f1h, g_f1h); cudaGetSymbolAddress((void**)&f1l, g_f1l);
    cudaGetSymbolAddress((void**)&wiTh, g_wiT_h); cudaGetSymbolAddress((void**)&wiTl, g_wiT_l);
    cudaGetSymbolAddress((void**)&wgTh, g_wgT_h); cudaGetSymbolAddress((void**)&wgTl, g_wgT_l);
    cudaGetSymbolAddress((void**)&woTh, g_woT_h); cudaGetSymbolAddress((void**)&woTl, g_woT_l);
    cudaGetSymbolAddress((void**)&f1Th, g_f1T_h); cudaGetSymbolAddress((void**)&f1Tl, g_f1T_l);
    cudaGetSymbolAddress((void**)&f2Th, g_f2T_h); cudaGetSymbolAddress((void**)&f2Tl, g_f2T_l);

    const long nED = (long)NTOK * DMODEL;
    const long nEH = (long)NTOK * HID;

    splam_kernel<<<1, HID>>>(Lambda);
    split_kernel<<<(int)((nED + 255)/256), 256>>>(x, nED, xh, xl);
    wtsplit_kernel<<<(DMODEL*HID2 + 255)/256, 256>>>(w_in,   DMODEL, HID2,   wiTh, wiTl);
    wtsplit_kernel<<<(HID*HID2   + 255)/256, 256>>>(w_gates, HID,    HID2,   wgTh, wgTl);
    wtsplit_kernel<<<(HID*DMODEL + 255)/256, 256>>>(w_out,   HID,    DMODEL, woTh, woTl);
    wtsplit_kernel<<<(DMODEL*INNER+255)/256, 256>>>(ffn_w1,  DMODEL, INNER,  f1Th, f1Tl);
    wtsplit_kernel<<<(INNER*DMODEL+255)/256, 256>>>(ffn_w2,  INNER,  DMODEL, f2Th, f2Tl);

    // 1. xz = x @ w_in
    mma_gemm<<<dim3(HID2/128, NTOK/128), 256, GEMM_SMEM>>>(
        xh, xl, wiTh, wiTl, NTOK, HID2, DMODEL, nullptr, 0, xz, nullptr, nullptr);
    // 2. conv + silu -> xc hi/lo
    conv_silu_kernel<<<(int)((nEH + 255)/256), 256>>>(conv_w, conv_b);
    // 3. gates = xc @ w_gates + b_gates
    mma_gemm<<<dim3(HID2/128, NTOK/128), 256, GEMM_SMEM>>>(
        xch, xcl, wgTh, wgTl, NTOK, HID2, HID, b_gates, 0, gates, nullptr, nullptr);
    // 4. alpha / beta'
    alphabeta_kernel<<<(int)((nEH/4 + 255)/256), 256>>>();
    // 5-7. scan (+ y = silu(z)*h, split)
    scanA_kernel<<<BATCH*NC, HID>>>();
    scanB_kernel<<<BATCH, HID>>>();
    scanC_kernel<<<BATCH*NC, HID>>>();
    // 8. out1 = y @ w_out
    mma_gemm<<<dim3(DMODEL/128, NTOK/128), 256, GEMM_SMEM>>>(
        yh, yl, woTh, woTl, NTOK, DMODEL, HID, nullptr, 0, out1, nullptr, nullptr);
    // 9. hs = LN(out1 + x)  (+ split)
    ln_kernel<<<NTOK, DMODEL>>>(out1, x, ln1_g, ln1_b, hs, hsh, hsl);
    // 10. ff1 = silu(hs @ ffn_w1 + b1) -> hi/lo only
    mma_gemm<<<dim3(INNER/128, NTOK/128), 256, GEMM_SMEM>>>(
        hsh, hsl, f1Th, f1Tl, NTOK, INNER, DMODEL, ffn_b1, 1, nullptr, f1h, f1l);
    // 11. ff2 = ff1 @ ffn_w2 + b2
    mma_gemm<<<dim3(DMODEL/128, NTOK/128), 256, GEMM_SMEM>>>(
        f1h, f1l, f2Th, f2Tl, NTOK, DMODEL, INNER, ffn_b2, 0, ff2, nullptr, nullptr);
    // 12. out = LN(ff2 + hs)
    ln_kernel<<<NTOK, DMODEL>>>(ff2, hs, ln2_g, ln2_b, (float*)d_out, nullptr, nullptr);
}

// round 4
// speedup vs baseline: 3.0323x; 1.3425x over previous
#include <cuda_runtime.h>
#include <cuda_bf16.h>
#include <math.h>
#include <stdint.h>

#define BATCH  32
#define SEQ    2048
#define DMODEL 256
#define HID    512
#define HID2   1024
#define INNER  1024
#define NTOK   (BATCH*SEQ)   // 65536
#define NC     16
#define CLEN   (SEQ/NC)

// ---------------------------------------------------------------------------
// Scratch (fp32 everywhere; GEMM operands pre-rounded to tf32 via cvt.rna)
// ---------------------------------------------------------------------------
__device__ float g_xz   [(size_t)NTOK*HID2];   // [xh | z]
__device__ float g_xc   [(size_t)NTOK*HID];    // rounded (GEMM operand + betap)
__device__ float g_alpha[(size_t)NTOK*HID];
__device__ float g_betap[(size_t)NTOK*HID];
__device__ float g_y    [(size_t)NTOK*HID];    // rounded
__device__ float g_out1 [(size_t)NTOK*DMODEL];
__device__ float g_hs   [(size_t)NTOK*DMODEL]; // rounded
__device__ float g_ff1  [(size_t)NTOK*INNER];  // rounded
__device__ float g_ff2  [(size_t)NTOK*DMODEL];
__device__ float g_xr   [(size_t)NTOK*DMODEL]; // rounded copy of x
__device__ float g_cA   [BATCH*NC*HID];
__device__ float g_cB   [BATCH*NC*HID];
__device__ float g_carry[BATCH*NC*HID];
__device__ float g_splam[HID];
__device__ float g_bil  [HID2];                // interleaved gates bias
// transposed (rounded) weights [N,K]
__device__ __align__(256) float g_wiT[HID2*DMODEL];
__device__ __align__(256) float g_wgT[HID2*HID];   // column-interleaved rec/inp
__device__ __align__(256) float g_woT[DMODEL*HID];
__device__ __align__(256) float g_f1T[INNER*DMODEL];
__device__ __align__(256) float g_f2T[DMODEL*INNER];

// ---------------------------------------------------------------------------
// helpers
// ---------------------------------------------------------------------------
__device__ __forceinline__ uint32_t smem_u32(const void* p){
    uint32_t a;
    asm("{ .reg .u64 t; cvta.to.shared.u64 t, %1; cvt.u32.u64 %0, t; }"
        : "=r"(a) : "l"(p));
    return a;
}
__device__ __forceinline__ void cp_async16(uint32_t dst, const void* src){
    asm volatile("cp.async.cg.shared.global [%0], [%1], 16;" :: "r"(dst), "l"(src));
}
__device__ __forceinline__ void cp_commit(){ asm volatile("cp.async.commit_group;"); }

__device__ __forceinline__ float rna_tf32(float v){
    uint32_t o;
    asm("cvt.rna.tf32.f32 %0, %1;" : "=r"(o) : "f"(v));
    return __uint_as_float(o);
}

#define LDSM4(R, A) \
    asm volatile("ldmatrix.sync.aligned.m8n8.x4.shared.b16 {%0,%1,%2,%3}, [%4];" \
        : "=r"((R)[0]),"=r"((R)[1]),"=r"((R)[2]),"=r"((R)[3]) : "r"(A))

#define MMA_TF32(C, A, B0, B1) \
    asm volatile("mma.sync.aligned.m16n8k8.row.col.f32.tf32.tf32.f32 " \
        "{%0,%1,%2,%3},{%4,%5,%6,%7},{%8,%9},{%0,%1,%2,%3};" \
        : "+f"((C)[0]),"+f"((C)[1]),"+f"((C)[2]),"+f"((C)[3]) \
        : "r"((A)[0]),"r"((A)[1]),"r"((A)[2]),"r"((A)[3]),"r"(B0),"r"(B1))

// ---------------------------------------------------------------------------
// tf32 GEMM: C[M,N] = A[M,K] @ Bt[N,K]^T, fp32 operands pre-rounded to tf32.
// block 128x128, 8 warps (2x4), warp tile 64x32, BK=32, cp.async double buffer
// mode: 0 = plain, 1 = silu, 2 = fused gates->alpha/betap epilogue
// rnd : round output to tf32 (for downstream GEMM operands)
// ---------------------------------------------------------------------------
#define BK      32
#define PITCHF  36                 // floats per smem row (144 B)
#define PITCHB  144
#define TILE_B  (128*PITCHB)       // 18432
#define OFF_B   TILE_B
#define STAGE   (2*TILE_B)         // 36864
#define GEMM_SMEM (2*STAGE)        // 73728

__global__ __launch_bounds__(256)
void mma_gemm(const float* __restrict__ A, const float* __restrict__ Bt,
              int M, int N, int K,
              const float* __restrict__ bias, int mode, int rnd,
              float* __restrict__ Cf)
{
    extern __shared__ __align__(128) char smem[];
    const uint32_t sb = smem_u32(smem);
    const int tid = threadIdx.x;
    const int wid = tid >> 5, lane = tid & 31;
    const long brow = (long)blockIdx.y * 128;
    const long bcol = (long)blockIdx.x * 128;

    const int rowBase = (wid >> 2) * 64;
    const int colBase = (wid & 3) * 32;

    float acc[4][4][4];
#pragma unroll
    for (int a = 0; a < 4; a++)
#pragma unroll
        for (int b = 0; b < 4; b++)
#pragma unroll
            for (int c = 0; c < 4; c++) acc[a][b][c] = 0.f;

    const int nch = K / BK;

    auto load_stage = [&](int s, int cidx){
        const uint32_t base = sb + s * STAGE;
        const long kc = (long)cidx * BK;
#pragma unroll
        for (int i = tid; i < 1024; i += 256) {
            const int row = i >> 3, ch = i & 7;
            const uint32_t d = row * PITCHB + ch * 16;
            cp_async16(base + d,         A  + (brow + row) * (long)K + kc + ch * 4);
            cp_async16(base + OFF_B + d, Bt + (bcol + row) * (long)K + kc + ch * 4);
        }
        cp_commit();
    };

    load_stage(0, 0);

    // ldmatrix per-thread source addresses (constant offsets per lane)
    const int aRowSel = ((lane >> 3) & 1) * 8 + (lane & 7);
    const int aKSel   = (lane >> 4) * 4;                     // 0 or 4
    const int bRowSel = ((lane >> 4) & 1) * 8 + (lane & 7);
    const int bKSel   = ((lane >> 3) & 1) * 4;

    for (int c = 0; c < nch; c++) {
        if (c + 1 < nch) { load_stage((c + 1) & 1, c + 1);
                           asm volatile("cp.async.wait_group 1;" ::: "memory"); }
        else             { asm volatile("cp.async.wait_group 0;" ::: "memory"); }
        __syncthreads();

        const uint32_t st = sb + (c & 1) * STAGE;
#pragma unroll
        for (int ks = 0; ks < 4; ks++) {
            const int k0 = ks * 8;
            uint32_t bfr[2][4];
#pragma unroll
            for (int np = 0; np < 2; np++) {
                const uint32_t addr = st + OFF_B
                    + (uint32_t)(colBase + np*16 + bRowSel) * PITCHB
                    + (uint32_t)(k0 + bKSel) * 4;
                LDSM4(bfr[np], addr);
            }
#pragma unroll
            for (int mi = 0; mi < 4; mi++) {
                const uint32_t addr = st
                    + (uint32_t)(rowBase + mi*16 + aRowSel) * PITCHB
                    + (uint32_t)(k0 + aKSel) * 4;
                uint32_t afr[4];
                LDSM4(afr, addr);
#pragma unroll
                for (int ni = 0; ni < 4; ni++) {
                    const int np = ni >> 1, q = (ni & 1) * 2;
                    MMA_TF32(acc[mi][ni], afr, bfr[np][q], bfr[np][q+1]);
                }
            }
        }
        __syncthreads();
    }

    // epilogue
    const int gID = lane >> 2, tig = lane & 3;
#pragma unroll
    for (int mi = 0; mi < 4; mi++) {
#pragma unroll
        for (int ni = 0; ni < 4; ni++) {
            const long col = bcol + colBase + ni*8 + tig*2;
#pragma unroll
            for (int half = 0; half < 2; half++) {
                const long row = brow + rowBase + mi*16 + gID + half*8;
                float v0 = acc[mi][ni][half*2];
                float v1 = acc[mi][ni][half*2+1];
                if (mode == 2) {
                    // fused gates epilogue: col even = rec_h, odd = inp_h, h=col/2
                    const int h = (int)(col >> 1);
                    const float rec = v0 + g_bil[col];
                    const float inp = v1 + g_bil[col + 1];
                    const float sp = g_splam[h];
                    const float sr = __fdividef(1.f, 1.f + __expf(-rec));
                    const float a  = __expf(-sp * sr);
                    const float si = __fdividef(1.f, 1.f + __expf(-inp));
                    const float xc = g_xc[row * HID + h];
                    g_alpha[row * HID + h] = a;
                    g_betap[row * HID + h] = sqrtf(1.f - a*a + 1e-8f) * si * xc;
                } else {
                    if (bias) { v0 += __ldg(&bias[col]); v1 += __ldg(&bias[col+1]); }
                    if (mode == 1) {
                        v0 = __fdividef(v0, 1.f + __expf(-v0));
                        v1 = __fdividef(v1, 1.f + __expf(-v1));
                    }
                    if (rnd) { v0 = rna_tf32(v0); v1 = rna_tf32(v1); }
                    *(float2*)&Cf[row * N + col] = make_float2(v0, v1);
                }
            }
        }
    }
}

// ---------------------------------------------------------------------------
// Prep kernels
// ---------------------------------------------------------------------------
__global__ void splam_kernel(const float* __restrict__ Lambda,
                             const float* __restrict__ b_gates)
{
    int h = threadIdx.x;   // 512
    g_splam[h] = log1pf(expf(Lambda[h]));
    g_bil[2*h]     = b_gates[h];
    g_bil[2*h + 1] = b_gates[HID + h];
}

__global__ void roundcopy_kernel(const float* __restrict__ in, long n4,
                                 float* __restrict__ out)
{
    long i = (long)blockIdx.x * blockDim.x + threadIdx.x;
    if (i >= n4) return;
    float4 v = ((const float4*)in)[i];
    v.x = rna_tf32(v.x); v.y = rna_tf32(v.y);
    v.z = rna_tf32(v.z); v.w = rna_tf32(v.w);
    ((float4*)out)[i] = v;
}

// W[K,N] -> WT[N,K] rounded; optional rec/inp column interleave
__global__ void wT_kernel(const float* __restrict__ W, int K, int N,
                          float* __restrict__ WT, int il)
{
    long i = (long)blockIdx.x * blockDim.x + threadIdx.x;
    if (i >= (long)K * N) return;
    int k = (int)(i % K);
    int n = (int)(i / K);
    int col = il ? ((n >> 1) + (n & 1) * HID) : n;
    WT[i] = rna_tf32(W[(long)k * N + col]);
}

// causal depthwise conv (K=4) + bias + silu -> xc (tf32-rounded fp32)
__global__ void conv_silu_kernel(const float* __restrict__ conv_w,
                                 const float* __restrict__ conv_b)
{
    long idx = (long)blockIdx.x * blockDim.x + threadIdx.x;
    if (idx >= (long)NTOK * HID) return;
    int  h = (int)(idx % HID);
    long n = idx / HID;
    int  t = (int)(n % SEQ);
    long b = n / SEQ;
    float acc = conv_b[h];
#pragma unroll
    for (int k = 0; k < 4; k++) {
        int tt = t - 3 + k;
        if (tt >= 0)
            acc = fmaf(g_xz[((long)b*SEQ + tt)*HID2 + h], conv_w[h*4 + k], acc);
    }
    float v = __fdividef(acc, 1.f + __expf(-acc));
    g_xc[idx] = rna_tf32(v);
}

// ---------------------------------------------------------------------------
// 3-phase chunked scan
// ---------------------------------------------------------------------------
__global__ void scanA_kernel()
{
    int h = threadIdx.x;
    int c = blockIdx.x % NC;
    int b = blockIdx.x / NC;
    long base = ((long)b*SEQ + c*CLEN)*HID + h;
    float A = 1.f, Bv = 0.f;
    for (int t = 0; t < CLEN; t++) {
        float a = g_alpha[base], p = g_betap[base];
        Bv = fmaf(a, Bv, p);
        A *= a;
        base += HID;
    }
    g_cA[(b*NC + c)*HID + h] = A;
    g_cB[(b*NC + c)*HID + h] = Bv;
}

__global__ void scanB_kernel()
{
    int h = threadIdx.x;
    int b = blockIdx.x;
    float carry = 0.f;
    for (int c = 0; c < NC; c++) {
        int i = (b*NC + c)*HID + h;
        g_carry[i] = carry;
        carry = fmaf(g_cA[i], carry, g_cB[i]);
    }
}

__global__ void scanC_kernel()
{
    int h = threadIdx.x;
    int c = blockIdx.x % NC;
    int b = blockIdx.x / NC;
    float hr = g_carry[(b*NC + c)*HID + h];
    long base  = ((long)b*SEQ + c*CLEN)*HID  + h;
    long zbase = ((long)b*SEQ + c*CLEN)*HID2 + HID + h;
    for (int t = 0; t < CLEN; t++) {
        float a = g_alpha[base], p = g_betap[base];
        hr = fmaf(a, hr, p);
        float z  = g_xz[zbase];
        float sz = __fdividef(z, 1.f + __expf(-z));
        g_y[base] = rna_tf32(sz * hr);
        base  += HID;
        zbase += HID2;
    }
}

// LayerNorm(a + r) * g + b ; rnd -> round (for GEMM-operand outputs)
__global__ __launch_bounds__(256)
void ln_kernel(const float* __restrict__ a, const float* __restrict__ r,
               const float* __restrict__ g, const float* __restrict__ bb,
               float* __restrict__ out, int rnd)
{
    long n = blockIdx.x;
    int  h = threadIdx.x;
    float v = a[n*DMODEL + h] + r[n*DMODEL + h];

    __shared__ float sm[8];
    int lane = h & 31, wid = h >> 5;

    float s = v;
#pragma unroll
    for (int o = 16; o > 0; o >>= 1) s += __shfl_xor_sync(0xffffffffu, s, o);
    if (lane == 0) sm[wid] = s;
    __syncthreads();
    float tot = 0.f;
#pragma unroll
    for (int i = 0; i < 8; i++) tot += sm[i];
    float mean = tot * (1.f / DMODEL);
    float d = v - mean;
    __syncthreads();

    float s2 = d * d;
#pragma unroll
    for (int o = 16; o > 0; o >>= 1) s2 += __shfl_xor_sync(0xffffffffu, s2, o);
    if (lane == 0) sm[wid] = s2;
    __syncthreads();
    float tot2 = 0.f;
#pragma unroll
    for (int i = 0; i < 8; i++) tot2 += sm[i];
    float var = tot2 * (1.f / DMODEL);

    float o_ = d * rsqrtf(var + 1e-12f) * g[h] + bb[h];
    if (rnd) o_ = rna_tf32(o_);
    out[n*DMODEL + h] = o_;
}

// ---------------------------------------------------------------------------
// Launch
// ---------------------------------------------------------------------------
extern "C" void kernel_launch(void* const* d_in, const int* in_sizes, int n_in,
                              void* d_out, int out_size)
{
    const float* x      = (const float*)d_in[0];
    const float* w_in   = (const float*)d_in[1];
    const float* conv_w = (const float*)d_in[2];
    const float* conv_b = (const float*)d_in[3];
    const float* w_gates= (const float*)d_in[4];
    const float* b_gates= (const float*)d_in[5];
    const float* Lambda = (const float*)d_in[6];
    const float* w_out  = (const float*)d_in[7];
    const float* ln1_g  = (const float*)d_in[8];
    const float* ln1_b  = (const float*)d_in[9];
    const float* ffn_w1 = (const float*)d_in[10];
    const float* ffn_b1 = (const float*)d_in[11];
    const float* ffn_w2 = (const float*)d_in[12];
    const float* ffn_b2 = (const float*)d_in[13];
    const float* ln2_g  = (const float*)d_in[14];
    const float* ln2_b  = (const float*)d_in[15];

    static bool attr_set = false;
    if (!attr_set) {
        cudaFuncSetAttribute(mma_gemm, cudaFuncAttributeMaxDynamicSharedMemorySize, GEMM_SMEM);
        attr_set = true;
    }

    float *xz, *out1, *hs, *ff1, *ff2, *xr, *y, *xc;
    float *wiT, *wgT, *woT, *f1T, *f2T;
    cudaGetSymbolAddress((void**)&xz,   g_xz);
    cudaGetSymbolAddress((void**)&out1, g_out1);
    cudaGetSymbolAddress((void**)&hs,   g_hs);
    cudaGetSymbolAddress((void**)&ff1,  g_ff1);
    cudaGetSymbolAddress((void**)&ff2,  g_ff2);
    cudaGetSymbolAddress((void**)&xr,   g_xr);
    cudaGetSymbolAddress((void**)&y,    g_y);
    cudaGetSymbolAddress((void**)&xc,   g_xc);
    cudaGetSymbolAddress((void**)&wiT,  g_wiT);
    cudaGetSymbolAddress((void**)&wgT,  g_wgT);
    cudaGetSymbolAddress((void**)&woT,  g_woT);
    cudaGetSymbolAddress((void**)&f1T,  g_f1T);
    cudaGetSymbolAddress((void**)&f2T,  g_f2T);

    const long nED = (long)NTOK * DMODEL;
    const long nEH = (long)NTOK * HID;

    splam_kernel<<<1, HID>>>(Lambda, b_gates);
    roundcopy_kernel<<<(int)((nED/4 + 255)/256), 256>>>(x, nED/4, xr);
    wT_kernel<<<(DMODEL*HID2 + 255)/256, 256>>>(w_in,   DMODEL, HID2,   wiT, 0);
    wT_kernel<<<(HID*HID2   + 255)/256, 256>>>(w_gates, HID,    HID2,   wgT, 1);
    wT_kernel<<<(HID*DMODEL + 255)/256, 256>>>(w_out,   HID,    DMODEL, woT, 0);
    wT_kernel<<<(DMODEL*INNER+255)/256, 256>>>(ffn_w1,  DMODEL, INNER,  f1T, 0);
    wT_kernel<<<(INNER*DMODEL+255)/256, 256>>>(ffn_w2,  INNER,  DMODEL, f2T, 0);

    // 1. xz = x @ w_in
    mma_gemm<<<dim3(HID2/128, NTOK/128), 256, GEMM_SMEM>>>(
        xr, wiT, NTOK, HID2, DMODEL, nullptr, 0, 0, xz);
    // 2. conv + silu -> xc (rounded)
    conv_silu_kernel<<<(int)((nEH + 255)/256), 256>>>(conv_w, conv_b);
    // 3. gates GEMM with fused alpha/betap epilogue (interleaved columns)
    mma_gemm<<<dim3(HID2/128, NTOK/128), 256, GEMM_SMEM>>>(
        xc, wgT, NTOK, HID2, HID, nullptr, 2, 0, nullptr);
    // 4-6. chunked scan (+ y = silu(z)*h, rounded)
    scanA_kernel<<<BATCH*NC, HID>>>();
    scanB_kernel<<<BATCH, HID>>>();
    scanC_kernel<<<BATCH*NC, HID>>>();
    // 7. out1 = y @ w_out
    mma_gemm<<<dim3(DMODEL/128, NTOK/128), 256, GEMM_SMEM>>>(
        y, woT, NTOK, DMODEL, HID, nullptr, 0, 0, out1);
    // 8. hs = LN(out1 + x)  (rounded — GEMM operand + residual)
    ln_kernel<<<NTOK, DMODEL>>>(out1, x, ln1_g, ln1_b, hs, 1);
    // 9. ff1 = silu(hs @ ffn_w1 + b1)  (rounded)
    mma_gemm<<<dim3(INNER/128, NTOK/128), 256, GEMM_SMEM>>>(
        hs, f1T, NTOK, INNER, DMODEL, ffn_b1, 1, 1, ff1);
    // 10. ff2 = ff1 @ ffn_w2 + b2
    mma_gemm<<<dim3(DMODEL/128, NTOK/128), 256, GEMM_SMEM>>>(
        ff1, f2T, NTOK, DMODEL, INNER, ffn_b2, 0, 0, ff2);
    // 11. out = LN(ff2 + hs)
    ln_kernel<<<NTOK, DMODEL>>>(ff2, hs, ln2_g, ln2_b, (float*)d_out, 0);
}

// round 5
// speedup vs baseline: 3.0332x; 1.0003x over previous
#include <cuda_runtime.h>
#include <cuda_bf16.h>
#include <math.h>
#include <stdint.h>

#define BATCH  32
#define SEQ    2048
#define DMODEL 256
#define HID    512
#define HID2   1024
#define INNER  1024
#define NTOK   (BATCH*SEQ)   // 65536
#define NC     16
#define CLEN   (SEQ/NC)      // 128

// ---------------------------------------------------------------------------
// Scratch
// ---------------------------------------------------------------------------
__device__ float g_xz   [(size_t)NTOK*HID2];   // [xh | z]
__device__ float g_xc   [(size_t)NTOK*HID];    // rounded
__device__ float g_alpha[(size_t)NTOK*HID];
__device__ float g_betap[(size_t)NTOK*HID];
__device__ float g_y    [(size_t)NTOK*HID];    // rounded
__device__ float g_hs   [(size_t)NTOK*DMODEL]; // rounded
__device__ float g_ff1  [(size_t)NTOK*INNER];  // rounded
__device__ float g_xr   [(size_t)NTOK*DMODEL]; // rounded copy of x
__device__ float g_cA   [BATCH*NC*HID];
__device__ float g_cB   [BATCH*NC*HID];
__device__ float g_carry[BATCH*NC*HID];
__device__ float g_splam[HID];
__device__ float g_bil  [HID2];                // interleaved gates bias
// transposed (rounded) weights [N,K]
__device__ __align__(256) float g_wiT[HID2*DMODEL];
__device__ __align__(256) float g_wgT[HID2*HID];   // column-interleaved rec/inp
__device__ __align__(256) float g_woT[DMODEL*HID];
__device__ __align__(256) float g_f1T[INNER*DMODEL];
__device__ __align__(256) float g_f2T[DMODEL*INNER];

// ---------------------------------------------------------------------------
// helpers
// ---------------------------------------------------------------------------
__device__ __forceinline__ uint32_t smem_u32(const void* p){
    uint32_t a;
    asm("{ .reg .u64 t; cvta.to.shared.u64 t, %1; cvt.u32.u64 %0, t; }"
        : "=r"(a) : "l"(p));
    return a;
}
__device__ __forceinline__ void cp_async16(uint32_t dst, const void* src){
    asm volatile("cp.async.cg.shared.global [%0], [%1], 16;" :: "r"(dst), "l"(src));
}
__device__ __forceinline__ void cp_commit(){ asm volatile("cp.async.commit_group;"); }

__device__ __forceinline__ float rna_tf32(float v){
    uint32_t o;
    asm("cvt.rna.tf32.f32 %0, %1;" : "=r"(o) : "f"(v));
    return __uint_as_float(o);
}

#define LDSM4(R, A) \
    asm volatile("ldmatrix.sync.aligned.m8n8.x4.shared.b16 {%0,%1,%2,%3}, [%4];" \
        : "=r"((R)[0]),"=r"((R)[1]),"=r"((R)[2]),"=r"((R)[3]) : "r"(A))

#define MMA_TF32(C, A, B0, B1) \
    asm volatile("mma.sync.aligned.m16n8k8.row.col.f32.tf32.tf32.f32 " \
        "{%0,%1,%2,%3},{%4,%5,%6,%7},{%8,%9},{%0,%1,%2,%3};" \
        : "+f"((C)[0]),"+f"((C)[1]),"+f"((C)[2]),"+f"((C)[3]) \
        : "r"((A)[0]),"r"((A)[1]),"r"((A)[2]),"r"((A)[3]),"r"(B0),"r"(B1))

// ---------------------------------------------------------------------------
// tf32 GEMM (128x128 tile, 256 thr): mode 0 plain, 1 silu, 2 fused gates
//   mode 2: N cols are interleaved (rec,inp) pairs; epilogue computes
//   alpha/betap, writes them, and also performs the per-chunk scanA reduction
//   (tile rows == one scan chunk) writing g_cA/g_cB.
// ---------------------------------------------------------------------------
#define BK      32
#define PITCHB  144
#define TILE_B  (128*PITCHB)       // 18432
#define OFF_B   TILE_B
#define STAGE   (2*TILE_B)         // 36864
#define GEMM_SMEM (2*STAGE)        // 73728

__global__ __launch_bounds__(256)
void mma_gemm(const float* __restrict__ A, const float* __restrict__ Bt,
              int M, int N, int K,
              const float* __restrict__ bias, int mode, int rnd,
              float* __restrict__ Cf)
{
    extern __shared__ __align__(128) char smem[];
    const uint32_t sb = smem_u32(smem);
    const int tid = threadIdx.x;
    const int wid = tid >> 5, lane = tid & 31;
    const long brow = (long)blockIdx.y * 128;
    const long bcol = (long)blockIdx.x * 128;

    const int rowBase = (wid >> 2) * 64;
    const int colBase = (wid & 3) * 32;

    float acc[4][4][4];
#pragma unroll
    for (int a = 0; a < 4; a++)
#pragma unroll
        for (int b = 0; b < 4; b++)
#pragma unroll
            for (int c = 0; c < 4; c++) acc[a][b][c] = 0.f;

    const int nch = K / BK;

    auto load_stage = [&](int s, int cidx){
        const uint32_t base = sb + s * STAGE;
        const long kc = (long)cidx * BK;
#pragma unroll
        for (int i = tid; i < 1024; i += 256) {
            const int row = i >> 3, ch = i & 7;
            const uint32_t d = row * PITCHB + ch * 16;
            cp_async16(base + d,         A  + (brow + row) * (long)K + kc + ch * 4);
            cp_async16(base + OFF_B + d, Bt + (bcol + row) * (long)K + kc + ch * 4);
        }
        cp_commit();
    };

    load_stage(0, 0);

    const int aRowSel = ((lane >> 3) & 1) * 8 + (lane & 7);
    const int aKSel   = (lane >> 4) * 4;
    const int bRowSel = ((lane >> 4) & 1) * 8 + (lane & 7);
    const int bKSel   = ((lane >> 3) & 1) * 4;

    for (int c = 0; c < nch; c++) {
        if (c + 1 < nch) { load_stage((c + 1) & 1, c + 1);
                           asm volatile("cp.async.wait_group 1;" ::: "memory"); }
        else             { asm volatile("cp.async.wait_group 0;" ::: "memory"); }
        __syncthreads();

        const uint32_t st = sb + (c & 1) * STAGE;
#pragma unroll
        for (int ks = 0; ks < 4; ks++) {
            const int k0 = ks * 8;
            uint32_t bfr[2][4];
#pragma unroll
            for (int np = 0; np < 2; np++) {
                const uint32_t addr = st + OFF_B
                    + (uint32_t)(colBase + np*16 + bRowSel) * PITCHB
                    + (uint32_t)(k0 + bKSel) * 4;
                LDSM4(bfr[np], addr);
            }
#pragma unroll
            for (int mi = 0; mi < 4; mi++) {
                const uint32_t addr = st
                    + (uint32_t)(rowBase + mi*16 + aRowSel) * PITCHB
                    + (uint32_t)(k0 + aKSel) * 4;
                uint32_t afr[4];
                LDSM4(afr, addr);
#pragma unroll
                for (int ni = 0; ni < 4; ni++) {
                    const int np = ni >> 1, q = (ni & 1) * 2;
                    MMA_TF32(acc[mi][ni], afr, bfr[np][q], bfr[np][q+1]);
                }
            }
        }
        __syncthreads();
    }

    const int gID = lane >> 2, tig = lane & 3;

    if (mode == 2) {
        // ---- fused gates epilogue + chunk-level scanA ----
        float* sA   = (float*)smem;              // [128][64]
        float* sB   = sA + 128*64;               // [128][64]
        float* segb = sB + 128*64;               // [64][4][2]
#pragma unroll
        for (int mi = 0; mi < 4; mi++) {
#pragma unroll
            for (int ni = 0; ni < 4; ni++) {
                const long col = bcol + colBase + ni*8 + tig*2;
                const int hloc = ((colBase) >> 1) + ni*4 + tig;  // 0..63
                const int h    = (int)(col >> 1);
#pragma unroll
                for (int half = 0; half < 2; half++) {
                    const int  rloc = rowBase + mi*16 + gID + half*8;
                    const long row  = brow + rloc;
                    const float rec = acc[mi][ni][half*2]   + g_bil[col];
                    const float inp = acc[mi][ni][half*2+1] + g_bil[col + 1];
                    const float sp = g_splam[h];
                    const float sr = __fdividef(1.f, 1.f + __expf(-rec));
                    const float a  = __expf(-sp * sr);
                    const float si = __fdividef(1.f, 1.f + __expf(-inp));
                    const float xc = g_xc[row * HID + h];
                    const float bp = sqrtf(1.f - a*a + 1e-8f) * si * xc;
                    g_alpha[row * HID + h] = a;
                    g_betap[row * HID + h] = bp;
                    sA[rloc * 64 + hloc] = a;
                    sB[rloc * 64 + hloc] = bp;
                }
            }
        }
        __syncthreads();
        // segmented scan: 4 segments x 32 steps, 64 channels, 256 threads
        {
            const int ch  = tid & 63;
            const int seg = tid >> 6;           // 0..3
            float Aprod = 1.f, Bacc = 0.f;
            int r = seg * 32;
#pragma unroll 8
            for (int t = 0; t < 32; t++, r++) {
                const float a = sA[r * 64 + ch];
                const float p = sB[r * 64 + ch];
                Bacc = fmaf(a, Bacc, p);
                Aprod *= a;
            }
            segb[(ch * 4 + seg) * 2]     = Aprod;
            segb[(ch * 4 + seg) * 2 + 1] = Bacc;
        }
        __syncthreads();
        if (tid < 64) {
            float At = 1.f, Bt2 = 0.f;
#pragma unroll
            for (int seg = 0; seg < 4; seg++) {
                const float a = segb[(tid * 4 + seg) * 2];
                const float p = segb[(tid * 4 + seg) * 2 + 1];
                Bt2 = fmaf(a, Bt2, p);
                At *= a;
            }
            const int b  = (int)(brow >> 11);         // /SEQ
            const int cc = (int)((brow >> 7) & 15);
            const int h  = (int)(bcol >> 1) + tid;
            g_cA[(b*NC + cc)*HID + h] = At;
            g_cB[(b*NC + cc)*HID + h] = Bt2;
        }
        return;
    }

    // plain / silu epilogue
#pragma unroll
    for (int mi = 0; mi < 4; mi++) {
#pragma unroll
        for (int ni = 0; ni < 4; ni++) {
            const long col = bcol + colBase + ni*8 + tig*2;
            float b0 = 0.f, b1 = 0.f;
            if (bias) { b0 = __ldg(&bias[col]); b1 = __ldg(&bias[col+1]); }
#pragma unroll
            for (int half = 0; half < 2; half++) {
                const long row = brow + rowBase + mi*16 + gID + half*8;
                float v0 = acc[mi][ni][half*2]   + b0;
                float v1 = acc[mi][ni][half*2+1] + b1;
                if (mode == 1) {
                    v0 = __fdividef(v0, 1.f + __expf(-v0));
                    v1 = __fdividef(v1, 1.f + __expf(-v1));
                }
                if (rnd) { v0 = rna_tf32(v0); v1 = rna_tf32(v1); }
                *(float2*)&Cf[row * N + col] = make_float2(v0, v1);
            }
        }
    }
}

// ---------------------------------------------------------------------------
// tf32 GEMM with fused residual + LayerNorm epilogue.
// tile 128 x 256 (full DMODEL), 512 threads, 16 warps (2 x 8).
// out = LN(A@Bt^T + bias + R) * gamma + beta   [optionally tf32-rounded]
// ---------------------------------------------------------------------------
#define TILE_A2 (128*PITCHB)         // 18432
#define TILE_B2 (256*PITCHB)         // 36864
#define OFF_B2  TILE_A2
#define STAGE2  (TILE_A2 + TILE_B2)  // 55296
#define LN_SMEM (2*STAGE2 + 2*128*4) // 111616

__global__ __launch_bounds__(512)
void mma_gemm_ln(const float* __restrict__ A, const float* __restrict__ Bt,
                 int K,
                 const float* __restrict__ bias,
                 const float* __restrict__ R,
                 const float* __restrict__ gamma, const float* __restrict__ beta,
                 int rnd, float* __restrict__ Cf)
{
    extern __shared__ __align__(128) char smem[];
    const uint32_t sb = smem_u32(smem);
    float* srow  = (float*)(smem + 2*STAGE2);
    float* srow2 = srow + 128;
    const int tid = threadIdx.x;
    const int wid = tid >> 5, lane = tid & 31;
    const long brow = (long)blockIdx.y * 128;

    const int rowBase = (wid >> 3) * 64;
    const int colBase = (wid & 7) * 32;

    float acc[4][4][4];
#pragma unroll
    for (int a = 0; a < 4; a++)
#pragma unroll
        for (int b = 0; b < 4; b++)
#pragma unroll
            for (int c = 0; c < 4; c++) acc[a][b][c] = 0.f;

    const int nch = K / BK;

    auto load_stage = [&](int s, int cidx){
        const uint32_t base = sb + s * STAGE2;
        const long kc = (long)cidx * BK;
#pragma unroll
        for (int i = tid; i < 3072; i += 512) {
            const int row = i >> 3, ch = i & 7;
            if (row < 128) {
                cp_async16(base + row * PITCHB + ch * 16,
                           A + (brow + row) * (long)K + kc + ch * 4);
            } else {
                const int br = row - 128;
                cp_async16(base + OFF_B2 + br * PITCHB + ch * 16,
                           Bt + br * (long)K + kc + ch * 4);
            }
        }
        cp_commit();
    };

    load_stage(0, 0);

    const int aRowSel = ((lane >> 3) & 1) * 8 + (lane & 7);
    const int aKSel   = (lane >> 4) * 4;
    const int bRowSel = ((lane >> 4) & 1) * 8 + (lane & 7);
    const int bKSel   = ((lane >> 3) & 1) * 4;

    for (int c = 0; c < nch; c++) {
        if (c + 1 < nch) { load_stage((c + 1) & 1, c + 1);
                           asm volatile("cp.async.wait_group 1;" ::: "memory"); }
        else             { asm volatile("cp.async.wait_group 0;" ::: "memory"); }
        __syncthreads();

        const uint32_t st = sb + (c & 1) * STAGE2;
#pragma unroll
        for (int ks = 0; ks < 4; ks++) {
            const int k0 = ks * 8;
            uint32_t bfr[2][4];
#pragma unroll
            for (int np = 0; np < 2; np++) {
                const uint32_t addr = st + OFF_B2
                    + (uint32_t)(colBase + np*16 + bRowSel) * PITCHB
                    + (uint32_t)(k0 + bKSel) * 4;
                LDSM4(bfr[np], addr);
            }
#pragma unroll
            for (int mi = 0; mi < 4; mi++) {
                const uint32_t addr = st
                    + (uint32_t)(rowBase + mi*16 + aRowSel) * PITCHB
                    + (uint32_t)(k0 + aKSel) * 4;
                uint32_t afr[4];
                LDSM4(afr, addr);
#pragma unroll
                for (int ni = 0; ni < 4; ni++) {
                    const int np = ni >> 1, q = (ni & 1) * 2;
                    MMA_TF32(acc[mi][ni], afr, bfr[np][q], bfr[np][q+1]);
                }
            }
        }
        __syncthreads();
    }

    // ---- fused residual + LN epilogue ----
    if (tid < 128) { srow[tid] = 0.f; srow2[tid] = 0.f; }
    __syncthreads();

    const int gID = lane >> 2, tig = lane & 3;

    // phase 1: v = acc + bias + residual ; accumulate row sums
#pragma unroll
    for (int mi = 0; mi < 4; mi++) {
#pragma unroll
        for (int half = 0; half < 2; half++) {
            const int  rloc = rowBase + mi*16 + gID + half*8;
            const long row  = brow + rloc;
            float s = 0.f, s2 = 0.f;
#pragma unroll
            for (int ni = 0; ni < 4; ni++) {
                const int col = colBase + ni*8 + tig*2;
                float2 rv = *(const float2*)&R[row * DMODEL + col];
                float v0 = acc[mi][ni][half*2]   + rv.x;
                float v1 = acc[mi][ni][half*2+1] + rv.y;
                if (bias) { v0 += __ldg(&bias[col]); v1 += __ldg(&bias[col+1]); }
                acc[mi][ni][half*2]   = v0;
                acc[mi][ni][half*2+1] = v1;
                s  += v0 + v1;
                s2 += v0*v0 + v1*v1;
            }
            atomicAdd(&srow[rloc],  s);
            atomicAdd(&srow2[rloc], s2);
        }
    }
    __syncthreads();

    // phase 2: normalize + write
#pragma unroll
    for (int mi = 0; mi < 4; mi++) {
#pragma unroll
        for (int half = 0; half < 2; half++) {
            const int  rloc = rowBase + mi*16 + gID + half*8;
            const long row  = brow + rloc;
            const float mean = srow[rloc] * (1.f / DMODEL);
            float var = srow2[rloc] * (1.f / DMODEL) - mean * mean;
            const float rs = rsqrtf(var + 1e-12f);
#pragma unroll
            for (int ni = 0; ni < 4; ni++) {
                const int col = colBase + ni*8 + tig*2;
                float2 gv = *(const float2*)&gamma[col];
                float2 bv = *(const float2*)&beta[col];
                float v0 = (acc[mi][ni][half*2]   - mean) * rs * gv.x + bv.x;
                float v1 = (acc[mi][ni][half*2+1] - mean) * rs * gv.y + bv.y;
                if (rnd) { v0 = rna_tf32(v0); v1 = rna_tf32(v1); }
                *(float2*)&Cf[row * DMODEL + col] = make_float2(v0, v1);
            }
        }
    }
}

// ---------------------------------------------------------------------------
// Prep: splam/bias interleave + all 5 weight transposes in one launch
// ---------------------------------------------------------------------------
#define WT_B0 1
#define WT_B1 (WT_B0 + (DMODEL*HID2)/256)
#define WT_B2 (WT_B1 + (HID*HID2)/256)
#define WT_B3 (WT_B2 + (HID*DMODEL)/256)
#define WT_B4 (WT_B3 + (DMODEL*INNER)/256)
#define WT_B5 (WT_B4 + (INNER*DMODEL)/256)

__global__ __launch_bounds__(256)
void prep_kernel(const float* __restrict__ Lambda, const float* __restrict__ b_gates,
                 const float* __restrict__ w_in, const float* __restrict__ w_gates,
                 const float* __restrict__ w_out, const float* __restrict__ ffn_w1,
                 const float* __restrict__ ffn_w2)
{
    const int blk = blockIdx.x;
    const int t = threadIdx.x;
    if (blk == 0) {
#pragma unroll
        for (int q = 0; q < 2; q++) {
            int h = t + q * 256;
            g_splam[h] = log1pf(expf(Lambda[h]));
            g_bil[2*h]     = b_gates[h];
            g_bil[2*h + 1] = b_gates[HID + h];
        }
        return;
    }
    const float* W; float* WT; int K, N, il = 0; long base;
    if (blk < WT_B1)      { W = w_in;    WT = g_wiT; K = DMODEL; N = HID2;   base = (long)(blk - WT_B0) * 256; }
    else if (blk < WT_B2) { W = w_gates; WT = g_wgT; K = HID;    N = HID2;   base = (long)(blk - WT_B1) * 256; il = 1; }
    else if (blk < WT_B3) { W = w_out;   WT = g_woT; K = HID;    N = DMODEL; base = (long)(blk - WT_B2) * 256; }
    else if (blk < WT_B4) { W = ffn_w1;  WT = g_f1T; K = DMODEL; N = INNER;  base = (long)(blk - WT_B3) * 256; }
    else                  { W = ffn_w2;  WT = g_f2T; K = INNER;  N = DMODEL; base = (long)(blk - WT_B4) * 256; }
    const long i = base + t;
    const int k = (int)(i % K);
    const int n = (int)(i / K);
    const int col = il ? ((n >> 1) + (n & 1) * HID) : n;
    WT[i] = rna_tf32(W[(long)k * N + col]);
}

__global__ void roundcopy_kernel(const float* __restrict__ in, long n4,
                                 float* __restrict__ out)
{
    long i = (long)blockIdx.x * blockDim.x + threadIdx.x;
    if (i >= n4) return;
    float4 v = ((const float4*)in)[i];
    v.x = rna_tf32(v.x); v.y = rna_tf32(v.y);
    v.z = rna_tf32(v.z); v.w = rna_tf32(v.w);
    ((float4*)out)[i] = v;
}

// causal depthwise conv (K=4) + bias + silu -> xc (rounded)
__global__ void conv_silu_kernel(const float* __restrict__ conv_w,
                                 const float* __restrict__ conv_b)
{
    long idx = (long)blockIdx.x * blockDim.x + threadIdx.x;
    if (idx >= (long)NTOK * HID) return;
    int  h = (int)(idx % HID);
    long n = idx / HID;
    int  t = (int)(n % SEQ);
    long b = n / SEQ;
    float acc = conv_b[h];
#pragma unroll
    for (int k = 0; k < 4; k++) {
        int tt = t - 3 + k;
        if (tt >= 0)
            acc = fmaf(g_xz[((long)b*SEQ + tt)*HID2 + h], conv_w[h*4 + k], acc);
    }
    float v = __fdividef(acc, 1.f + __expf(-acc));
    g_xc[idx] = rna_tf32(v);
}

// ---------------------------------------------------------------------------
// scan phases B and C
// ---------------------------------------------------------------------------
__global__ void scanB_kernel()
{
    int h = threadIdx.x;
    int b = blockIdx.x;
    float carry = 0.f;
    for (int c = 0; c < NC; c++) {
        int i = (b*NC + c)*HID + h;
        g_carry[i] = carry;
        carry = fmaf(g_cA[i], carry, g_cB[i]);
    }
}

__global__ void scanC_kernel()
{
    int h = threadIdx.x;
    int c = blockIdx.x % NC;
    int b = blockIdx.x / NC;
    float hr = g_carry[(b*NC + c)*HID + h];
    long base  = ((long)b*SEQ + c*CLEN)*HID  + h;
    long zbase = ((long)b*SEQ + c*CLEN)*HID2 + HID + h;
    for (int t = 0; t < CLEN; t++) {
        float a = g_alpha[base], p = g_betap[base];
        hr = fmaf(a, hr, p);
        float z  = g_xz[zbase];
        float sz = __fdividef(z, 1.f + __expf(-z));
        g_y[base] = rna_tf32(sz * hr);
        base  += HID;
        zbase += HID2;
    }
}

// ---------------------------------------------------------------------------
// Launch
// ---------------------------------------------------------------------------
extern "C" void kernel_launch(void* const* d_in, const int* in_sizes, int n_in,
                              void* d_out, int out_size)
{
    const float* x      = (const float*)d_in[0];
    const float* w_in   = (const float*)d_in[1];
    const float* conv_w = (const float*)d_in[2];
    const float* conv_b = (const float*)d_in[3];
    const float* w_gates= (const float*)d_in[4];
    const float* b_gates= (const float*)d_in[5];
    const float* Lambda = (const float*)d_in[6];
    const float* w_out  = (const float*)d_in[7];
    const float* ln1_g  = (const float*)d_in[8];
    const float* ln1_b  = (const float*)d_in[9];
    const float* ffn_w1 = (const float*)d_in[10];
    const float* ffn_b1 = (const float*)d_in[11];
    const float* ffn_w2 = (const float*)d_in[12];
    const float* ffn_b2 = (const float*)d_in[13];
    const float* ln2_g  = (const float*)d_in[14];
    const float* ln2_b  = (const float*)d_in[15];

    static bool attr_set = false;
    if (!attr_set) {
        cudaFuncSetAttribute(mma_gemm,    cudaFuncAttributeMaxDynamicSharedMemorySize, GEMM_SMEM);
        cudaFuncSetAttribute(mma_gemm_ln, cudaFuncAttributeMaxDynamicSharedMemorySize, LN_SMEM);
        attr_set = true;
    }

    float *xz, *hs, *ff1, *xr, *y, *xc;
    float *wiT, *wgT, *woT, *f1T, *f2T;
    cudaGetSymbolAddress((void**)&xz,  g_xz);
    cudaGetSymbolAddress((void**)&hs,  g_hs);
    cudaGetSymbolAddress((void**)&ff1, g_ff1);
    cudaGetSymbolAddress((void**)&xr,  g_xr);
    cudaGetSymbolAddress((void**)&y,   g_y);
    cudaGetSymbolAddress((void**)&xc,  g_xc);
    cudaGetSymbolAddress((void**)&wiT, g_wiT);
    cudaGetSymbolAddress((void**)&wgT, g_wgT);
    cudaGetSymbolAddress((void**)&woT, g_woT);
    cudaGetSymbolAddress((void**)&f1T, g_f1T);
    cudaGetSymbolAddress((void**)&f2T, g_f2T);

    const long nED = (long)NTOK * DMODEL;
    const long nEH = (long)NTOK * HID;

    // prep
    prep_kernel<<<WT_B5, 256>>>(Lambda, b_gates, w_in, w_gates, w_out, ffn_w1, ffn_w2);
    roundcopy_kernel<<<(int)((nED/4 + 255)/256), 256>>>(x, nED/4, xr);

    // 1. xz = x @ w_in
    mma_gemm<<<dim3(HID2/128, NTOK/128), 256, GEMM_SMEM>>>(
        xr, wiT, NTOK, HID2, DMODEL, nullptr, 0, 0, xz);
    // 2. conv + silu -> xc
    conv_silu_kernel<<<(int)((nEH + 255)/256), 256>>>(conv_w, conv_b);
    // 3. gates GEMM + fused alpha/betap + chunk scanA
    mma_gemm<<<dim3(HID2/128, NTOK/128), 256, GEMM_SMEM>>>(
        xc, wgT, NTOK, HID2, HID, nullptr, 2, 0, nullptr);
    // 4-5. scan carry + full scan (+ y = silu(z)*h)
    scanB_kernel<<<BATCH, HID>>>();
    scanC_kernel<<<BATCH*NC, HID>>>();
    // 6. hs = LN(y @ w_out + x)   (fused LN1, rounded)
    mma_gemm_ln<<<dim3(1, NTOK/128), 512, LN_SMEM>>>(
        y, woT, HID, nullptr, x, ln1_g, ln1_b, 1, hs);
    // 7. ff1 = silu(hs @ ffn_w1 + b1)  (rounded)
    mma_gemm<<<dim3(INNER/128, NTOK/128), 256, GEMM_SMEM>>>(
        hs, f1T, NTOK, INNER, DMODEL, ffn_b1, 1, 1, ff1);
    // 8. out = LN(ff1 @ ffn_w2 + b2 + hs)   (fused LN2)
    mma_gemm_ln<<<dim3(1, NTOK/128), 512, LN_SMEM>>>(
        ff1, f2T, INNER, ffn_b2, hs, ln2_g, ln2_b, 0, (float*)d_out);
}

// round 7
// speedup vs baseline: 4.0249x; 1.3270x over previous
#include <cuda_runtime.h>
#include <cuda_fp16.h>
#include <math.h>
#include <stdint.h>

#define BATCH  32
#define SEQ    2048
#define DMODEL 256
#define HID    512
#define HID2   1024
#define INNER  1024
#define NTOK   (BATCH*SEQ)   // 65536
#define NC     16
#define CLEN   (SEQ/NC)      // 128

// ---------------------------------------------------------------------------
// Scratch
// ---------------------------------------------------------------------------
__device__ float g_xz   [(size_t)NTOK*HID2];   // [xh | z] fp32
__device__ float g_alpha[(size_t)NTOK*HID];
__device__ float g_betap[(size_t)NTOK*HID];
__device__ float g_hs   [(size_t)NTOK*DMODEL]; // fp32 residual for LN2
__device__ float g_cA   [BATCH*NC*HID];
__device__ float g_cB   [BATCH*NC*HID];
__device__ float g_carry[BATCH*NC*HID];
__device__ float g_splam[HID];
__device__ float g_bil  [HID2];
// fp16 GEMM operands
__device__ __align__(256) __half g_xr [(size_t)NTOK*DMODEL];
__device__ __align__(256) __half g_xc [(size_t)NTOK*HID];
__device__ __align__(256) __half g_y  [(size_t)NTOK*HID];
__device__ __align__(256) __half g_hsh[(size_t)NTOK*DMODEL];
__device__ __align__(256) __half g_ff1[(size_t)NTOK*INNER];
// transposed fp16 weights [N,K]
__device__ __align__(256) __half g_wiT[HID2*DMODEL];
__device__ __align__(256) __half g_wgT[HID2*HID];   // interleaved rec/inp cols
__device__ __align__(256) __half g_woT[DMODEL*HID];
__device__ __align__(256) __half g_f1T[INNER*DMODEL];
__device__ __align__(256) __half g_f2T[DMODEL*INNER];

// ---------------------------------------------------------------------------
// helpers
// ---------------------------------------------------------------------------
__device__ __forceinline__ uint32_t smem_u32(const void* p){
    uint32_t a;
    asm("{ .reg .u64 t; cvta.to.shared.u64 t, %1; cvt.u32.u64 %0, t; }"
        : "=r"(a) : "l"(p));
    return a;
}
__device__ __forceinline__ void cp_async16(uint32_t dst, const void* src){
    asm volatile("cp.async.cg.shared.global [%0], [%1], 16;" :: "r"(dst), "l"(src));
}
__device__ __forceinline__ void cp_commit(){ asm volatile("cp.async.commit_group;"); }

#define LDSM4(R, A) \
    asm volatile("ldmatrix.sync.aligned.m8n8.x4.shared.b16 {%0,%1,%2,%3}, [%4];" \
        : "=r"((R)[0]),"=r"((R)[1]),"=r"((R)[2]),"=r"((R)[3]) : "r"(A))

#define MMA_F16(C, A, B0, B1) \
    asm volatile("mma.sync.aligned.m16n8k16.row.col.f32.f16.f16.f32 " \
        "{%0,%1,%2,%3},{%4,%5,%6,%7},{%8,%9},{%0,%1,%2,%3};" \
        : "+f"((C)[0]),"+f"((C)[1]),"+f"((C)[2]),"+f"((C)[3]) \
        : "r"((A)[0]),"r"((A)[1]),"r"((A)[2]),"r"((A)[3]),"r"(B0),"r"(B1))

// ---------------------------------------------------------------------------
// fp16 GEMM (128x128 tile, 256 thr, BK=32, PROW=80)
// mode: 0 = plain fp32 out, 1 = silu + fp16 out, 2 = fused gates epilogue
// ---------------------------------------------------------------------------
#define BK    32
#define PROW  80
#define SZ_T  (128*PROW)           // 10240
#define OFF_B SZ_T
#define STAGE (2*SZ_T)             // 20480
// smem requirement: max(2*STAGE = 40960, mode-2 overlay = 2*32768 + 2048 = 67584)
#define GEMM_SMEM 69632

__global__ __launch_bounds__(256)
void mma_gemm(const __half* __restrict__ A, const __half* __restrict__ Bt,
              int M, int N, int K,
              const float* __restrict__ bias, int mode,
              float* __restrict__ Cf, __half* __restrict__ Ch)
{
    extern __shared__ __align__(128) char smem[];
    const uint32_t sb = smem_u32(smem);
    const int tid = threadIdx.x;
    const int wid = tid >> 5, lane = tid & 31;
    const long brow = (long)blockIdx.y * 128;
    const long bcol = (long)blockIdx.x * 128;

    const int rowBase = (wid >> 2) * 64;
    const int colBase = (wid & 3) * 32;

    float acc[4][4][4];
#pragma unroll
    for (int a = 0; a < 4; a++)
#pragma unroll
        for (int b = 0; b < 4; b++)
#pragma unroll
            for (int c = 0; c < 4; c++) acc[a][b][c] = 0.f;

    const int nch = K / BK;

    auto load_stage = [&](int s, int cidx){
        const uint32_t base = sb + s * STAGE;
        const long kc = (long)cidx * BK;
#pragma unroll
        for (int i = tid; i < 512; i += 256) {
            const int row = i >> 2, ch = i & 3;
            const uint32_t d = row * PROW + ch * 16;
            cp_async16(base + d,         A  + (brow + row) * (long)K + kc + ch * 8);
            cp_async16(base + OFF_B + d, Bt + (bcol + row) * (long)K + kc + ch * 8);
        }
        cp_commit();
    };

    load_stage(0, 0);

    const int g = lane >> 3, r = lane & 7;

    for (int c = 0; c < nch; c++) {
        if (c + 1 < nch) { load_stage((c + 1) & 1, c + 1);
                           asm volatile("cp.async.wait_group 1;" ::: "memory"); }
        else             { asm volatile("cp.async.wait_group 0;" ::: "memory"); }
        __syncthreads();

        const uint32_t st = sb + (c & 1) * STAGE;
#pragma unroll
        for (int ks = 0; ks < 2; ks++) {
            const int k0 = ks * 16;
            uint32_t bf[2][4];
#pragma unroll
            for (int p = 0; p < 2; p++) {
                const uint32_t boff =
                    (uint32_t)(colBase + p*16 + ((g >> 1) << 3) + r) * PROW
                    + (uint32_t)(k0 + ((g & 1) << 3)) * 2;
                LDSM4(bf[p], st + OFF_B + boff);
            }
#pragma unroll
            for (int mi = 0; mi < 4; mi++) {
                const uint32_t aoff =
                    (uint32_t)(rowBase + mi*16 + r + ((g & 1) << 3)) * PROW
                    + (uint32_t)(k0 + ((g >> 1) << 3)) * 2;
                uint32_t af[4];
                LDSM4(af, st + aoff);
#pragma unroll
                for (int ni = 0; ni < 4; ni++) {
                    const int p = ni >> 1, q = (ni & 1) * 2;
                    MMA_F16(acc[mi][ni], af, bf[p][q], bf[p][q+1]);
                }
            }
        }
        __syncthreads();
    }

    const int gID = lane >> 2, tig = lane & 3;

    if (mode == 2) {
        // fused gates epilogue + per-chunk scanA (tile rows == one scan chunk)
        float* sA   = (float*)smem;              // [128][64]  32768 B
        float* sB   = sA + 128*64;               // [128][64]  32768 B
        float* segb = sB + 128*64;               // [64][4][2]  2048 B
#pragma unroll
        for (int mi = 0; mi < 4; mi++) {
#pragma unroll
            for (int ni = 0; ni < 4; ni++) {
                const long col = bcol + colBase + ni*8 + tig*2;
                const int hloc = (colBase >> 1) + ni*4 + tig;
                const int h    = (int)(col >> 1);
#pragma unroll
                for (int half = 0; half < 2; half++) {
                    const int  rloc = rowBase + mi*16 + gID + half*8;
                    const long row  = brow + rloc;
                    const float rec = acc[mi][ni][half*2]   + g_bil[col];
                    const float inp = acc[mi][ni][half*2+1] + g_bil[col + 1];
                    const float sp = g_splam[h];
                    const float sr = __fdividef(1.f, 1.f + __expf(-rec));
                    const float a  = __expf(-sp * sr);
                    const float si = __fdividef(1.f, 1.f + __expf(-inp));
                    const float xc = __half2float(g_xc[row * HID + h]);
                    const float bp = sqrtf(1.f - a*a + 1e-8f) * si * xc;
                    g_alpha[row * HID + h] = a;
                    g_betap[row * HID + h] = bp;
                    sA[rloc * 64 + hloc] = a;
                    sB[rloc * 64 + hloc] = bp;
                }
            }
        }
        __syncthreads();
        {
            const int ch  = tid & 63;
            const int seg = tid >> 6;
            float Aprod = 1.f, Bacc = 0.f;
            int rr = seg * 32;
#pragma unroll 8
            for (int t = 0; t < 32; t++, rr++) {
                const float a = sA[rr * 64 + ch];
                const float p = sB[rr * 64 + ch];
                Bacc = fmaf(a, Bacc, p);
                Aprod *= a;
            }
            segb[(ch * 4 + seg) * 2]     = Aprod;
            segb[(ch * 4 + seg) * 2 + 1] = Bacc;
        }
        __syncthreads();
        if (tid < 64) {
            float At = 1.f, Bv = 0.f;
#pragma unroll
            for (int seg = 0; seg < 4; seg++) {
                const float a = segb[(tid * 4 + seg) * 2];
                const float p = segb[(tid * 4 + seg) * 2 + 1];
                Bv = fmaf(a, Bv, p);
                At *= a;
            }
            const int b  = (int)(brow >> 11);
            const int cc = (int)((brow >> 7) & 15);
            const int h  = (int)(bcol >> 1) + tid;
            g_cA[(b*NC + cc)*HID + h] = At;
            g_cB[(b*NC + cc)*HID + h] = Bv;
        }
        return;
    }

#pragma unroll
    for (int mi = 0; mi < 4; mi++) {
#pragma unroll
        for (int ni = 0; ni < 4; ni++) {
            const long col = bcol + colBase + ni*8 + tig*2;
            float b0 = 0.f, b1 = 0.f;
            if (bias) { b0 = __ldg(&bias[col]); b1 = __ldg(&bias[col+1]); }
#pragma unroll
            for (int half = 0; half < 2; half++) {
                const long row = brow + rowBase + mi*16 + gID + half*8;
                float v0 = acc[mi][ni][half*2]   + b0;
                float v1 = acc[mi][ni][half*2+1] + b1;
                if (mode == 1) {
                    v0 = __fdividef(v0, 1.f + __expf(-v0));
                    v1 = __fdividef(v1, 1.f + __expf(-v1));
                    *(__half2*)&Ch[row * N + col] = __floats2half2_rn(v0, v1);
                } else {
                    *(float2*)&Cf[row * N + col] = make_float2(v0, v1);
                }
            }
        }
    }
}

// ---------------------------------------------------------------------------
// fp16 GEMM + fused residual/LayerNorm. tile 128x256, 512 thr (2x8 warps).
// ---------------------------------------------------------------------------
#define TILE_A2 (128*PROW)           // 10240
#define TILE_B2 (256*PROW)           // 20480
#define OFF_B2  TILE_A2
#define STAGE2  (TILE_A2 + TILE_B2)  // 30720
#define LN_SMEM (2*STAGE2 + 2*128*4) // 62464

__global__ __launch_bounds__(512)
void mma_gemm_ln(const __half* __restrict__ A, const __half* __restrict__ Bt,
                 int K,
                 const float* __restrict__ bias,
                 const float* __restrict__ R,
                 const float* __restrict__ gamma, const float* __restrict__ beta,
                 float* __restrict__ Cf, __half* __restrict__ Ch)
{
    extern __shared__ __align__(128) char smem[];
    const uint32_t sb = smem_u32(smem);
    float* srow  = (float*)(smem + 2*STAGE2);
    float* srow2 = srow + 128;
    const int tid = threadIdx.x;
    const int wid = tid >> 5, lane = tid & 31;
    const long brow = (long)blockIdx.y * 128;

    const int rowBase = (wid >> 3) * 64;
    const int colBase = (wid & 7) * 32;

    float acc[4][4][4];
#pragma unroll
    for (int a = 0; a < 4; a++)
#pragma unroll
        for (int b = 0; b < 4; b++)
#pragma unroll
            for (int c = 0; c < 4; c++) acc[a][b][c] = 0.f;

    const int nch = K / BK;

    auto load_stage = [&](int s, int cidx){
        const uint32_t base = sb + s * STAGE2;
        const long kc = (long)cidx * BK;
#pragma unroll
        for (int i = tid; i < 1536; i += 512) {
            const int row = i >> 2, ch = i & 3;
            if (row < 128) {
                cp_async16(base + row * PROW + ch * 16,
                           A + (brow + row) * (long)K + kc + ch * 8);
            } else {
                const int br = row - 128;
                cp_async16(base + OFF_B2 + br * PROW + ch * 16,
                           Bt + br * (long)K + kc + ch * 8);
            }
        }
        cp_commit();
    };

    load_stage(0, 0);

    const int g = lane >> 3, r = lane & 7;

    for (int c = 0; c < nch; c++) {
        if (c + 1 < nch) { load_stage((c + 1) & 1, c + 1);
                           asm volatile("cp.async.wait_group 1;" ::: "memory"); }
        else             { asm volatile("cp.async.wait_group 0;" ::: "memory"); }
        __syncthreads();

        const uint32_t st = sb + (c & 1) * STAGE2;
#pragma unroll
        for (int ks = 0; ks < 2; ks++) {
            const int k0 = ks * 16;
            uint32_t bf[2][4];
#pragma unroll
            for (int p = 0; p < 2; p++) {
                const uint32_t boff =
                    (uint32_t)(colBase + p*16 + ((g >> 1) << 3) + r) * PROW
                    + (uint32_t)(k0 + ((g & 1) << 3)) * 2;
                LDSM4(bf[p], st + OFF_B2 + boff);
            }
#pragma unroll
            for (int mi = 0; mi < 4; mi++) {
                const uint32_t aoff =
                    (uint32_t)(rowBase + mi*16 + r + ((g & 1) << 3)) * PROW
                    + (uint32_t)(k0 + ((g >> 1) << 3)) * 2;
                uint32_t af[4];
                LDSM4(af, st + aoff);
#pragma unroll
                for (int ni = 0; ni < 4; ni++) {
                    const int p = ni >> 1, q = (ni & 1) * 2;
                    MMA_F16(acc[mi][ni], af, bf[p][q], bf[p][q+1]);
                }
            }
        }
        __syncthreads();
    }

    if (tid < 128) { srow[tid] = 0.f; srow2[tid] = 0.f; }
    __syncthreads();

    const int gID = lane >> 2, tig = lane & 3;

#pragma unroll
    for (int mi = 0; mi < 4; mi++) {
#pragma unroll
        for (int half = 0; half < 2; half++) {
            const int  rloc = rowBase + mi*16 + gID + half*8;
            const long row  = brow + rloc;
            float s = 0.f, s2 = 0.f;
#pragma unroll
            for (int ni = 0; ni < 4; ni++) {
                const int col = colBase + ni*8 + tig*2;
                float2 rv = *(const float2*)&R[row * DMODEL + col];
                float v0 = acc[mi][ni][half*2]   + rv.x;
                float v1 = acc[mi][ni][half*2+1] + rv.y;
                if (bias) { v0 += __ldg(&bias[col]); v1 += __ldg(&bias[col+1]); }
                acc[mi][ni][half*2]   = v0;
                acc[mi][ni][half*2+1] = v1;
                s  += v0 + v1;
                s2 += v0*v0 + v1*v1;
            }
            atomicAdd(&srow[rloc],  s);
            atomicAdd(&srow2[rloc], s2);
        }
    }
    __syncthreads();

#pragma unroll
    for (int mi = 0; mi < 4; mi++) {
#pragma unroll
        for (int half = 0; half < 2; half++) {
            const int  rloc = rowBase + mi*16 + gID + half*8;
            const long row  = brow + rloc;
            const float mean = srow[rloc] * (1.f / DMODEL);
            float var = srow2[rloc] * (1.f / DMODEL) - mean * mean;
            const float rs = rsqrtf(var + 1e-12f);
#pragma unroll
            for (int ni = 0; ni < 4; ni++) {
                const int col = colBase + ni*8 + tig*2;
                float2 gv = *(const float2*)&gamma[col];
                float2 bv = *(const float2*)&beta[col];
                float v0 = (acc[mi][ni][half*2]   - mean) * rs * gv.x + bv.x;
                float v1 = (acc[mi][ni][half*2+1] - mean) * rs * gv.y + bv.y;
                *(float2*)&Cf[row * DMODEL + col] = make_float2(v0, v1);
                if (Ch) *(__half2*)&Ch[row * DMODEL + col] = __floats2half2_rn(v0, v1);
            }
        }
    }
}

// ---------------------------------------------------------------------------
// Prep: splam/bias + all weight transposes (fp16) in one launch
// ---------------------------------------------------------------------------
#define WT_B0 1
#define WT_B1 (WT_B0 + (DMODEL*HID2)/256)
#define WT_B2 (WT_B1 + (HID*HID2)/256)
#define WT_B3 (WT_B2 + (HID*DMODEL)/256)
#define WT_B4 (WT_B3 + (DMODEL*INNER)/256)
#define WT_B5 (WT_B4 + (INNER*DMODEL)/256)

__global__ __launch_bounds__(256)
void prep_kernel(const float* __restrict__ Lambda, const float* __restrict__ b_gates,
                 const float* __restrict__ w_in, const float* __restrict__ w_gates,
                 const float* __restrict__ w_out, const float* __restrict__ ffn_w1,
                 const float* __restrict__ ffn_w2)
{
    const int blk = blockIdx.x;
    const int t = threadIdx.x;
    if (blk == 0) {
#pragma unroll
        for (int q = 0; q < 2; q++) {
            int h = t + q * 256;
            g_splam[h] = log1pf(expf(Lambda[h]));
            g_bil[2*h]     = b_gates[h];
            g_bil[2*h + 1] = b_gates[HID + h];
        }
        return;
    }
    const float* W; __half* WT; int K, N, il = 0; long base;
    if (blk < WT_B1)      { W = w_in;    WT = g_wiT; K = DMODEL; N = HID2;   base = (long)(blk - WT_B0) * 256; }
    else if (blk < WT_B2) { W = w_gates; WT = g_wgT; K = HID;    N = HID2;   base = (long)(blk - WT_B1) * 256; il = 1; }
    else if (blk < WT_B3) { W = w_out;   WT = g_woT; K = HID;    N = DMODEL; base = (long)(blk - WT_B2) * 256; }
    else if (blk < WT_B4) { W = ffn_w1;  WT = g_f1T; K = DMODEL; N = INNER;  base = (long)(blk - WT_B3) * 256; }
    else                  { W = ffn_w2;  WT = g_f2T; K = INNER;  N = DMODEL; base = (long)(blk - WT_B4) * 256; }
    const long i = base + t;
    const int k = (int)(i % K);
    const int n = (int)(i / K);
    const int col = il ? ((n >> 1) + (n & 1) * HID) : n;
    WT[i] = __float2half_rn(W[(long)k * N + col]);
}

__global__ void x2h_kernel(const float* __restrict__ in, long n4,
                           __half* __restrict__ out)
{
    long i = (long)blockIdx.x * blockDim.x + threadIdx.x;
    if (i >= n4) return;
    float4 v = ((const float4*)in)[i];
    __half2 h0 = __floats2half2_rn(v.x, v.y);
    __half2 h1 = __floats2half2_rn(v.z, v.w);
    ((__half2*)out)[2*i]   = h0;
    ((__half2*)out)[2*i+1] = h1;
}

// causal depthwise conv + bias + silu -> xc fp16. grid (SEQ, BATCH), no div/mod
__global__ __launch_bounds__(256)
void conv_silu_kernel(const float* __restrict__ conv_w,
                      const float* __restrict__ conv_b)
{
    const int t = blockIdx.x, b = blockIdx.y;
    const long base = ((long)b*SEQ + t)*HID2;
    const long obase = ((long)b*SEQ + t)*HID;
#pragma unroll
    for (int q = 0; q < 2; q++) {
        const int h = threadIdx.x + q * 256;
        float acc = conv_b[h];
#pragma unroll
        for (int k = 0; k < 4; k++) {
            const int tt = t - 3 + k;
            if (tt >= 0)
                acc = fmaf(g_xz[base + (long)(k-3)*HID2 + h], conv_w[h*4 + k], acc);
        }
        const float v = __fdividef(acc, 1.f + __expf(-acc));
        g_xc[obase + h] = __float2half_rn(v);
    }
}

// ---------------------------------------------------------------------------
// scan phases B and C
// ---------------------------------------------------------------------------
__global__ void scanB_kernel()
{
    int h = threadIdx.x;
    int b = blockIdx.x;
    float carry = 0.f;
    for (int c = 0; c < NC; c++) {
        int i = (b*NC + c)*HID + h;
        g_carry[i] = carry;
        carry = fmaf(g_cA[i], carry, g_cB[i]);
    }
}

__global__ void scanC_kernel()
{
    int h = threadIdx.x;
    int c = blockIdx.x % NC;
    int b = blockIdx.x / NC;
    float hr = g_carry[(b*NC + c)*HID + h];
    long base  = ((long)b*SEQ + c*CLEN)*HID  + h;
    long zbase = ((long)b*SEQ + c*CLEN)*HID2 + HID + h;
    for (int t = 0; t < CLEN; t++) {
        float a = g_alpha[base], p = g_betap[base];
        hr = fmaf(a, hr, p);
        float z  = g_xz[zbase];
        float sz = __fdividef(z, 1.f + __expf(-z));
        g_y[base] = __float2half_rn(sz * hr);
        base  += HID;
        zbase += HID2;
    }
}

// ---------------------------------------------------------------------------
// Launch
// ---------------------------------------------------------------------------
extern "C" void kernel_launch(void* const* d_in, const int* in_sizes, int n_in,
                              void* d_out, int out_size)
{
    const float* x      = (const float*)d_in[0];
    const float* w_in   = (const float*)d_in[1];
    const float* conv_w = (const float*)d_in[2];
    const float* conv_b = (const float*)d_in[3];
    const float* w_gates= (const float*)d_in[4];
    const float* b_gates= (const float*)d_in[5];
    const float* Lambda = (const float*)d_in[6];
    const float* w_out  = (const float*)d_in[7];
    const float* ln1_g  = (const float*)d_in[8];
    const float* ln1_b  = (const float*)d_in[9];
    const float* ffn_w1 = (const float*)d_in[10];
    const float* ffn_b1 = (const float*)d_in[11];
    const float* ffn_w2 = (const float*)d_in[12];
    const float* ffn_b2 = (const float*)d_in[13];
    const float* ln2_g  = (const float*)d_in[14];
    const float* ln2_b  = (const float*)d_in[15];

    static bool attr_set = false;
    if (!attr_set) {
        cudaFuncSetAttribute(mma_gemm,    cudaFuncAttributeMaxDynamicSharedMemorySize, GEMM_SMEM);
        cudaFuncSetAttribute(mma_gemm_ln, cudaFuncAttributeMaxDynamicSharedMemorySize, LN_SMEM);
        attr_set = true;
    }

    float *xz, *hs;
    __half *xr, *xc, *y, *hsh, *ff1, *wiT, *wgT, *woT, *f1T, *f2T;
    cudaGetSymbolAddress((void**)&xz,  g_xz);
    cudaGetSymbolAddress((void**)&hs,  g_hs);
    cudaGetSymbolAddress((void**)&xr,  g_xr);
    cudaGetSymbolAddress((void**)&xc,  g_xc);
    cudaGetSymbolAddress((void**)&y,   g_y);
    cudaGetSymbolAddress((void**)&hsh, g_hsh);
    cudaGetSymbolAddress((void**)&ff1, g_ff1);
    cudaGetSymbolAddress((void**)&wiT, g_wiT);
    cudaGetSymbolAddress((void**)&wgT, g_wgT);
    cudaGetSymbolAddress((void**)&woT, g_woT);
    cudaGetSymbolAddress((void**)&f1T, g_f1T);
    cudaGetSymbolAddress((void**)&f2T, g_f2T);

    const long nED = (long)NTOK * DMODEL;

    prep_kernel<<<WT_B5, 256>>>(Lambda, b_gates, w_in, w_gates, w_out, ffn_w1, ffn_w2);
    x2h_kernel<<<(int)((nED/4 + 255)/256), 256>>>(x, nED/4, xr);

    // 1. xz = x @ w_in  (fp32 out)
    mma_gemm<<<dim3(HID2/128, NTOK/128), 256, GEMM_SMEM>>>(
        xr, wiT, NTOK, HID2, DMODEL, nullptr, 0, xz, nullptr);
    // 2. conv + silu -> xc (fp16)
    conv_silu_kernel<<<dim3(SEQ, BATCH), 256>>>(conv_w, conv_b);
    // 3. gates GEMM + fused alpha/betap + chunk scanA
    mma_gemm<<<dim3(HID2/128, NTOK/128), 256, GEMM_SMEM>>>(
        xc, wgT, NTOK, HID2, HID, nullptr, 2, nullptr, nullptr);
    // 4-5. scan carry + full scan (y fp16)
    scanB_kernel<<<BATCH, HID>>>();
    scanC_kernel<<<BATCH*NC, HID>>>();
    // 6. hs = LN(y @ w_out + x)  (fp32 + fp16 copy)
    mma_gemm_ln<<<dim3(1, NTOK/128), 512, LN_SMEM>>>(
        y, woT, HID, nullptr, x, ln1_g, ln1_b, hs, hsh);
    // 7. ff1 = silu(hs @ ffn_w1 + b1)  (fp16)
    mma_gemm<<<dim3(INNER/128, NTOK/128), 256, GEMM_SMEM>>>(
        hsh, f1T, NTOK, INNER, DMODEL, ffn_b1, 1, nullptr, ff1);
    // 8. out = LN(ff1 @ ffn_w2 + b2 + hs)
    mma_gemm_ln<<<dim3(1, NTOK/128), 512, LN_SMEM>>>(
        ff1, f2T, INNER, ffn_b2, hs, ln2_g, ln2_b, (float*)d_out, nullptr);
}

// round 8
// speedup vs baseline: 4.1178x; 1.0231x over previous
#include <cuda_runtime.h>
#include <cuda_fp16.h>
#include <math.h>
#include <stdint.h>

#define BATCH  32
#define SEQ    2048
#define DMODEL 256
#define HID    512
#define HID2   1024
#define INNER  1024
#define NTOK   (BATCH*SEQ)   // 65536
#define NC     16
#define CLEN   (SEQ/NC)      // 128
#define CONV_CHUNK 128

// ---------------------------------------------------------------------------
// Scratch
// ---------------------------------------------------------------------------
__device__ float g_alpha[(size_t)NTOK*HID];
__device__ float g_betap[(size_t)NTOK*HID];
__device__ float g_hs   [(size_t)NTOK*DMODEL]; // fp32 residual for LN2
__device__ float g_cA   [BATCH*NC*HID];
__device__ float g_cB   [BATCH*NC*HID];
__device__ float g_carry[BATCH*NC*HID];
__device__ float g_splam[HID];
__device__ float g_bil  [HID2];
// fp16 buffers
__device__ __align__(256) __half g_xzh[(size_t)NTOK*HID2];  // [xh | z]
__device__ __align__(256) __half g_xr [(size_t)NTOK*DMODEL];
__device__ __align__(256) __half g_xc [(size_t)NTOK*HID];
__device__ __align__(256) __half g_y  [(size_t)NTOK*HID];
__device__ __align__(256) __half g_hsh[(size_t)NTOK*DMODEL];
__device__ __align__(256) __half g_ff1[(size_t)NTOK*INNER];
// transposed fp16 weights [N,K]
__device__ __align__(256) __half g_wiT[HID2*DMODEL];
__device__ __align__(256) __half g_wgT[HID2*HID];   // interleaved rec/inp cols
__device__ __align__(256) __half g_woT[DMODEL*HID];
__device__ __align__(256) __half g_f1T[INNER*DMODEL];
__device__ __align__(256) __half g_f2T[DMODEL*INNER];

// ---------------------------------------------------------------------------
// helpers
// ---------------------------------------------------------------------------
__device__ __forceinline__ uint32_t smem_u32(const void* p){
    uint32_t a;
    asm("{ .reg .u64 t; cvta.to.shared.u64 t, %1; cvt.u32.u64 %0, t; }"
        : "=r"(a) : "l"(p));
    return a;
}
__device__ __forceinline__ void cp_async16(uint32_t dst, const void* src){
    asm volatile("cp.async.cg.shared.global [%0], [%1], 16;" :: "r"(dst), "l"(src));
}
__device__ __forceinline__ void cp_commit(){ asm volatile("cp.async.commit_group;"); }

#define LDSM4(R, A) \
    asm volatile("ldmatrix.sync.aligned.m8n8.x4.shared.b16 {%0,%1,%2,%3}, [%4];" \
        : "=r"((R)[0]),"=r"((R)[1]),"=r"((R)[2]),"=r"((R)[3]) : "r"(A))

#define MMA_F16(C, A, B0, B1) \
    asm volatile("mma.sync.aligned.m16n8k16.row.col.f32.f16.f16.f32 " \
        "{%0,%1,%2,%3},{%4,%5,%6,%7},{%8,%9},{%0,%1,%2,%3};" \
        : "+f"((C)[0]),"+f"((C)[1]),"+f"((C)[2]),"+f"((C)[3]) \
        : "r"((A)[0]),"r"((A)[1]),"r"((A)[2]),"r"((A)[3]),"r"(B0),"r"(B1))

// ---------------------------------------------------------------------------
// fp16 GEMM (128x128 tile, 256 thr, BK=32, PROW=80)
// mode: 0 = plain, 1 = silu, 2 = fused gates epilogue
// output: Ch (fp16) if non-null, else Cf (fp32)
// ---------------------------------------------------------------------------
#define BK    32
#define PROW  80
#define SZ_T  (128*PROW)           // 10240
#define OFF_B SZ_T
#define STAGE (2*SZ_T)             // 20480
#define GEMM_SMEM_PLAIN (2*STAGE)  // 40960
#define GEMM_SMEM_GATES 69632      // >= overlay 2*32768 + 2048 = 67584

__global__ __launch_bounds__(256)
void mma_gemm(const __half* __restrict__ A, const __half* __restrict__ Bt,
              int M, int N, int K,
              const float* __restrict__ bias, int mode,
              float* __restrict__ Cf, __half* __restrict__ Ch)
{
    extern __shared__ __align__(128) char smem[];
    const uint32_t sb = smem_u32(smem);
    const int tid = threadIdx.x;
    const int wid = tid >> 5, lane = tid & 31;
    const long brow = (long)blockIdx.y * 128;
    const long bcol = (long)blockIdx.x * 128;

    const int rowBase = (wid >> 2) * 64;
    const int colBase = (wid & 3) * 32;

    float acc[4][4][4];
#pragma unroll
    for (int a = 0; a < 4; a++)
#pragma unroll
        for (int b = 0; b < 4; b++)
#pragma unroll
            for (int c = 0; c < 4; c++) acc[a][b][c] = 0.f;

    const int nch = K / BK;

    auto load_stage = [&](int s, int cidx){
        const uint32_t base = sb + s * STAGE;
        const long kc = (long)cidx * BK;
#pragma unroll
        for (int i = tid; i < 512; i += 256) {
            const int row = i >> 2, ch = i & 3;
            const uint32_t d = row * PROW + ch * 16;
            cp_async16(base + d,         A  + (brow + row) * (long)K + kc + ch * 8);
            cp_async16(base + OFF_B + d, Bt + (bcol + row) * (long)K + kc + ch * 8);
        }
        cp_commit();
    };

    load_stage(0, 0);

    const int g = lane >> 3, r = lane & 7;

    for (int c = 0; c < nch; c++) {
        if (c + 1 < nch) { load_stage((c + 1) & 1, c + 1);
                           asm volatile("cp.async.wait_group 1;" ::: "memory"); }
        else             { asm volatile("cp.async.wait_group 0;" ::: "memory"); }
        __syncthreads();

        const uint32_t st = sb + (c & 1) * STAGE;
#pragma unroll
        for (int ks = 0; ks < 2; ks++) {
            const int k0 = ks * 16;
            uint32_t bf[2][4];
#pragma unroll
            for (int p = 0; p < 2; p++) {
                const uint32_t boff =
                    (uint32_t)(colBase + p*16 + ((g >> 1) << 3) + r) * PROW
                    + (uint32_t)(k0 + ((g & 1) << 3)) * 2;
                LDSM4(bf[p], st + OFF_B + boff);
            }
#pragma unroll
            for (int mi = 0; mi < 4; mi++) {
                const uint32_t aoff =
                    (uint32_t)(rowBase + mi*16 + r + ((g & 1) << 3)) * PROW
                    + (uint32_t)(k0 + ((g >> 1) << 3)) * 2;
                uint32_t af[4];
                LDSM4(af, st + aoff);
#pragma unroll
                for (int ni = 0; ni < 4; ni++) {
                    const int p = ni >> 1, q = (ni & 1) * 2;
                    MMA_F16(acc[mi][ni], af, bf[p][q], bf[p][q+1]);
                }
            }
        }
        __syncthreads();
    }

    const int gID = lane >> 2, tig = lane & 3;

    if (mode == 2) {
        // fused gates epilogue + per-chunk scanA (tile rows == one scan chunk)
        float* sA   = (float*)smem;              // [128][64]  32768 B
        float* sB   = sA + 128*64;               // [128][64]  32768 B
        float* segb = sB + 128*64;               // [64][4][2]  2048 B
#pragma unroll
        for (int mi = 0; mi < 4; mi++) {
#pragma unroll
            for (int ni = 0; ni < 4; ni++) {
                const long col = bcol + colBase + ni*8 + tig*2;
                const int hloc = (colBase >> 1) + ni*4 + tig;
                const int h    = (int)(col >> 1);
#pragma unroll
                for (int half = 0; half < 2; half++) {
                    const int  rloc = rowBase + mi*16 + gID + half*8;
                    const long row  = brow + rloc;
                    const float rec = acc[mi][ni][half*2]   + g_bil[col];
                    const float inp = acc[mi][ni][half*2+1] + g_bil[col + 1];
                    const float sp = g_splam[h];
                    const float sr = __fdividef(1.f, 1.f + __expf(-rec));
                    const float a  = __expf(-sp * sr);
                    const float si = __fdividef(1.f, 1.f + __expf(-inp));
                    const float xc = __half2float(g_xc[row * HID + h]);
                    const float bp = sqrtf(1.f - a*a + 1e-8f) * si * xc;
                    g_alpha[row * HID + h] = a;
                    g_betap[row * HID + h] = bp;
                    sA[rloc * 64 + hloc] = a;
                    sB[rloc * 64 + hloc] = bp;
                }
            }
        }
        __syncthreads();
        {
            const int ch  = tid & 63;
            const int seg = tid >> 6;
            float Aprod = 1.f, Bacc = 0.f;
            int rr = seg * 32;
#pragma unroll 8
            for (int t = 0; t < 32; t++, rr++) {
                const float a = sA[rr * 64 + ch];
                const float p = sB[rr * 64 + ch];
                Bacc = fmaf(a, Bacc, p);
                Aprod *= a;
            }
            segb[(ch * 4 + seg) * 2]     = Aprod;
            segb[(ch * 4 + seg) * 2 + 1] = Bacc;
        }
        __syncthreads();
        if (tid < 64) {
            float At = 1.f, Bv = 0.f;
#pragma unroll
            for (int seg = 0; seg < 4; seg++) {
                const float a = segb[(tid * 4 + seg) * 2];
                const float p = segb[(tid * 4 + seg) * 2 + 1];
                Bv = fmaf(a, Bv, p);
                At *= a;
            }
            const int b  = (int)(brow >> 11);
            const int cc = (int)((brow >> 7) & 15);
            const int h  = (int)(bcol >> 1) + tid;
            g_cA[(b*NC + cc)*HID + h] = At;
            g_cB[(b*NC + cc)*HID + h] = Bv;
        }
        return;
    }

#pragma unroll
    for (int mi = 0; mi < 4; mi++) {
#pragma unroll
        for (int ni = 0; ni < 4; ni++) {
            const long col = bcol + colBase + ni*8 + tig*2;
            float b0 = 0.f, b1 = 0.f;
            if (bias) { b0 = __ldg(&bias[col]); b1 = __ldg(&bias[col+1]); }
#pragma unroll
            for (int half = 0; half < 2; half++) {
                const long row = brow + rowBase + mi*16 + gID + half*8;
                float v0 = acc[mi][ni][half*2]   + b0;
                float v1 = acc[mi][ni][half*2+1] + b1;
                if (mode == 1) {
                    v0 = __fdividef(v0, 1.f + __expf(-v0));
                    v1 = __fdividef(v1, 1.f + __expf(-v1));
                }
                if (Ch) *(__half2*)&Ch[row * N + col] = __floats2half2_rn(v0, v1);
                else    *(float2*)&Cf[row * N + col] = make_float2(v0, v1);
            }
        }
    }
}

// ---------------------------------------------------------------------------
// fp16 GEMM + fused residual/LayerNorm. tile 128x256, 512 thr (2x8 warps).
// ---------------------------------------------------------------------------
#define TILE_A2 (128*PROW)           // 10240
#define TILE_B2 (256*PROW)           // 20480
#define OFF_B2  TILE_A2
#define STAGE2  (TILE_A2 + TILE_B2)  // 30720
#define LN_SMEM (2*STAGE2 + 2*128*4) // 62464

__global__ __launch_bounds__(512)
void mma_gemm_ln(const __half* __restrict__ A, const __half* __restrict__ Bt,
                 int K,
                 const float* __restrict__ bias,
                 const float* __restrict__ R,
                 const float* __restrict__ gamma, const float* __restrict__ beta,
                 float* __restrict__ Cf, __half* __restrict__ Ch)
{
    extern __shared__ __align__(128) char smem[];
    const uint32_t sb = smem_u32(smem);
    float* srow  = (float*)(smem + 2*STAGE2);
    float* srow2 = srow + 128;
    const int tid = threadIdx.x;
    const int wid = tid >> 5, lane = tid & 31;
    const long brow = (long)blockIdx.y * 128;

    const int rowBase = (wid >> 3) * 64;
    const int colBase = (wid & 7) * 32;

    float acc[4][4][4];
#pragma unroll
    for (int a = 0; a < 4; a++)
#pragma unroll
        for (int b = 0; b < 4; b++)
#pragma unroll
            for (int c = 0; c < 4; c++) acc[a][b][c] = 0.f;

    const int nch = K / BK;

    auto load_stage = [&](int s, int cidx){
        const uint32_t base = sb + s * STAGE2;
        const long kc = (long)cidx * BK;
#pragma unroll
        for (int i = tid; i < 1536; i += 512) {
            const int row = i >> 2, ch = i & 3;
            if (row < 128) {
                cp_async16(base + row * PROW + ch * 16,
                           A + (brow + row) * (long)K + kc + ch * 8);
            } else {
                const int br = row - 128;
                cp_async16(base + OFF_B2 + br * PROW + ch * 16,
                           Bt + br * (long)K + kc + ch * 8);
            }
        }
        cp_commit();
    };

    load_stage(0, 0);

    const int g = lane >> 3, r = lane & 7;

    for (int c = 0; c < nch; c++) {
        if (c + 1 < nch) { load_stage((c + 1) & 1, c + 1);
                           asm volatile("cp.async.wait_group 1;" ::: "memory"); }
        else             { asm volatile("cp.async.wait_group 0;" ::: "memory"); }
        __syncthreads();

        const uint32_t st = sb + (c & 1) * STAGE2;
#pragma unroll
        for (int ks = 0; ks < 2; ks++) {
            const int k0 = ks * 16;
            uint32_t bf[2][4];
#pragma unroll
            for (int p = 0; p < 2; p++) {
                const uint32_t boff =
                    (uint32_t)(colBase + p*16 + ((g >> 1) << 3) + r) * PROW
                    + (uint32_t)(k0 + ((g & 1) << 3)) * 2;
                LDSM4(bf[p], st + OFF_B2 + boff);
            }
#pragma unroll
            for (int mi = 0; mi < 4; mi++) {
                const uint32_t aoff =
                    (uint32_t)(rowBase + mi*16 + r + ((g & 1) << 3)) * PROW
                    + (uint32_t)(k0 + ((g >> 1) << 3)) * 2;
                uint32_t af[4];
                LDSM4(af, st + aoff);
#pragma unroll
                for (int ni = 0; ni < 4; ni++) {
                    const int p = ni >> 1, q = (ni & 1) * 2;
                    MMA_F16(acc[mi][ni], af, bf[p][q], bf[p][q+1]);
                }
            }
        }
        __syncthreads();
    }

    if (tid < 128) { srow[tid] = 0.f; srow2[tid] = 0.f; }
    __syncthreads();

    const int gID = lane >> 2, tig = lane & 3;

#pragma unroll
    for (int mi = 0; mi < 4; mi++) {
#pragma unroll
        for (int half = 0; half < 2; half++) {
            const int  rloc = rowBase + mi*16 + gID + half*8;
            const long row  = brow + rloc;
            float s = 0.f, s2 = 0.f;
#pragma unroll
            for (int ni = 0; ni < 4; ni++) {
                const int col = colBase + ni*8 + tig*2;
                float2 rv = *(const float2*)&R[row * DMODEL + col];
                float v0 = acc[mi][ni][half*2]   + rv.x;
                float v1 = acc[mi][ni][half*2+1] + rv.y;
                if (bias) { v0 += __ldg(&bias[col]); v1 += __ldg(&bias[col+1]); }
                acc[mi][ni][half*2]   = v0;
                acc[mi][ni][half*2+1] = v1;
                s  += v0 + v1;
                s2 += v0*v0 + v1*v1;
            }
            atomicAdd(&srow[rloc],  s);
            atomicAdd(&srow2[rloc], s2);
        }
    }
    __syncthreads();

#pragma unroll
    for (int mi = 0; mi < 4; mi++) {
#pragma unroll
        for (int half = 0; half < 2; half++) {
            const int  rloc = rowBase + mi*16 + gID + half*8;
            const long row  = brow + rloc;
            const float mean = srow[rloc] * (1.f / DMODEL);
            float var = srow2[rloc] * (1.f / DMODEL) - mean * mean;
            const float rs = rsqrtf(var + 1e-12f);
#pragma unroll
            for (int ni = 0; ni < 4; ni++) {
                const int col = colBase + ni*8 + tig*2;
                float2 gv = *(const float2*)&gamma[col];
                float2 bv = *(const float2*)&beta[col];
                float v0 = (acc[mi][ni][half*2]   - mean) * rs * gv.x + bv.x;
                float v1 = (acc[mi][ni][half*2+1] - mean) * rs * gv.y + bv.y;
                *(float2*)&Cf[row * DMODEL + col] = make_float2(v0, v1);
                if (Ch) *(__half2*)&Ch[row * DMODEL + col] = __floats2half2_rn(v0, v1);
            }
        }
    }
}

// ---------------------------------------------------------------------------
// Prep: splam/bias + all weight transposes (fp16) in one launch
// ---------------------------------------------------------------------------
#define WT_B0 1
#define WT_B1 (WT_B0 + (DMODEL*HID2)/256)
#define WT_B2 (WT_B1 + (HID*HID2)/256)
#define WT_B3 (WT_B2 + (HID*DMODEL)/256)
#define WT_B4 (WT_B3 + (DMODEL*INNER)/256)
#define WT_B5 (WT_B4 + (INNER*DMODEL)/256)

__global__ __launch_bounds__(256)
void prep_kernel(const float* __restrict__ Lambda, const float* __restrict__ b_gates,
                 const float* __restrict__ w_in, const float* __restrict__ w_gates,
                 const float* __restrict__ w_out, const float* __restrict__ ffn_w1,
                 const float* __restrict__ ffn_w2)
{
    const int blk = blockIdx.x;
    const int t = threadIdx.x;
    if (blk == 0) {
#pragma unroll
        for (int q = 0; q < 2; q++) {
            int h = t + q * 256;
            g_splam[h] = log1pf(expf(Lambda[h]));
            g_bil[2*h]     = b_gates[h];
            g_bil[2*h + 1] = b_gates[HID + h];
        }
        return;
    }
    const float* W; __half* WT; int K, N, il = 0; long base;
    if (blk < WT_B1)      { W = w_in;    WT = g_wiT; K = DMODEL; N = HID2;   base = (long)(blk - WT_B0) * 256; }
    else if (blk < WT_B2) { W = w_gates; WT = g_wgT; K = HID;    N = HID2;   base = (long)(blk - WT_B1) * 256; il = 1; }
    else if (blk < WT_B3) { W = w_out;   WT = g_woT; K = HID;    N = DMODEL; base = (long)(blk - WT_B2) * 256; }
    else if (blk < WT_B4) { W = ffn_w1;  WT = g_f1T; K = DMODEL; N = INNER;  base = (long)(blk - WT_B3) * 256; }
    else                  { W = ffn_w2;  WT = g_f2T; K = INNER;  N = DMODEL; base = (long)(blk - WT_B4) * 256; }
    const long i = base + t;
    const int k = (int)(i % K);
    const int n = (int)(i / K);
    const int col = il ? ((n >> 1) + (n & 1) * HID) : n;
    WT[i] = __float2half_rn(W[(long)k * N + col]);
}

__global__ void x2h_kernel(const float* __restrict__ in, long n4,
                           __half* __restrict__ out)
{
    long i = (long)blockIdx.x * blockDim.x + threadIdx.x;
    if (i >= n4) return;
    float4 v = ((const float4*)in)[i];
    ((__half2*)out)[2*i]   = __floats2half2_rn(v.x, v.y);
    ((__half2*)out)[2*i+1] = __floats2half2_rn(v.z, v.w);
}

// ---------------------------------------------------------------------------
// Sliding-window causal depthwise conv (K=4) + bias + silu.
// Each thread: 2 channels (one half2) x CONV_CHUNK timesteps, 3-tap history
// in registers -> each xh element read exactly once.
// grid (SEQ/CONV_CHUNK, BATCH), block 256 (covers all 512 channels as half2)
// ---------------------------------------------------------------------------
__global__ __launch_bounds__(256)
void conv_silu_kernel(const float* __restrict__ conv_w,
                      const float* __restrict__ conv_b)
{
    const int h2 = threadIdx.x;              // half2 index: h = 2*h2
    const int b  = blockIdx.y;
    const int t0 = blockIdx.x * CONV_CHUNK;
    const int h  = h2 << 1;

    const float4 wa = *(const float4*)&conv_w[h * 4];
    const float4 wb = *(const float4*)&conv_w[h * 4 + 4];
    const float  ca = conv_b[h], cb = conv_b[h + 1];

    const __half2* xz = (const __half2*)g_xzh;
    const long rs = HID2 / 2;                // half2 per token row
    long base = ((long)b * SEQ + t0) * rs + h2;

    float a0 = 0.f, a1 = 0.f, a2 = 0.f;      // x[t-3], x[t-2], x[t-1] ch h
    float b0 = 0.f, b1 = 0.f, b2 = 0.f;      // same for ch h+1
    if (t0 >= 3) {
        __half2 p;
        p = xz[base - 3*rs]; a0 = __low2float(p); b0 = __high2float(p);
        p = xz[base - 2*rs]; a1 = __low2float(p); b1 = __high2float(p);
        p = xz[base - 1*rs]; a2 = __low2float(p); b2 = __high2float(p);
    }

    __half2* xcp = (__half2*)g_xc;
    long ob = ((long)b * SEQ + t0) * (HID / 2) + h2;

#pragma unroll 4
    for (int t = 0; t < CONV_CHUNK; t++) {
        const __half2 cur = xz[base]; base += rs;
        const float xa = __low2float(cur), xb = __high2float(cur);
        float va = ca, vb = cb;
        va = fmaf(wa.x, a0, va); va = fmaf(wa.y, a1, va);
        va = fmaf(wa.z, a2, va); va = fmaf(wa.w, xa, va);
        vb = fmaf(wb.x, b0, vb); vb = fmaf(wb.y, b1, vb);
        vb = fmaf(wb.z, b2, vb); vb = fmaf(wb.w, xb, vb);
        a0 = a1; a1 = a2; a2 = xa;
        b0 = b1; b1 = b2; b2 = xb;
        va = __fdividef(va, 1.f + __expf(-va));
        vb = __fdividef(vb, 1.f + __expf(-vb));
        xcp[ob] = __floats2half2_rn(va, vb);
        ob += HID / 2;
    }
}

// ---------------------------------------------------------------------------
// scan phases B and C
// ---------------------------------------------------------------------------
__global__ void scanB_kernel()
{
    int h = threadIdx.x;
    int b = blockIdx.x;
    float carry = 0.f;
    for (int c = 0; c < NC; c++) {
        int i = (b*NC + c)*HID + h;
        g_carry[i] = carry;
        carry = fmaf(g_cA[i], carry, g_cB[i]);
    }
}

__global__ void scanC_kernel()
{
    int h = threadIdx.x;
    int c = blockIdx.x % NC;
    int b = blockIdx.x / NC;
    float hr = g_carry[(b*NC + c)*HID + h];
    long base  = ((long)b*SEQ + c*CLEN)*HID  + h;
    long zbase = ((long)b*SEQ + c*CLEN)*HID2 + HID + h;
    for (int t = 0; t < CLEN; t++) {
        float a = g_alpha[base], p = g_betap[base];
        hr = fmaf(a, hr, p);
        float z  = __half2float(g_xzh[zbase]);
        float sz = __fdividef(z, 1.f + __expf(-z));
        g_y[base] = __float2half_rn(sz * hr);
        base  += HID;
        zbase += HID2;
    }
}

// ---------------------------------------------------------------------------
// Launch
// ---------------------------------------------------------------------------
extern "C" void kernel_launch(void* const* d_in, const int* in_sizes, int n_in,
                              void* d_out, int out_size)
{
    const float* x      = (const float*)d_in[0];
    const float* w_in   = (const float*)d_in[1];
    const float* conv_w = (const float*)d_in[2];
    const float* conv_b = (const float*)d_in[3];
    const float* w_gates= (const float*)d_in[4];
    const float* b_gates= (const float*)d_in[5];
    const float* Lambda = (const float*)d_in[6];
    const float* w_out  = (const float*)d_in[7];
    const float* ln1_g  = (const float*)d_in[8];
    const float* ln1_b  = (const float*)d_in[9];
    const float* ffn_w1 = (const float*)d_in[10];
    const float* ffn_b1 = (const float*)d_in[11];
    const float* ffn_w2 = (const float*)d_in[12];
    const float* ffn_b2 = (const float*)d_in[13];
    const float* ln2_g  = (const float*)d_in[14];
    const float* ln2_b  = (const float*)d_in[15];

    static bool attr_set = false;
    if (!attr_set) {
        cudaFuncSetAttribute(mma_gemm,    cudaFuncAttributeMaxDynamicSharedMemorySize, GEMM_SMEM_GATES);
        cudaFuncSetAttribute(mma_gemm_ln, cudaFuncAttributeMaxDynamicSharedMemorySize, LN_SMEM);
        attr_set = true;
    }

    float *hs;
    __half *xzh, *xr, *xc, *y, *hsh, *ff1, *wiT, *wgT, *woT, *f1T, *f2T;
    cudaGetSymbolAddress((void**)&hs,  g_hs);
    cudaGetSymbolAddress((void**)&xzh, g_xzh);
    cudaGetSymbolAddress((void**)&xr,  g_xr);
    cudaGetSymbolAddress((void**)&xc,  g_xc);
    cudaGetSymbolAddress((void**)&y,   g_y);
    cudaGetSymbolAddress((void**)&hsh, g_hsh);
    cudaGetSymbolAddress((void**)&ff1, g_ff1);
    cudaGetSymbolAddress((void**)&wiT, g_wiT);
    cudaGetSymbolAddress((void**)&wgT, g_wgT);
    cudaGetSymbolAddress((void**)&woT, g_woT);
    cudaGetSymbolAddress((void**)&f1T, g_f1T);
    cudaGetSymbolAddress((void**)&f2T, g_f2T);

    const long nED = (long)NTOK * DMODEL;

    prep_kernel<<<WT_B5, 256>>>(Lambda, b_gates, w_in, w_gates, w_out, ffn_w1, ffn_w2);
    x2h_kernel<<<(int)((nED/4 + 255)/256), 256>>>(x, nED/4, xr);

    // 1. xz = x @ w_in  (fp16 out)
    mma_gemm<<<dim3(HID2/128, NTOK/128), 256, GEMM_SMEM_PLAIN>>>(
        xr, wiT, NTOK, HID2, DMODEL, nullptr, 0, nullptr, xzh);
    // 2. sliding-window conv + silu -> xc (fp16)
    conv_silu_kernel<<<dim3(SEQ/CONV_CHUNK, BATCH), 256>>>(conv_w, conv_b);
    // 3. gates GEMM + fused alpha/betap + chunk scanA
    mma_gemm<<<dim3(HID2/128, NTOK/128), 256, GEMM_SMEM_GATES>>>(
        xc, wgT, NTOK, HID2, HID, nullptr, 2, nullptr, nullptr);
    // 4-5. scan carry + full scan (y fp16)
    scanB_kernel<<<BATCH, HID>>>();
    scanC_kernel<<<BATCH*NC, HID>>>();
    // 6. hs = LN(y @ w_out + x)  (fp32 + fp16 copy)
    mma_gemm_ln<<<dim3(1, NTOK/128), 512, LN_SMEM>>>(
        y, woT, HID, nullptr, x, ln1_g, ln1_b, hs, hsh);
    // 7. ff1 = silu(hs @ ffn_w1 + b1)  (fp16)
    mma_gemm<<<dim3(INNER/128, NTOK/128), 256, GEMM_SMEM_PLAIN>>>(
        hsh, f1T, NTOK, INNER, DMODEL, ffn_b1, 1, nullptr, ff1);
    // 8. out = LN(ff1 @ ffn_w2 + b2 + hs)
    mma_gemm_ln<<<dim3(1, NTOK/128), 512, LN_SMEM>>>(
        ff1, f2T, INNER, ffn_b2, hs, ln2_g, ln2_b, (float*)d_out, nullptr);
}

// round 9
// speedup vs baseline: 4.4683x; 1.0851x over previous
#include <cuda_runtime.h>
#include <cuda_fp16.h>
#include <math.h>
#include <stdint.h>

#define BATCH  32
#define SEQ    2048
#define DMODEL 256
#define HID    512
#define HID2   1024
#define INNER  1024
#define NTOK   (BATCH*SEQ)   // 65536
#define NC     16
#define CLEN   (SEQ/NC)      // 128
#define CONV_CHUNK 64

// ---------------------------------------------------------------------------
// Scratch
// ---------------------------------------------------------------------------
__device__ float g_hs   [(size_t)NTOK*DMODEL]; // fp32 residual for LN2
__device__ float g_cA   [BATCH*NC*HID];
__device__ float g_cB   [BATCH*NC*HID];
__device__ float g_carry[BATCH*NC*HID];
__device__ float g_splam[HID];
__device__ float g_bil  [HID2];
// packed per-step scan coefficients: (1-alpha, beta') per (token, channel)
__device__ __align__(256) __half2 g_ab[(size_t)NTOK*HID];   // 134 MB
// fp16 buffers
__device__ __align__(256) __half g_xzh[(size_t)NTOK*HID2];  // [xh | z]
__device__ __align__(256) __half g_xr [(size_t)NTOK*DMODEL];
__device__ __align__(256) __half g_xc [(size_t)NTOK*HID];
__device__ __align__(256) __half g_y  [(size_t)NTOK*HID];
__device__ __align__(256) __half g_hsh[(size_t)NTOK*DMODEL];
__device__ __align__(256) __half g_ff1[(size_t)NTOK*INNER];
// transposed fp16 weights [N,K]
__device__ __align__(256) __half g_wiT[HID2*DMODEL];
__device__ __align__(256) __half g_wgT[HID2*HID];   // interleaved rec/inp cols
__device__ __align__(256) __half g_woT[DMODEL*HID];
__device__ __align__(256) __half g_f1T[INNER*DMODEL];
__device__ __align__(256) __half g_f2T[DMODEL*INNER];

// ---------------------------------------------------------------------------
// helpers
// ---------------------------------------------------------------------------
__device__ __forceinline__ uint32_t smem_u32(const void* p){
    uint32_t a;
    asm("{ .reg .u64 t; cvta.to.shared.u64 t, %1; cvt.u32.u64 %0, t; }"
        : "=r"(a) : "l"(p));
    return a;
}
__device__ __forceinline__ void cp_async16(uint32_t dst, const void* src){
    asm volatile("cp.async.cg.shared.global [%0], [%1], 16;" :: "r"(dst), "l"(src));
}
__device__ __forceinline__ void cp_commit(){ asm volatile("cp.async.commit_group;"); }

#define LDSM4(R, A) \
    asm volatile("ldmatrix.sync.aligned.m8n8.x4.shared.b16 {%0,%1,%2,%3}, [%4];" \
        : "=r"((R)[0]),"=r"((R)[1]),"=r"((R)[2]),"=r"((R)[3]) : "r"(A))

#define MMA_F16(C, A, B0, B1) \
    asm volatile("mma.sync.aligned.m16n8k16.row.col.f32.f16.f16.f32 " \
        "{%0,%1,%2,%3},{%4,%5,%6,%7},{%8,%9},{%0,%1,%2,%3};" \
        : "+f"((C)[0]),"+f"((C)[1]),"+f"((C)[2]),"+f"((C)[3]) \
        : "r"((A)[0]),"r"((A)[1]),"r"((A)[2]),"r"((A)[3]),"r"(B0),"r"(B1))

// ---------------------------------------------------------------------------
// fp16 GEMM (128x128 tile, 256 thr, BK=32, PROW=80)
// mode: 0 = plain, 1 = silu, 2 = fused gates epilogue (+chunk scanA)
// output: Ch (fp16) if non-null, else Cf (fp32)
// ---------------------------------------------------------------------------
#define BK    32
#define PROW  80
#define SZ_T  (128*PROW)           // 10240
#define OFF_B SZ_T
#define STAGE (2*SZ_T)             // 20480
// pipeline 2*STAGE = 40960 ; mode-2 overlay = 128*64*4 + 2048 = 34816 -> fits
#define GEMM_SMEM (2*STAGE)

__global__ __launch_bounds__(256)
void mma_gemm(const __half* __restrict__ A, const __half* __restrict__ Bt,
              int M, int N, int K,
              const float* __restrict__ bias, int mode,
              float* __restrict__ Cf, __half* __restrict__ Ch)
{
    extern __shared__ __align__(128) char smem[];
    const uint32_t sb = smem_u32(smem);
    const int tid = threadIdx.x;
    const int wid = tid >> 5, lane = tid & 31;
    const long brow = (long)blockIdx.y * 128;
    const long bcol = (long)blockIdx.x * 128;

    const int rowBase = (wid >> 2) * 64;
    const int colBase = (wid & 3) * 32;

    float acc[4][4][4];
#pragma unroll
    for (int a = 0; a < 4; a++)
#pragma unroll
        for (int b = 0; b < 4; b++)
#pragma unroll
            for (int c = 0; c < 4; c++) acc[a][b][c] = 0.f;

    const int nch = K / BK;

    auto load_stage = [&](int s, int cidx){
        const uint32_t base = sb + s * STAGE;
        const long kc = (long)cidx * BK;
#pragma unroll
        for (int i = tid; i < 512; i += 256) {
            const int row = i >> 2, ch = i & 3;
            const uint32_t d = row * PROW + ch * 16;
            cp_async16(base + d,         A  + (brow + row) * (long)K + kc + ch * 8);
            cp_async16(base + OFF_B + d, Bt + (bcol + row) * (long)K + kc + ch * 8);
        }
        cp_commit();
    };

    load_stage(0, 0);

    const int g = lane >> 3, r = lane & 7;

    for (int c = 0; c < nch; c++) {
        if (c + 1 < nch) { load_stage((c + 1) & 1, c + 1);
                           asm volatile("cp.async.wait_group 1;" ::: "memory"); }
        else             { asm volatile("cp.async.wait_group 0;" ::: "memory"); }
        __syncthreads();

        const uint32_t st = sb + (c & 1) * STAGE;
#pragma unroll
        for (int ks = 0; ks < 2; ks++) {
            const int k0 = ks * 16;
            uint32_t bf[2][4];
#pragma unroll
            for (int p = 0; p < 2; p++) {
                const uint32_t boff =
                    (uint32_t)(colBase + p*16 + ((g >> 1) << 3) + r) * PROW
                    + (uint32_t)(k0 + ((g & 1) << 3)) * 2;
                LDSM4(bf[p], st + OFF_B + boff);
            }
#pragma unroll
            for (int mi = 0; mi < 4; mi++) {
                const uint32_t aoff =
                    (uint32_t)(rowBase + mi*16 + r + ((g & 1) << 3)) * PROW
                    + (uint32_t)(k0 + ((g >> 1) << 3)) * 2;
                uint32_t af[4];
                LDSM4(af, st + aoff);
#pragma unroll
                for (int ni = 0; ni < 4; ni++) {
                    const int p = ni >> 1, q = (ni & 1) * 2;
                    MMA_F16(acc[mi][ni], af, bf[p][q], bf[p][q+1]);
                }
            }
        }
        __syncthreads();
    }

    const int gID = lane >> 2, tig = lane & 3;

    if (mode == 2) {
        // fused gates epilogue + per-chunk scanA (tile rows == one scan chunk)
        // overlay: sAB [128][64] half2 (om, bp) = 32768 B, segb = 2048 B
        __half2* sAB  = (__half2*)smem;
        float*   segb = (float*)(smem + 128*64*4);
#pragma unroll
        for (int mi = 0; mi < 4; mi++) {
#pragma unroll
            for (int ni = 0; ni < 4; ni++) {
                const long col = bcol + colBase + ni*8 + tig*2;
                const int hloc = (colBase >> 1) + ni*4 + tig;
                const int h    = (int)(col >> 1);
#pragma unroll
                for (int half = 0; half < 2; half++) {
                    const int  rloc = rowBase + mi*16 + gID + half*8;
                    const long row  = brow + rloc;
                    const float rec = acc[mi][ni][half*2]   + g_bil[col];
                    const float inp = acc[mi][ni][half*2+1] + g_bil[col + 1];
                    const float sp = g_splam[h];
                    const float sr = __fdividef(1.f, 1.f + __expf(-rec));
                    const float om = -expm1f(-sp * sr);          // 1 - alpha
                    const float a  = 1.f - om;
                    const float si = __fdividef(1.f, 1.f + __expf(-inp));
                    const float xc = __half2float(g_xc[row * HID + h]);
                    const float bp = sqrtf(1.f - a*a + 1e-8f) * si * xc;
                    const __half2 pk = __floats2half2_rn(om, bp);
                    g_ab[row * HID + h] = pk;
                    sAB[rloc * 64 + hloc] = pk;
                }
            }
        }
        __syncthreads();
        {
            const int ch  = tid & 63;
            const int seg = tid >> 6;
            float Aprod = 1.f, Bacc = 0.f;
            int rr = seg * 32;
#pragma unroll 8
            for (int t = 0; t < 32; t++, rr++) {
                const __half2 pk = sAB[rr * 64 + ch];
                const float a = 1.f - __low2float(pk);
                const float p = __high2float(pk);
                Bacc = fmaf(a, Bacc, p);
                Aprod *= a;
            }
            segb[(ch * 4 + seg) * 2]     = Aprod;
            segb[(ch * 4 + seg) * 2 + 1] = Bacc;
        }
        __syncthreads();
        if (tid < 64) {
            float At = 1.f, Bv = 0.f;
#pragma unroll
            for (int seg = 0; seg < 4; seg++) {
                const float a = segb[(tid * 4 + seg) * 2];
                const float p = segb[(tid * 4 + seg) * 2 + 1];
                Bv = fmaf(a, Bv, p);
                At *= a;
            }
            const int b  = (int)(brow >> 11);
            const int cc = (int)((brow >> 7) & 15);
            const int h  = (int)(bcol >> 1) + tid;
            g_cA[(b*NC + cc)*HID + h] = At;
            g_cB[(b*NC + cc)*HID + h] = Bv;
        }
        return;
    }

#pragma unroll
    for (int mi = 0; mi < 4; mi++) {
#pragma unroll
        for (int ni = 0; ni < 4; ni++) {
            const long col = bcol + colBase + ni*8 + tig*2;
            float b0 = 0.f, b1 = 0.f;
            if (bias) { b0 = __ldg(&bias[col]); b1 = __ldg(&bias[col+1]); }
#pragma unroll
            for (int half = 0; half < 2; half++) {
                const long row = brow + rowBase + mi*16 + gID + half*8;
                float v0 = acc[mi][ni][half*2]   + b0;
                float v1 = acc[mi][ni][half*2+1] + b1;
                if (mode == 1) {
                    v0 = __fdividef(v0, 1.f + __expf(-v0));
                    v1 = __fdividef(v1, 1.f + __expf(-v1));
                }
                if (Ch) *(__half2*)&Ch[row * N + col] = __floats2half2_rn(v0, v1);
                else    *(float2*)&Cf[row * N + col] = make_float2(v0, v1);
            }
        }
    }
}

// ---------------------------------------------------------------------------
// fp16 GEMM + fused residual/LayerNorm. tile 128x256, 512 thr (2x8 warps).
// ---------------------------------------------------------------------------
#define TILE_A2 (128*PROW)           // 10240
#define TILE_B2 (256*PROW)           // 20480
#define OFF_B2  TILE_A2
#define STAGE2  (TILE_A2 + TILE_B2)  // 30720
#define LN_SMEM (2*STAGE2 + 2*128*4) // 62464

__global__ __launch_bounds__(512)
void mma_gemm_ln(const __half* __restrict__ A, const __half* __restrict__ Bt,
                 int K,
                 const float* __restrict__ bias,
                 const float* __restrict__ R,
                 const float* __restrict__ gamma, const float* __restrict__ beta,
                 float* __restrict__ Cf, __half* __restrict__ Ch)
{
    extern __shared__ __align__(128) char smem[];
    const uint32_t sb = smem_u32(smem);
    float* srow  = (float*)(smem + 2*STAGE2);
    float* srow2 = srow + 128;
    const int tid = threadIdx.x;
    const int wid = tid >> 5, lane = tid & 31;
    const long brow = (long)blockIdx.y * 128;

    const int rowBase = (wid >> 3) * 64;
    const int colBase = (wid & 7) * 32;

    float acc[4][4][4];
#pragma unroll
    for (int a = 0; a < 4; a++)
#pragma unroll
        for (int b = 0; b < 4; b++)
#pragma unroll
            for (int c = 0; c < 4; c++) acc[a][b][c] = 0.f;

    const int nch = K / BK;

    auto load_stage = [&](int s, int cidx){
        const uint32_t base = sb + s * STAGE2;
        const long kc = (long)cidx * BK;
#pragma unroll
        for (int i = tid; i < 1536; i += 512) {
            const int row = i >> 2, ch = i & 3;
            if (row < 128) {
                cp_async16(base + row * PROW + ch * 16,
                           A + (brow + row) * (long)K + kc + ch * 8);
            } else {
                const int br = row - 128;
                cp_async16(base + OFF_B2 + br * PROW + ch * 16,
                           Bt + br * (long)K + kc + ch * 8);
            }
        }
        cp_commit();
    };

    load_stage(0, 0);

    const int g = lane >> 3, r = lane & 7;

    for (int c = 0; c < nch; c++) {
        if (c + 1 < nch) { load_stage((c + 1) & 1, c + 1);
                           asm volatile("cp.async.wait_group 1;" ::: "memory"); }
        else             { asm volatile("cp.async.wait_group 0;" ::: "memory"); }
        __syncthreads();

        const uint32_t st = sb + (c & 1) * STAGE2;
#pragma unroll
        for (int ks = 0; ks < 2; ks++) {
            const int k0 = ks * 16;
            uint32_t bf[2][4];
#pragma unroll
            for (int p = 0; p < 2; p++) {
                const uint32_t boff =
                    (uint32_t)(colBase + p*16 + ((g >> 1) << 3) + r) * PROW
                    + (uint32_t)(k0 + ((g & 1) << 3)) * 2;
                LDSM4(bf[p], st + OFF_B2 + boff);
            }
#pragma unroll
            for (int mi = 0; mi < 4; mi++) {
                const uint32_t aoff =
                    (uint32_t)(rowBase + mi*16 + r + ((g & 1) << 3)) * PROW
                    + (uint32_t)(k0 + ((g >> 1) << 3)) * 2;
                uint32_t af[4];
                LDSM4(af, st + aoff);
#pragma unroll
                for (int ni = 0; ni < 4; ni++) {
                    const int p = ni >> 1, q = (ni & 1) * 2;
                    MMA_F16(acc[mi][ni], af, bf[p][q], bf[p][q+1]);
                }
            }
        }
        __syncthreads();
    }

    if (tid < 128) { srow[tid] = 0.f; srow2[tid] = 0.f; }
    __syncthreads();

    const int gID = lane >> 2, tig = lane & 3;

#pragma unroll
    for (int mi = 0; mi < 4; mi++) {
#pragma unroll
        for (int half = 0; half < 2; half++) {
            const int  rloc = rowBase + mi*16 + gID + half*8;
            const long row  = brow + rloc;
            float s = 0.f, s2 = 0.f;
#pragma unroll
            for (int ni = 0; ni < 4; ni++) {
                const int col = colBase + ni*8 + tig*2;
                float2 rv = *(const float2*)&R[row * DMODEL + col];
                float v0 = acc[mi][ni][half*2]   + rv.x;
                float v1 = acc[mi][ni][half*2+1] + rv.y;
                if (bias) { v0 += __ldg(&bias[col]); v1 += __ldg(&bias[col+1]); }
                acc[mi][ni][half*2]   = v0;
                acc[mi][ni][half*2+1] = v1;
                s  += v0 + v1;
                s2 += v0*v0 + v1*v1;
            }
            atomicAdd(&srow[rloc],  s);
            atomicAdd(&srow2[rloc], s2);
        }
    }
    __syncthreads();

#pragma unroll
    for (int mi = 0; mi < 4; mi++) {
#pragma unroll
        for (int half = 0; half < 2; half++) {
            const int  rloc = rowBase + mi*16 + gID + half*8;
            const long row  = brow + rloc;
            const float mean = srow[rloc] * (1.f / DMODEL);
            float var = srow2[rloc] * (1.f / DMODEL) - mean * mean;
            const float rs = rsqrtf(var + 1e-12f);
#pragma unroll
            for (int ni = 0; ni < 4; ni++) {
                const int col = colBase + ni*8 + tig*2;
                float2 gv = *(const float2*)&gamma[col];
                float2 bv = *(const float2*)&beta[col];
                float v0 = (acc[mi][ni][half*2]   - mean) * rs * gv.x + bv.x;
                float v1 = (acc[mi][ni][half*2+1] - mean) * rs * gv.y + bv.y;
                *(float2*)&Cf[row * DMODEL + col] = make_float2(v0, v1);
                if (Ch) *(__half2*)&Ch[row * DMODEL + col] = __floats2half2_rn(v0, v1);
            }
        }
    }
}

// ---------------------------------------------------------------------------
// Prep: splam/bias + all weight transposes (fp16) in one launch
// ---------------------------------------------------------------------------
#define WT_B0 1
#define WT_B1 (WT_B0 + (DMODEL*HID2)/256)
#define WT_B2 (WT_B1 + (HID*HID2)/256)
#define WT_B3 (WT_B2 + (HID*DMODEL)/256)
#define WT_B4 (WT_B3 + (DMODEL*INNER)/256)
#define WT_B5 (WT_B4 + (INNER*DMODEL)/256)

__global__ __launch_bounds__(256)
void prep_kernel(const float* __restrict__ Lambda, const float* __restrict__ b_gates,
                 const float* __restrict__ w_in, const float* __restrict__ w_gates,
                 const float* __restrict__ w_out, const float* __restrict__ ffn_w1,
                 const float* __restrict__ ffn_w2)
{
    const int blk = blockIdx.x;
    const int t = threadIdx.x;
    if (blk == 0) {
#pragma unroll
        for (int q = 0; q < 2; q++) {
            int h = t + q * 256;
            g_splam[h] = log1pf(expf(Lambda[h]));
            g_bil[2*h]     = b_gates[h];
            g_bil[2*h + 1] = b_gates[HID + h];
        }
        return;
    }
    const float* W; __half* WT; int K, N, il = 0; long base;
    if (blk < WT_B1)      { W = w_in;    WT = g_wiT; K = DMODEL; N = HID2;   base = (long)(blk - WT_B0) * 256; }
    else if (blk < WT_B2) { W = w_gates; WT = g_wgT; K = HID;    N = HID2;   base = (long)(blk - WT_B1) * 256; il = 1; }
    else if (blk < WT_B3) { W = w_out;   WT = g_woT; K = HID;    N = DMODEL; base = (long)(blk - WT_B2) * 256; }
    else if (blk < WT_B4) { W = ffn_w1;  WT = g_f1T; K = DMODEL; N = INNER;  base = (long)(blk - WT_B3) * 256; }
    else                  { W = ffn_w2;  WT = g_f2T; K = INNER;  N = DMODEL; base = (long)(blk - WT_B4) * 256; }
    const long i = base + t;
    const int k = (int)(i % K);
    const int n = (int)(i / K);
    const int col = il ? ((n >> 1) + (n & 1) * HID) : n;
    WT[i] = __float2half_rn(W[(long)k * N + col]);
}

__global__ void x2h_kernel(const float* __restrict__ in, long n4,
                           __half* __restrict__ out)
{
    long i = (long)blockIdx.x * blockDim.x + threadIdx.x;
    if (i >= n4) return;
    float4 v = ((const float4*)in)[i];
    ((__half2*)out)[2*i]   = __floats2half2_rn(v.x, v.y);
    ((__half2*)out)[2*i+1] = __floats2half2_rn(v.z, v.w);
}

// ---------------------------------------------------------------------------
// Sliding-window causal depthwise conv (K=4) + bias + silu.
// ---------------------------------------------------------------------------
__global__ __launch_bounds__(256)
void conv_silu_kernel(const float* __restrict__ conv_w,
                      const float* __restrict__ conv_b)
{
    const int h2 = threadIdx.x;              // half2 index: h = 2*h2
    const int b  = blockIdx.y;
    const int t0 = blockIdx.x * CONV_CHUNK;
    const int h  = h2 << 1;

    const float4 wa = *(const float4*)&conv_w[h * 4];
    const float4 wb = *(const float4*)&conv_w[h * 4 + 4];
    const float  ca = conv_b[h], cb = conv_b[h + 1];

    const __half2* xz = (const __half2*)g_xzh;
    const long rs = HID2 / 2;
    long base = ((long)b * SEQ + t0) * rs + h2;

    float a0 = 0.f, a1 = 0.f, a2 = 0.f;
    float b0 = 0.f, b1 = 0.f, b2 = 0.f;
    if (t0 >= 3) {
        __half2 p;
        p = xz[base - 3*rs]; a0 = __low2float(p); b0 = __high2float(p);
        p = xz[base - 2*rs]; a1 = __low2float(p); b1 = __high2float(p);
        p = xz[base - 1*rs]; a2 = __low2float(p); b2 = __high2float(p);
    }

    __half2* xcp = (__half2*)g_xc;
    long ob = ((long)b * SEQ + t0) * (HID / 2) + h2;

#pragma unroll 4
    for (int t = 0; t < CONV_CHUNK; t++) {
        const __half2 cur = xz[base]; base += rs;
        const float xa = __low2float(cur), xb = __high2float(cur);
        float va = ca, vb = cb;
        va = fmaf(wa.x, a0, va); va = fmaf(wa.y, a1, va);
        va = fmaf(wa.z, a2, va); va = fmaf(wa.w, xa, va);
        vb = fmaf(wb.x, b0, vb); vb = fmaf(wb.y, b1, vb);
        vb = fmaf(wb.z, b2, vb); vb = fmaf(wb.w, xb, vb);
        a0 = a1; a1 = a2; a2 = xa;
        b0 = b1; b1 = b2; b2 = xb;
        va = __fdividef(va, 1.f + __expf(-va));
        vb = __fdividef(vb, 1.f + __expf(-vb));
        xcp[ob] = __floats2half2_rn(va, vb);
        ob += HID / 2;
    }
}

// ---------------------------------------------------------------------------
// scan phases B and C
// ---------------------------------------------------------------------------
__global__ void scanB_kernel()
{
    int h = threadIdx.x;
    int b = blockIdx.x;
    float carry = 0.f;
    for (int c = 0; c < NC; c++) {
        int i = (b*NC + c)*HID + h;
        g_carry[i] = carry;
        carry = fmaf(g_cA[i], carry, g_cB[i]);
    }
}

__global__ void scanC_kernel()
{
    int h = threadIdx.x;
    int c = blockIdx.x % NC;
    int b = blockIdx.x / NC;
    float hr = g_carry[(b*NC + c)*HID + h];
    long base  = ((long)b*SEQ + c*CLEN)*HID  + h;
    long zbase = ((long)b*SEQ + c*CLEN)*HID2 + HID + h;
    for (int t = 0; t < CLEN; t++) {
        const __half2 pk = g_ab[base];
        const float om = __low2float(pk);      // 1 - alpha
        const float p  = __high2float(pk);     // beta'
        // h = (1-om)*h + p
        hr = fmaf(-om, hr, hr) + p;
        float z  = __half2float(g_xzh[zbase]);
        float sz = __fdividef(z, 1.f + __expf(-z));
        g_y[base] = __float2half_rn(sz * hr);
        base  += HID;
        zbase += HID2;
    }
}

// ---------------------------------------------------------------------------
// Launch
// ---------------------------------------------------------------------------
extern "C" void kernel_launch(void* const* d_in, const int* in_sizes, int n_in,
                              void* d_out, int out_size)
{
    const float* x      = (const float*)d_in[0];
    const float* w_in   = (const float*)d_in[1];
    const float* conv_w = (const float*)d_in[2];
    const float* conv_b = (const float*)d_in[3];
    const float* w_gates= (const float*)d_in[4];
    const float* b_gates= (const float*)d_in[5];
    const float* Lambda = (const float*)d_in[6];
    const float* w_out  = (const float*)d_in[7];
    const float* ln1_g  = (const float*)d_in[8];
    const float* ln1_b  = (const float*)d_in[9];
    const float* ffn_w1 = (const float*)d_in[10];
    const float* ffn_b1 = (const float*)d_in[11];
    const float* ffn_w2 = (const float*)d_in[12];
    const float* ffn_b2 = (const float*)d_in[13];
    const float* ln2_g  = (const float*)d_in[14];
    const float* ln2_b  = (const float*)d_in[15];

    static bool attr_set = false;
    if (!attr_set) {
        cudaFuncSetAttribute(mma_gemm,    cudaFuncAttributeMaxDynamicSharedMemorySize, GEMM_SMEM);
        cudaFuncSetAttribute(mma_gemm_ln, cudaFuncAttributeMaxDynamicSharedMemorySize, LN_SMEM);
        attr_set = true;
    }

    float *hs;
    __half *xzh, *xr, *xc, *y, *hsh, *ff1, *wiT, *wgT, *woT, *f1T, *f2T;
    cudaGetSymbolAddress((void**)&hs,  g_hs);
    cudaGetSymbolAddress((void**)&xzh, g_xzh);
    cudaGetSymbolAddress((void**)&xr,  g_xr);
    cudaGetSymbolAddress((void**)&xc,  g_xc);
    cudaGetSymbolAddress((void**)&y,   g_y);
    cudaGetSymbolAddress((void**)&hsh, g_hsh);
    cudaGetSymbolAddress((void**)&ff1, g_ff1);
    cudaGetSymbolAddress((void**)&wiT, g_wiT);
    cudaGetSymbolAddress((void**)&wgT, g_wgT);
    cudaGetSymbolAddress((void**)&woT, g_woT);
    cudaGetSymbolAddress((void**)&f1T, g_f1T);
    cudaGetSymbolAddress((void**)&f2T, g_f2T);

    const long nED = (long)NTOK * DMODEL;

    prep_kernel<<<WT_B5, 256>>>(Lambda, b_gates, w_in, w_gates, w_out, ffn_w1, ffn_w2);
    x2h_kernel<<<(int)((nED/4 + 255)/256), 256>>>(x, nED/4, xr);

    // 1. xz = x @ w_in  (fp16 out)
    mma_gemm<<<dim3(HID2/128, NTOK/128), 256, GEMM_SMEM>>>(
        xr, wiT, NTOK, HID2, DMODEL, nullptr, 0, nullptr, xzh);
    // 2. sliding-window conv + silu -> xc (fp16)
    conv_silu_kernel<<<dim3(SEQ/CONV_CHUNK, BATCH), 256>>>(conv_w, conv_b);
    // 3. gates GEMM + fused (1-alpha, beta') + chunk scanA
    mma_gemm<<<dim3(HID2/128, NTOK/128), 256, GEMM_SMEM>>>(
        xc, wgT, NTOK, HID2, HID, nullptr, 2, nullptr, nullptr);
    // 4-5. scan carry + full scan (y fp16)
    scanB_kernel<<<BATCH, HID>>>();
    scanC_kernel<<<BATCH*NC, HID>>>();
    // 6. hs = LN(y @ w_out + x)  (fp32 + fp16 copy)
    mma_gemm_ln<<<dim3(1, NTOK/128), 512, LN_SMEM>>>(
        y, woT, HID, nullptr, x, ln1_g, ln1_b, hs, hsh);
    // 7. ff1 = silu(hs @ ffn_w1 + b1)  (fp16)
    mma_gemm<<<dim3(INNER/128, NTOK/128), 256, GEMM_SMEM>>>(
        hsh, f1T, NTOK, INNER, DMODEL, ffn_b1, 1, nullptr, ff1);
    // 8. out = LN(ff1 @ ffn_w2 + b2 + hs)
    mma_gemm_ln<<<dim3(1, NTOK/128), 512, LN_SMEM>>>(
        ff1, f2T, INNER, ffn_b2, hs, ln2_g, ln2_b, (float*)d_out, nullptr);
}

// round 10
// speedup vs baseline: 4.4749x; 1.0015x over previous
#include <cuda_runtime.h>
#include <cuda_fp16.h>
#include <math.h>
#include <stdint.h>

#define BATCH  32
#define SEQ    2048
#define DMODEL 256
#define HID    512
#define HID2   1024
#define INNER  1024
#define NTOK   (BATCH*SEQ)   // 65536
#define NC     32
#define CLEN   (SEQ/NC)      // 64
#define CONV_CHUNK 32

// ---------------------------------------------------------------------------
// Scratch
// ---------------------------------------------------------------------------
__device__ float g_hs   [(size_t)NTOK*DMODEL]; // fp32 residual for LN2
__device__ float g_cA   [BATCH*NC*HID];
__device__ float g_cB   [BATCH*NC*HID];
__device__ float g_splam[HID];
__device__ float g_bil  [HID2];
// packed per-step scan coefficients: (1-alpha, beta') per (token, channel)
__device__ __align__(256) __half2 g_ab[(size_t)NTOK*HID];   // 134 MB
// fp16 buffers
__device__ __align__(256) __half g_xzh[(size_t)NTOK*HID2];  // [xh | z]
__device__ __align__(256) __half g_xr [(size_t)NTOK*DMODEL];
__device__ __align__(256) __half g_xc [(size_t)NTOK*HID];
__device__ __align__(256) __half g_y  [(size_t)NTOK*HID];
__device__ __align__(256) __half g_hsh[(size_t)NTOK*DMODEL];
__device__ __align__(256) __half g_ff1[(size_t)NTOK*INNER];
// transposed fp16 weights [N,K]
__device__ __align__(256) __half g_wiT[HID2*DMODEL];
__device__ __align__(256) __half g_wgT[HID2*HID];   // interleaved rec/inp cols
__device__ __align__(256) __half g_woT[DMODEL*HID];
__device__ __align__(256) __half g_f1T[INNER*DMODEL];
__device__ __align__(256) __half g_f2T[DMODEL*INNER];

// ---------------------------------------------------------------------------
// helpers
// ---------------------------------------------------------------------------
__device__ __forceinline__ uint32_t smem_u32(const void* p){
    uint32_t a;
    asm("{ .reg .u64 t; cvta.to.shared.u64 t, %1; cvt.u32.u64 %0, t; }"
        : "=r"(a) : "l"(p));
    return a;
}
__device__ __forceinline__ void cp_async16(uint32_t dst, const void* src){
    asm volatile("cp.async.cg.shared.global [%0], [%1], 16;" :: "r"(dst), "l"(src));
}
__device__ __forceinline__ void cp_commit(){ asm volatile("cp.async.commit_group;"); }

#define LDSM4(R, A) \
    asm volatile("ldmatrix.sync.aligned.m8n8.x4.shared.b16 {%0,%1,%2,%3}, [%4];" \
        : "=r"((R)[0]),"=r"((R)[1]),"=r"((R)[2]),"=r"((R)[3]) : "r"(A))

#define MMA_F16(C, A, B0, B1) \
    asm volatile("mma.sync.aligned.m16n8k16.row.col.f32.f16.f16.f32 " \
        "{%0,%1,%2,%3},{%4,%5,%6,%7},{%8,%9},{%0,%1,%2,%3};" \
        : "+f"((C)[0]),"+f"((C)[1]),"+f"((C)[2]),"+f"((C)[3]) \
        : "r"((A)[0]),"r"((A)[1]),"r"((A)[2]),"r"((A)[3]),"r"(B0),"r"(B1))

// ---------------------------------------------------------------------------
// fp16 GEMM (128x128 tile, 256 thr, BK=32, PROW=80)
// mode: 0 = plain, 1 = silu, 2 = fused gates epilogue (+2 chunk scanA's)
// output: Ch (fp16) if non-null, else Cf (fp32)
// ---------------------------------------------------------------------------
#define BK    32
#define PROW  80
#define SZ_T  (128*PROW)           // 10240
#define OFF_B SZ_T
#define STAGE (2*SZ_T)             // 20480
// pipeline 2*STAGE = 40960 ; mode-2 overlay = 128*64*4 + 2048 = 34816 -> fits
#define GEMM_SMEM (2*STAGE)

__global__ __launch_bounds__(256)
void mma_gemm(const __half* __restrict__ A, const __half* __restrict__ Bt,
              int M, int N, int K,
              const float* __restrict__ bias, int mode,
              float* __restrict__ Cf, __half* __restrict__ Ch)
{
    extern __shared__ __align__(128) char smem[];
    const uint32_t sb = smem_u32(smem);
    const int tid = threadIdx.x;
    const int wid = tid >> 5, lane = tid & 31;
    const long brow = (long)blockIdx.y * 128;
    const long bcol = (long)blockIdx.x * 128;

    const int rowBase = (wid >> 2) * 64;
    const int colBase = (wid & 3) * 32;

    float acc[4][4][4];
#pragma unroll
    for (int a = 0; a < 4; a++)
#pragma unroll
        for (int b = 0; b < 4; b++)
#pragma unroll
            for (int c = 0; c < 4; c++) acc[a][b][c] = 0.f;

    const int nch = K / BK;

    auto load_stage = [&](int s, int cidx){
        const uint32_t base = sb + s * STAGE;
        const long kc = (long)cidx * BK;
#pragma unroll
        for (int i = tid; i < 512; i += 256) {
            const int row = i >> 2, ch = i & 3;
            const uint32_t d = row * PROW + ch * 16;
            cp_async16(base + d,         A  + (brow + row) * (long)K + kc + ch * 8);
            cp_async16(base + OFF_B + d, Bt + (bcol + row) * (long)K + kc + ch * 8);
        }
        cp_commit();
    };

    load_stage(0, 0);

    const int g = lane >> 3, r = lane & 7;

    for (int c = 0; c < nch; c++) {
        if (c + 1 < nch) { load_stage((c + 1) & 1, c + 1);
                           asm volatile("cp.async.wait_group 1;" ::: "memory"); }
        else             { asm volatile("cp.async.wait_group 0;" ::: "memory"); }
        __syncthreads();

        const uint32_t st = sb + (c & 1) * STAGE;
#pragma unroll
        for (int ks = 0; ks < 2; ks++) {
            const int k0 = ks * 16;
            uint32_t bf[2][4];
#pragma unroll
            for (int p = 0; p < 2; p++) {
                const uint32_t boff =
                    (uint32_t)(colBase + p*16 + ((g >> 1) << 3) + r) * PROW
                    + (uint32_t)(k0 + ((g & 1) << 3)) * 2;
                LDSM4(bf[p], st + OFF_B + boff);
            }
#pragma unroll
            for (int mi = 0; mi < 4; mi++) {
                const uint32_t aoff =
                    (uint32_t)(rowBase + mi*16 + r + ((g & 1) << 3)) * PROW
                    + (uint32_t)(k0 + ((g >> 1) << 3)) * 2;
                uint32_t af[4];
                LDSM4(af, st + aoff);
#pragma unroll
                for (int ni = 0; ni < 4; ni++) {
                    const int p = ni >> 1, q = (ni & 1) * 2;
                    MMA_F16(acc[mi][ni], af, bf[p][q], bf[p][q+1]);
                }
            }
        }
        __syncthreads();
    }

    const int gID = lane >> 2, tig = lane & 3;

    if (mode == 2) {
        // fused gates epilogue; tile rows = 2 scan chunks of CLEN=64
        // overlay: sAB [128][64] half2 = 32768 B ; segb [64][4][2] = 2048 B
        __half2* sAB  = (__half2*)smem;
        float*   segb = (float*)(smem + 128*64*4);
#pragma unroll
        for (int mi = 0; mi < 4; mi++) {
#pragma unroll
            for (int ni = 0; ni < 4; ni++) {
                const long col = bcol + colBase + ni*8 + tig*2;
                const int hloc = (colBase >> 1) + ni*4 + tig;
                const int h    = (int)(col >> 1);
#pragma unroll
                for (int half = 0; half < 2; half++) {
                    const int  rloc = rowBase + mi*16 + gID + half*8;
                    const long row  = brow + rloc;
                    const float rec = acc[mi][ni][half*2]   + g_bil[col];
                    const float inp = acc[mi][ni][half*2+1] + g_bil[col + 1];
                    const float sp = g_splam[h];
                    const float sr = __fdividef(1.f, 1.f + __expf(-rec));
                    const float om = -expm1f(-sp * sr);          // 1 - alpha
                    const float a  = 1.f - om;
                    const float si = __fdividef(1.f, 1.f + __expf(-inp));
                    const float xc = __half2float(g_xc[row * HID + h]);
                    const float bp = sqrtf(1.f - a*a + 1e-8f) * si * xc;
                    const __half2 pk = __floats2half2_rn(om, bp);
                    g_ab[row * HID + h] = pk;
                    sAB[rloc * 64 + hloc] = pk;
                }
            }
        }
        __syncthreads();
        // per-chunk (64-row) segmented scan: 4 segments x 16 steps
        const int ch  = tid & 63;
        const int seg = tid >> 6;                 // 0..3
        const int b   = (int)(brow >> 11);        // /SEQ
        const int cc0 = (int)((brow >> 6) & (NC - 1));
#pragma unroll
        for (int sub = 0; sub < 2; sub++) {
            float Aprod = 1.f, Bacc = 0.f;
            int rr = sub * 64 + seg * 16;
#pragma unroll 8
            for (int t = 0; t < 16; t++, rr++) {
                const __half2 pk = sAB[rr * 64 + ch];
                const float a = 1.f - __low2float(pk);
                const float p = __high2float(pk);
                Bacc = fmaf(a, Bacc, p);
                Aprod *= a;
            }
            segb[(ch * 4 + seg) * 2]     = Aprod;
            segb[(ch * 4 + seg) * 2 + 1] = Bacc;
            __syncthreads();
            if (tid < 64) {
                float At = 1.f, Bv = 0.f;
#pragma unroll
                for (int s2 = 0; s2 < 4; s2++) {
                    const float a = segb[(tid * 4 + s2) * 2];
                    const float p = segb[(tid * 4 + s2) * 2 + 1];
                    Bv = fmaf(a, Bv, p);
                    At *= a;
                }
                const int h = (int)(bcol >> 1) + tid;
                g_cA[(b*NC + cc0 + sub)*HID + h] = At;
                g_cB[(b*NC + cc0 + sub)*HID + h] = Bv;
            }
            __syncthreads();
        }
        return;
    }

#pragma unroll
    for (int mi = 0; mi < 4; mi++) {
#pragma unroll
        for (int ni = 0; ni < 4; ni++) {
            const long col = bcol + colBase + ni*8 + tig*2;
            float b0 = 0.f, b1 = 0.f;
            if (bias) { b0 = __ldg(&bias[col]); b1 = __ldg(&bias[col+1]); }
#pragma unroll
            for (int half = 0; half < 2; half++) {
                const long row = brow + rowBase + mi*16 + gID + half*8;
                float v0 = acc[mi][ni][half*2]   + b0;
                float v1 = acc[mi][ni][half*2+1] + b1;
                if (mode == 1) {
                    v0 = __fdividef(v0, 1.f + __expf(-v0));
                    v1 = __fdividef(v1, 1.f + __expf(-v1));
                }
                if (Ch) *(__half2*)&Ch[row * N + col] = __floats2half2_rn(v0, v1);
                else    *(float2*)&Cf[row * N + col] = make_float2(v0, v1);
            }
        }
    }
}

// ---------------------------------------------------------------------------
// fp16 GEMM + fused residual/LayerNorm. tile 128x256, 512 thr (2x8 warps).
// ---------------------------------------------------------------------------
#define TILE_A2 (128*PROW)           // 10240
#define TILE_B2 (256*PROW)           // 20480
#define OFF_B2  TILE_A2
#define STAGE2  (TILE_A2 + TILE_B2)  // 30720
#define LN_SMEM (2*STAGE2 + 2*128*4) // 62464

__global__ __launch_bounds__(512)
void mma_gemm_ln(const __half* __restrict__ A, const __half* __restrict__ Bt,
                 int K,
                 const float* __restrict__ bias,
                 const float* __restrict__ R,
                 const float* __restrict__ gamma, const float* __restrict__ beta,
                 float* __restrict__ Cf, __half* __restrict__ Ch)
{
    extern __shared__ __align__(128) char smem[];
    const uint32_t sb = smem_u32(smem);
    float* srow  = (float*)(smem + 2*STAGE2);
    float* srow2 = srow + 128;
    const int tid = threadIdx.x;
    const int wid = tid >> 5, lane = tid & 31;
    const long brow = (long)blockIdx.y * 128;

    const int rowBase = (wid >> 3) * 64;
    const int colBase = (wid & 7) * 32;

    float acc[4][4][4];
#pragma unroll
    for (int a = 0; a < 4; a++)
#pragma unroll
        for (int b = 0; b < 4; b++)
#pragma unroll
            for (int c = 0; c < 4; c++) acc[a][b][c] = 0.f;

    const int nch = K / BK;

    auto load_stage = [&](int s, int cidx){
        const uint32_t base = sb + s * STAGE2;
        const long kc = (long)cidx * BK;
#pragma unroll
        for (int i = tid; i < 1536; i += 512) {
            const int row = i >> 2, ch = i & 3;
            if (row < 128) {
                cp_async16(base + row * PROW + ch * 16,
                           A + (brow + row) * (long)K + kc + ch * 8);
            } else {
                const int br = row - 128;
                cp_async16(base + OFF_B2 + br * PROW + ch * 16,
                           Bt + br * (long)K + kc + ch * 8);
            }
        }
        cp_commit();
    };

    load_stage(0, 0);

    const int g = lane >> 3, r = lane & 7;

    for (int c = 0; c < nch; c++) {
        if (c + 1 < nch) { load_stage((c + 1) & 1, c + 1);
                           asm volatile("cp.async.wait_group 1;" ::: "memory"); }
        else             { asm volatile("cp.async.wait_group 0;" ::: "memory"); }
        __syncthreads();

        const uint32_t st = sb + (c & 1) * STAGE2;
#pragma unroll
        for (int ks = 0; ks < 2; ks++) {
            const int k0 = ks * 16;
            uint32_t bf[2][4];
#pragma unroll
            for (int p = 0; p < 2; p++) {
                const uint32_t boff =
                    (uint32_t)(colBase + p*16 + ((g >> 1) << 3) + r) * PROW
                    + (uint32_t)(k0 + ((g & 1) << 3)) * 2;
                LDSM4(bf[p], st + OFF_B2 + boff);
            }
#pragma unroll
            for (int mi = 0; mi < 4; mi++) {
                const uint32_t aoff =
                    (uint32_t)(rowBase + mi*16 + r + ((g & 1) << 3)) * PROW
                    + (uint32_t)(k0 + ((g >> 1) << 3)) * 2;
                uint32_t af[4];
                LDSM4(af, st + aoff);
#pragma unroll
                for (int ni = 0; ni < 4; ni++) {
                    const int p = ni >> 1, q = (ni & 1) * 2;
                    MMA_F16(acc[mi][ni], af, bf[p][q], bf[p][q+1]);
                }
            }
        }
        __syncthreads();
    }

    if (tid < 128) { srow[tid] = 0.f; srow2[tid] = 0.f; }
    __syncthreads();

    const int gID = lane >> 2, tig = lane & 3;

#pragma unroll
    for (int mi = 0; mi < 4; mi++) {
#pragma unroll
        for (int half = 0; half < 2; half++) {
            const int  rloc = rowBase + mi*16 + gID + half*8;
            const long row  = brow + rloc;
            float s = 0.f, s2 = 0.f;
#pragma unroll
            for (int ni = 0; ni < 4; ni++) {
                const int col = colBase + ni*8 + tig*2;
                float2 rv = *(const float2*)&R[row * DMODEL + col];
                float v0 = acc[mi][ni][half*2]   + rv.x;
                float v1 = acc[mi][ni][half*2+1] + rv.y;
                if (bias) { v0 += __ldg(&bias[col]); v1 += __ldg(&bias[col+1]); }
                acc[mi][ni][half*2]   = v0;
                acc[mi][ni][half*2+1] = v1;
                s  += v0 + v1;
                s2 += v0*v0 + v1*v1;
            }
            atomicAdd(&srow[rloc],  s);
            atomicAdd(&srow2[rloc], s2);
        }
    }
    __syncthreads();

#pragma unroll
    for (int mi = 0; mi < 4; mi++) {
#pragma unroll
        for (int half = 0; half < 2; half++) {
            const int  rloc = rowBase + mi*16 + gID + half*8;
            const long row  = brow + rloc;
            const float mean = srow[rloc] * (1.f / DMODEL);
            float var = srow2[rloc] * (1.f / DMODEL) - mean * mean;
            const float rs = rsqrtf(var + 1e-12f);
#pragma unroll
            for (int ni = 0; ni < 4; ni++) {
                const int col = colBase + ni*8 + tig*2;
                float2 gv = *(const float2*)&gamma[col];
                float2 bv = *(const float2*)&beta[col];
                float v0 = (acc[mi][ni][half*2]   - mean) * rs * gv.x + bv.x;
                float v1 = (acc[mi][ni][half*2+1] - mean) * rs * gv.y + bv.y;
                *(float2*)&Cf[row * DMODEL + col] = make_float2(v0, v1);
                if (Ch) *(__half2*)&Ch[row * DMODEL + col] = __floats2half2_rn(v0, v1);
            }
        }
    }
}

// ---------------------------------------------------------------------------
// Prep: splam/bias + all weight transposes (fp16) in one launch
// ---------------------------------------------------------------------------
#define WT_B0 1
#define WT_B1 (WT_B0 + (DMODEL*HID2)/256)
#define WT_B2 (WT_B1 + (HID*HID2)/256)
#define WT_B3 (WT_B2 + (HID*DMODEL)/256)
#define WT_B4 (WT_B3 + (DMODEL*INNER)/256)
#define WT_B5 (WT_B4 + (INNER*DMODEL)/256)

__global__ __launch_bounds__(256)
void prep_kernel(const float* __restrict__ Lambda, const float* __restrict__ b_gates,
                 const float* __restrict__ w_in, const float* __restrict__ w_gates,
                 const float* __restrict__ w_out, const float* __restrict__ ffn_w1,
                 const float* __restrict__ ffn_w2)
{
    const int blk = blockIdx.x;
    const int t = threadIdx.x;
    if (blk == 0) {
#pragma unroll
        for (int q = 0; q < 2; q++) {
            int h = t + q * 256;
            g_splam[h] = log1pf(expf(Lambda[h]));
            g_bil[2*h]     = b_gates[h];
            g_bil[2*h + 1] = b_gates[HID + h];
        }
        return;
    }
    const float* W; __half* WT; int K, N, il = 0; long base;
    if (blk < WT_B1)      { W = w_in;    WT = g_wiT; K = DMODEL; N = HID2;   base = (long)(blk - WT_B0) * 256; }
    else if (blk < WT_B2) { W = w_gates; WT = g_wgT; K = HID;    N = HID2;   base = (long)(blk - WT_B1) * 256; il = 1; }
    else if (blk < WT_B3) { W = w_out;   WT = g_woT; K = HID;    N = DMODEL; base = (long)(blk - WT_B2) * 256; }
    else if (blk < WT_B4) { W = ffn_w1;  WT = g_f1T; K = DMODEL; N = INNER;  base = (long)(blk - WT_B3) * 256; }
    else                  { W = ffn_w2;  WT = g_f2T; K = INNER;  N = DMODEL; base = (long)(blk - WT_B4) * 256; }
    const long i = base + t;
    const int k = (int)(i % K);
    const int n = (int)(i / K);
    const int col = il ? ((n >> 1) + (n & 1) * HID) : n;
    WT[i] = __float2half_rn(W[(long)k * N + col]);
}

__global__ void x2h_kernel(const float* __restrict__ in, long n4,
                           __half* __restrict__ out)
{
    long i = (long)blockIdx.x * blockDim.x + threadIdx.x;
    if (i >= n4) return;
    float4 v = ((const float4*)in)[i];
    ((__half2*)out)[2*i]   = __floats2half2_rn(v.x, v.y);
    ((__half2*)out)[2*i+1] = __floats2half2_rn(v.z, v.w);
}

// ---------------------------------------------------------------------------
// Sliding-window causal depthwise conv (K=4) + bias + silu.
// ---------------------------------------------------------------------------
__global__ __launch_bounds__(256)
void conv_silu_kernel(const float* __restrict__ conv_w,
                      const float* __restrict__ conv_b)
{
    const int h2 = threadIdx.x;              // half2 index: h = 2*h2
    const int b  = blockIdx.y;
    const int t0 = blockIdx.x * CONV_CHUNK;
    const int h  = h2 << 1;

    const float4 wa = *(const float4*)&conv_w[h * 4];
    const float4 wb = *(const float4*)&conv_w[h * 4 + 4];
    const float  ca = conv_b[h], cb = conv_b[h + 1];

    const __half2* xz = (const __half2*)g_xzh;
    const long rs = HID2 / 2;
    long base = ((long)b * SEQ + t0) * rs + h2;

    float a0 = 0.f, a1 = 0.f, a2 = 0.f;
    float b0 = 0.f, b1 = 0.f, b2 = 0.f;
    if (t0 >= 3) {
        __half2 p;
        p = xz[base - 3*rs]; a0 = __low2float(p); b0 = __high2float(p);
        p = xz[base - 2*rs]; a1 = __low2float(p); b1 = __high2float(p);
        p = xz[base - 1*rs]; a2 = __low2float(p); b2 = __high2float(p);
    }

    __half2* xcp = (__half2*)g_xc;
    long ob = ((long)b * SEQ + t0) * (HID / 2) + h2;

#pragma unroll 4
    for (int t = 0; t < CONV_CHUNK; t++) {
        const __half2 cur = xz[base]; base += rs;
        const float xa = __low2float(cur), xb = __high2float(cur);
        float va = ca, vb = cb;
        va = fmaf(wa.x, a0, va); va = fmaf(wa.y, a1, va);
        va = fmaf(wa.z, a2, va); va = fmaf(wa.w, xa, va);
        vb = fmaf(wb.x, b0, vb); vb = fmaf(wb.y, b1, vb);
        vb = fmaf(wb.z, b2, vb); vb = fmaf(wb.w, xb, vb);
        a0 = a1; a1 = a2; a2 = xa;
        b0 = b1; b1 = b2; b2 = xb;
        va = __fdividef(va, 1.f + __expf(-va));
        vb = __fdividef(vb, 1.f + __expf(-vb));
        xcp[ob] = __floats2half2_rn(va, vb);
        ob += HID / 2;
    }
}

// ---------------------------------------------------------------------------
// scanC with integrated carry: block (b, c) recomputes its chunk carry from
// cA/cB[0..c) (same FMA sequence as the old scanB), then runs its CLEN steps.
// ---------------------------------------------------------------------------
__global__ void scanC_kernel()
{
    int h = threadIdx.x;
    int c = blockIdx.x % NC;
    int b = blockIdx.x / NC;

    float hr = 0.f;
    for (int j = 0; j < c; j++) {
        int i = (b*NC + j)*HID + h;
        hr = fmaf(g_cA[i], hr, g_cB[i]);
    }

    long base  = ((long)b*SEQ + c*CLEN)*HID  + h;
    long zbase = ((long)b*SEQ + c*CLEN)*HID2 + HID + h;
    for (int t = 0; t < CLEN; t++) {
        const __half2 pk = g_ab[base];
        const float om = __low2float(pk);      // 1 - alpha
        const float p  = __high2float(pk);     // beta'
        hr = fmaf(-om, hr, hr) + p;            // h = (1-om)*h + p
        float z  = __half2float(g_xzh[zbase]);
        float sz = __fdividef(z, 1.f + __expf(-z));
        g_y[base] = __float2half_rn(sz * hr);
        base  += HID;
        zbase += HID2;
    }
}

// ---------------------------------------------------------------------------
// Launch
// ---------------------------------------------------------------------------
extern "C" void kernel_launch(void* const* d_in, const int* in_sizes, int n_in,
                              void* d_out, int out_size)
{
    const float* x      = (const float*)d_in[0];
    const float* w_in   = (const float*)d_in[1];
    const float* conv_w = (const float*)d_in[2];
    const float* conv_b = (const float*)d_in[3];
    const float* w_gates= (const float*)d_in[4];
    const float* b_gates= (const float*)d_in[5];
    const float* Lambda = (const float*)d_in[6];
    const float* w_out  = (const float*)d_in[7];
    const float* ln1_g  = (const float*)d_in[8];
    const float* ln1_b  = (const float*)d_in[9];
    const float* ffn_w1 = (const float*)d_in[10];
    const float* ffn_b1 = (const float*)d_in[11];
    const float* ffn_w2 = (const float*)d_in[12];
    const float* ffn_b2 = (const float*)d_in[13];
    const float* ln2_g  = (const float*)d_in[14];
    const float* ln2_b  = (const float*)d_in[15];

    static bool attr_set = false;
    if (!attr_set) {
        cudaFuncSetAttribute(mma_gemm,    cudaFuncAttributeMaxDynamicSharedMemorySize, GEMM_SMEM);
        cudaFuncSetAttribute(mma_gemm_ln, cudaFuncAttributeMaxDynamicSharedMemorySize, LN_SMEM);
        attr_set = true;
    }

    float *hs;
    __half *xzh, *xr, *xc, *y, *hsh, *ff1, *wiT, *wgT, *woT, *f1T, *f2T;
    cudaGetSymbolAddress((void**)&hs,  g_hs);
    cudaGetSymbolAddress((void**)&xzh, g_xzh);
    cudaGetSymbolAddress((void**)&xr,  g_xr);
    cudaGetSymbolAddress((void**)&xc,  g_xc);
    cudaGetSymbolAddress((void**)&y,   g_y);
    cudaGetSymbolAddress((void**)&hsh, g_hsh);
    cudaGetSymbolAddress((void**)&ff1, g_ff1);
    cudaGetSymbolAddress((void**)&wiT, g_wiT);
    cudaGetSymbolAddress((void**)&wgT, g_wgT);
    cudaGetSymbolAddress((void**)&woT, g_woT);
    cudaGetSymbolAddress((void**)&f1T, g_f1T);
    cudaGetSymbolAddress((void**)&f2T, g_f2T);

    const long nED = (long)NTOK * DMODEL;

    prep_kernel<<<WT_B5, 256>>>(Lambda, b_gates, w_in, w_gates, w_out, ffn_w1, ffn_w2);
    x2h_kernel<<<(int)((nED/4 + 255)/256), 256>>>(x, nED/4, xr);

    // 1. xz = x @ w_in  (fp16 out)
    mma_gemm<<<dim3(HID2/128, NTOK/128), 256, GEMM_SMEM>>>(
        xr, wiT, NTOK, HID2, DMODEL, nullptr, 0, nullptr, xzh);
    // 2. sliding-window conv + silu -> xc (fp16)
    conv_silu_kernel<<<dim3(SEQ/CONV_CHUNK, BATCH), 256>>>(conv_w, conv_b);
    // 3. gates GEMM + fused (1-alpha, beta') + 2x chunk scanA per tile
    mma_gemm<<<dim3(HID2/128, NTOK/128), 256, GEMM_SMEM>>>(
        xc, wgT, NTOK, HID2, HID, nullptr, 2, nullptr, nullptr);
    // 4. scan (carry recomputed in-block) + y = silu(z)*h (fp16)
    scanC_kernel<<<BATCH*NC, HID>>>();
    // 5. hs = LN(y @ w_out + x)  (fp32 + fp16 copy)
    mma_gemm_ln<<<dim3(1, NTOK/128), 512, LN_SMEM>>>(
        y, woT, HID, nullptr, x, ln1_g, ln1_b, hs, hsh);
    // 6. ff1 = silu(hs @ ffn_w1 + b1)  (fp16)
    mma_gemm<<<dim3(INNER/128, NTOK/128), 256, GEMM_SMEM>>>(
        hsh, f1T, NTOK, INNER, DMODEL, ffn_b1, 1, nullptr, ff1);
    // 7. out = LN(ff1 @ ffn_w2 + b2 + hs)
    mma_gemm_ln<<<dim3(1, NTOK/128), 512, LN_SMEM>>>(
        ff1, f2T, INNER, ffn_b2, hs, ln2_g, ln2_b, (float*)d_out, nullptr);
}

// round 11
// speedup vs baseline: 4.6794x; 1.0457x over previous
#include <cuda_runtime.h>
#include <cuda_fp16.h>
#include <math.h>
#include <stdint.h>

#define BATCH  32
#define SEQ    2048
#define DMODEL 256
#define HID    512
#define HID2   1024
#define INNER  1024
#define NTOK   (BATCH*SEQ)   // 65536
#define NC     32
#define CLEN   (SEQ/NC)      // 64
#define CONV_CHUNK 32

// ---------------------------------------------------------------------------
// Scratch
// ---------------------------------------------------------------------------
__device__ float g_hs   [(size_t)NTOK*DMODEL]; // fp32 residual for LN2
__device__ float g_cA   [BATCH*NC*HID];
__device__ float g_cB   [BATCH*NC*HID];
__device__ float g_splam[HID];
__device__ float g_bil  [HID2];
// packed per-step scan coefficients: (1-alpha, beta') per (token, channel)
__device__ __align__(256) __half2 g_ab[(size_t)NTOK*HID];   // 134 MB
// fp16 buffers
__device__ __align__(256) __half g_xzh[(size_t)NTOK*HID2];  // [xh | z]
__device__ __align__(256) __half g_xr [(size_t)NTOK*DMODEL];
__device__ __align__(256) __half g_xc [(size_t)NTOK*HID];
__device__ __align__(256) __half g_y  [(size_t)NTOK*HID];
__device__ __align__(256) __half g_hsh[(size_t)NTOK*DMODEL];
__device__ __align__(256) __half g_ff1[(size_t)NTOK*INNER];
// transposed fp16 weights [N,K]
__device__ __align__(256) __half g_wiT[HID2*DMODEL];
__device__ __align__(256) __half g_wgT[HID2*HID];   // interleaved rec/inp cols
__device__ __align__(256) __half g_woT[DMODEL*HID];
__device__ __align__(256) __half g_f1T[INNER*DMODEL];
__device__ __align__(256) __half g_f2T[DMODEL*INNER];

// ---------------------------------------------------------------------------
// helpers
// ---------------------------------------------------------------------------
__device__ __forceinline__ uint32_t smem_u32(const void* p){
    uint32_t a;
    asm("{ .reg .u64 t; cvta.to.shared.u64 t, %1; cvt.u32.u64 %0, t; }"
        : "=r"(a) : "l"(p));
    return a;
}
__device__ __forceinline__ void cp_async16(uint32_t dst, const void* src){
    asm volatile("cp.async.cg.shared.global [%0], [%1], 16;" :: "r"(dst), "l"(src));
}
__device__ __forceinline__ void cp_commit(){ asm volatile("cp.async.commit_group;"); }

#define LDSM4(R, A) \
    asm volatile("ldmatrix.sync.aligned.m8n8.x4.shared.b16 {%0,%1,%2,%3}, [%4];" \
        : "=r"((R)[0]),"=r"((R)[1]),"=r"((R)[2]),"=r"((R)[3]) : "r"(A))

#define MMA_F16(C, A, B0, B1) \
    asm volatile("mma.sync.aligned.m16n8k16.row.col.f32.f16.f16.f32 " \
        "{%0,%1,%2,%3},{%4,%5,%6,%7},{%8,%9},{%0,%1,%2,%3};" \
        : "+f"((C)[0]),"+f"((C)[1]),"+f"((C)[2]),"+f"((C)[3]) \
        : "r"((A)[0]),"r"((A)[1]),"r"((A)[2]),"r"((A)[3]),"r"(B0),"r"(B1))

// ---------------------------------------------------------------------------
// fp16 GEMM (128x128 tile, 256 thr, BK=32, PROW=80)
// mode: 0 = plain, 1 = silu, 2 = fused gates epilogue (+2 chunk scanA's)
// col0: column offset of this launch's first tile (for split-N launches)
// output: Ch (fp16) if non-null, else Cf (fp32)
// ---------------------------------------------------------------------------
#define BK    32
#define PROW  80
#define SZ_T  (128*PROW)           // 10240
#define OFF_B SZ_T
#define STAGE (2*SZ_T)             // 20480
// pipeline 2*STAGE = 40960 ; mode-2 overlay = 128*64*4 + 2048 = 34816 -> fits
#define GEMM_SMEM (2*STAGE)

__global__ __launch_bounds__(256)
void mma_gemm(const __half* __restrict__ A, const __half* __restrict__ Bt,
              int M, int N, int K, int col0,
              const float* __restrict__ bias, int mode,
              float* __restrict__ Cf, __half* __restrict__ Ch)
{
    extern __shared__ __align__(128) char smem[];
    const uint32_t sb = smem_u32(smem);
    const int tid = threadIdx.x;
    const int wid = tid >> 5, lane = tid & 31;
    const long brow = (long)blockIdx.y * 128;
    const long bcol = (long)col0 + (long)blockIdx.x * 128;

    const int rowBase = (wid >> 2) * 64;
    const int colBase = (wid & 3) * 32;

    float acc[4][4][4];
#pragma unroll
    for (int a = 0; a < 4; a++)
#pragma unroll
        for (int b = 0; b < 4; b++)
#pragma unroll
            for (int c = 0; c < 4; c++) acc[a][b][c] = 0.f;

    const int nch = K / BK;

    auto load_stage = [&](int s, int cidx){
        const uint32_t base = sb + s * STAGE;
        const long kc = (long)cidx * BK;
#pragma unroll
        for (int i = tid; i < 512; i += 256) {
            const int row = i >> 2, ch = i & 3;
            const uint32_t d = row * PROW + ch * 16;
            cp_async16(base + d,         A  + (brow + row) * (long)K + kc + ch * 8);
            cp_async16(base + OFF_B + d, Bt + (bcol + row) * (long)K + kc + ch * 8);
        }
        cp_commit();
    };

    load_stage(0, 0);

    const int g = lane >> 3, r = lane & 7;

    for (int c = 0; c < nch; c++) {
        if (c + 1 < nch) { load_stage((c + 1) & 1, c + 1);
                           asm volatile("cp.async.wait_group 1;" ::: "memory"); }
        else             { asm volatile("cp.async.wait_group 0;" ::: "memory"); }
        __syncthreads();

        const uint32_t st = sb + (c & 1) * STAGE;
#pragma unroll
        for (int ks = 0; ks < 2; ks++) {
            const int k0 = ks * 16;
            uint32_t bf[2][4];
#pragma unroll
            for (int p = 0; p < 2; p++) {
                const uint32_t boff =
                    (uint32_t)(colBase + p*16 + ((g >> 1) << 3) + r) * PROW
                    + (uint32_t)(k0 + ((g & 1) << 3)) * 2;
                LDSM4(bf[p], st + OFF_B + boff);
            }
#pragma unroll
            for (int mi = 0; mi < 4; mi++) {
                const uint32_t aoff =
                    (uint32_t)(rowBase + mi*16 + r + ((g & 1) << 3)) * PROW
                    + (uint32_t)(k0 + ((g >> 1) << 3)) * 2;
                uint32_t af[4];
                LDSM4(af, st + aoff);
#pragma unroll
                for (int ni = 0; ni < 4; ni++) {
                    const int p = ni >> 1, q = (ni & 1) * 2;
                    MMA_F16(acc[mi][ni], af, bf[p][q], bf[p][q+1]);
                }
            }
        }
        __syncthreads();
    }

    const int gID = lane >> 2, tig = lane & 3;

    if (mode == 2) {
        // fused gates epilogue; tile rows = 2 scan chunks of CLEN=64
        // overlay: sAB [128][64] half2 = 32768 B ; segb [64][4][2] = 2048 B
        __half2* sAB  = (__half2*)smem;
        float*   segb = (float*)(smem + 128*64*4);
#pragma unroll
        for (int mi = 0; mi < 4; mi++) {
#pragma unroll
            for (int ni = 0; ni < 4; ni++) {
                const long col = bcol + colBase + ni*8 + tig*2;
                const int hloc = (colBase >> 1) + ni*4 + tig;
                const int h    = (int)(col >> 1);
#pragma unroll
                for (int half = 0; half < 2; half++) {
                    const int  rloc = rowBase + mi*16 + gID + half*8;
                    const long row  = brow + rloc;
                    const float rec = acc[mi][ni][half*2]   + g_bil[col];
                    const float inp = acc[mi][ni][half*2+1] + g_bil[col + 1];
                    const float sp = g_splam[h];
                    const float sr = __fdividef(1.f, 1.f + __expf(-rec));
                    const float om = -expm1f(-sp * sr);          // 1 - alpha
                    const float a  = 1.f - om;
                    const float si = __fdividef(1.f, 1.f + __expf(-inp));
                    const float xc = __half2float(g_xc[row * HID + h]);
                    const float bp = sqrtf(1.f - a*a + 1e-8f) * si * xc;
                    const __half2 pk = __floats2half2_rn(om, bp);
                    g_ab[row * HID + h] = pk;
                    sAB[rloc * 64 + hloc] = pk;
                }
            }
        }
        __syncthreads();
        // per-chunk (64-row) segmented scan: 4 segments x 16 steps
        const int ch  = tid & 63;
        const int seg = tid >> 6;                 // 0..3
        const int b   = (int)(brow >> 11);        // /SEQ
        const int cc0 = (int)((brow >> 6) & (NC - 1));
#pragma unroll
        for (int sub = 0; sub < 2; sub++) {
            float Aprod = 1.f, Bacc = 0.f;
            int rr = sub * 64 + seg * 16;
#pragma unroll 8
            for (int t = 0; t < 16; t++, rr++) {
                const __half2 pk = sAB[rr * 64 + ch];
                const float a = 1.f - __low2float(pk);
                const float p = __high2float(pk);
                Bacc = fmaf(a, Bacc, p);
                Aprod *= a;
            }
            segb[(ch * 4 + seg) * 2]     = Aprod;
            segb[(ch * 4 + seg) * 2 + 1] = Bacc;
            __syncthreads();
            if (tid < 64) {
                float At = 1.f, Bv = 0.f;
#pragma unroll
                for (int s2 = 0; s2 < 4; s2++) {
                    const float a = segb[(tid * 4 + s2) * 2];
                    const float p = segb[(tid * 4 + s2) * 2 + 1];
                    Bv = fmaf(a, Bv, p);
                    At *= a;
                }
                const int h = (int)(bcol >> 1) + tid;
                g_cA[(b*NC + cc0 + sub)*HID + h] = At;
                g_cB[(b*NC + cc0 + sub)*HID + h] = Bv;
            }
            __syncthreads();
        }
        return;
    }

#pragma unroll
    for (int mi = 0; mi < 4; mi++) {
#pragma unroll
        for (int ni = 0; ni < 4; ni++) {
            const long col = bcol + colBase + ni*8 + tig*2;
            float b0 = 0.f, b1 = 0.f;
            if (bias) { b0 = __ldg(&bias[col]); b1 = __ldg(&bias[col+1]); }
#pragma unroll
            for (int half = 0; half < 2; half++) {
                const long row = brow + rowBase + mi*16 + gID + half*8;
                float v0 = acc[mi][ni][half*2]   + b0;
                float v1 = acc[mi][ni][half*2+1] + b1;
                if (mode == 1) {
                    v0 = __fdividef(v0, 1.f + __expf(-v0));
                    v1 = __fdividef(v1, 1.f + __expf(-v1));
                }
                if (Ch) *(__half2*)&Ch[row * N + col] = __floats2half2_rn(v0, v1);
                else    *(float2*)&Cf[row * N + col] = make_float2(v0, v1);
            }
        }
    }
}

// ---------------------------------------------------------------------------
// fp16 GEMM + fused residual/LayerNorm. tile 128x256, 512 thr (2x8 warps).
// ---------------------------------------------------------------------------
#define TILE_A2 (128*PROW)           // 10240
#define TILE_B2 (256*PROW)           // 20480
#define OFF_B2  TILE_A2
#define STAGE2  (TILE_A2 + TILE_B2)  // 30720
#define LN_SMEM (2*STAGE2 + 2*128*4) // 62464

__global__ __launch_bounds__(512)
void mma_gemm_ln(const __half* __restrict__ A, const __half* __restrict__ Bt,
                 int K,
                 const float* __restrict__ bias,
                 const float* __restrict__ R,
                 const float* __restrict__ gamma, const float* __restrict__ beta,
                 float* __restrict__ Cf, __half* __restrict__ Ch)
{
    extern __shared__ __align__(128) char smem[];
    const uint32_t sb = smem_u32(smem);
    float* srow  = (float*)(smem + 2*STAGE2);
    float* srow2 = srow + 128;
    const int tid = threadIdx.x;
    const int wid = tid >> 5, lane = tid & 31;
    const long brow = (long)blockIdx.y * 128;

    const int rowBase = (wid >> 3) * 64;
    const int colBase = (wid & 7) * 32;

    float acc[4][4][4];
#pragma unroll
    for (int a = 0; a < 4; a++)
#pragma unroll
        for (int b = 0; b < 4; b++)
#pragma unroll
            for (int c = 0; c < 4; c++) acc[a][b][c] = 0.f;

    const int nch = K / BK;

    auto load_stage = [&](int s, int cidx){
        const uint32_t base = sb + s * STAGE2;
        const long kc = (long)cidx * BK;
#pragma unroll
        for (int i = tid; i < 1536; i += 512) {
            const int row = i >> 2, ch = i & 3;
            if (row < 128) {
                cp_async16(base + row * PROW + ch * 16,
                           A + (brow + row) * (long)K + kc + ch * 8);
            } else {
                const int br = row - 128;
                cp_async16(base + OFF_B2 + br * PROW + ch * 16,
                           Bt + br * (long)K + kc + ch * 8);
            }
        }
        cp_commit();
    };

    load_stage(0, 0);

    const int g = lane >> 3, r = lane & 7;

    for (int c = 0; c < nch; c++) {
        if (c + 1 < nch) { load_stage((c + 1) & 1, c + 1);
                           asm volatile("cp.async.wait_group 1;" ::: "memory"); }
        else             { asm volatile("cp.async.wait_group 0;" ::: "memory"); }
        __syncthreads();

        const uint32_t st = sb + (c & 1) * STAGE2;
#pragma unroll
        for (int ks = 0; ks < 2; ks++) {
            const int k0 = ks * 16;
            uint32_t bf[2][4];
#pragma unroll
            for (int p = 0; p < 2; p++) {
                const uint32_t boff =
                    (uint32_t)(colBase + p*16 + ((g >> 1) << 3) + r) * PROW
                    + (uint32_t)(k0 + ((g & 1) << 3)) * 2;
                LDSM4(bf[p], st + OFF_B2 + boff);
            }
#pragma unroll
            for (int mi = 0; mi < 4; mi++) {
                const uint32_t aoff =
                    (uint32_t)(rowBase + mi*16 + r + ((g & 1) << 3)) * PROW
                    + (uint32_t)(k0 + ((g >> 1) << 3)) * 2;
                uint32_t af[4];
                LDSM4(af, st + aoff);
#pragma unroll
                for (int ni = 0; ni < 4; ni++) {
                    const int p = ni >> 1, q = (ni & 1) * 2;
                    MMA_F16(acc[mi][ni], af, bf[p][q], bf[p][q+1]);
                }
            }
        }
        __syncthreads();
    }

    if (tid < 128) { srow[tid] = 0.f; srow2[tid] = 0.f; }
    __syncthreads();

    const int gID = lane >> 2, tig = lane & 3;

#pragma unroll
    for (int mi = 0; mi < 4; mi++) {
#pragma unroll
        for (int half = 0; half < 2; half++) {
            const int  rloc = rowBase + mi*16 + gID + half*8;
            const long row  = brow + rloc;
            float s = 0.f, s2 = 0.f;
#pragma unroll
            for (int ni = 0; ni < 4; ni++) {
                const int col = colBase + ni*8 + tig*2;
                float2 rv = *(const float2*)&R[row * DMODEL + col];
                float v0 = acc[mi][ni][half*2]   + rv.x;
                float v1 = acc[mi][ni][half*2+1] + rv.y;
                if (bias) { v0 += __ldg(&bias[col]); v1 += __ldg(&bias[col+1]); }
                acc[mi][ni][half*2]   = v0;
                acc[mi][ni][half*2+1] = v1;
                s  += v0 + v1;
                s2 += v0*v0 + v1*v1;
            }
            atomicAdd(&srow[rloc],  s);
            atomicAdd(&srow2[rloc], s2);
        }
    }
    __syncthreads();

#pragma unroll
    for (int mi = 0; mi < 4; mi++) {
#pragma unroll
        for (int half = 0; half < 2; half++) {
            const int  rloc = rowBase + mi*16 + gID + half*8;
            const long row  = brow + rloc;
            const float mean = srow[rloc] * (1.f / DMODEL);
            float var = srow2[rloc] * (1.f / DMODEL) - mean * mean;
            const float rs = rsqrtf(var + 1e-12f);
#pragma unroll
            for (int ni = 0; ni < 4; ni++) {
                const int col = colBase + ni*8 + tig*2;
                float2 gv = *(const float2*)&gamma[col];
                float2 bv = *(const float2*)&beta[col];
                float v0 = (acc[mi][ni][half*2]   - mean) * rs * gv.x + bv.x;
                float v1 = (acc[mi][ni][half*2+1] - mean) * rs * gv.y + bv.y;
                *(float2*)&Cf[row * DMODEL + col] = make_float2(v0, v1);
                if (Ch) *(__half2*)&Ch[row * DMODEL + col] = __floats2half2_rn(v0, v1);
            }
        }
    }
}

// ---------------------------------------------------------------------------
// Prep: splam/bias + all weight transposes + x->fp16 in ONE launch
// ---------------------------------------------------------------------------
#define WT_B0 1
#define WT_B1 (WT_B0 + (DMODEL*HID2)/256)
#define WT_B2 (WT_B1 + (HID*HID2)/256)
#define WT_B3 (WT_B2 + (HID*DMODEL)/256)
#define WT_B4 (WT_B3 + (DMODEL*INNER)/256)
#define WT_B5 (WT_B4 + (INNER*DMODEL)/256)
#define XH_BLKS ((NTOK*DMODEL/4)/256)     // 16384 blocks, float4 granularity
#define WT_B6 (WT_B5 + XH_BLKS)

__global__ __launch_bounds__(256)
void prep_kernel(const float* __restrict__ Lambda, const float* __restrict__ b_gates,
                 const float* __restrict__ w_in, const float* __restrict__ w_gates,
                 const float* __restrict__ w_out, const float* __restrict__ ffn_w1,
                 const float* __restrict__ ffn_w2, const float* __restrict__ x)
{
    const int blk = blockIdx.x;
    const int t = threadIdx.x;
    if (blk == 0) {
#pragma unroll
        for (int q = 0; q < 2; q++) {
            int h = t + q * 256;
            g_splam[h] = log1pf(expf(Lambda[h]));
            g_bil[2*h]     = b_gates[h];
            g_bil[2*h + 1] = b_gates[HID + h];
        }
        return;
    }
    if (blk >= WT_B5) {
        const long i = (long)(blk - WT_B5) * 256 + t;   // float4 index
        float4 v = ((const float4*)x)[i];
        ((__half2*)g_xr)[2*i]   = __floats2half2_rn(v.x, v.y);
        ((__half2*)g_xr)[2*i+1] = __floats2half2_rn(v.z, v.w);
        return;
    }
    const float* W; __half* WT; int K, N, il = 0; long base;
    if (blk < WT_B1)      { W = w_in;    WT = g_wiT; K = DMODEL; N = HID2;   base = (long)(blk - WT_B0) * 256; }
    else if (blk < WT_B2) { W = w_gates; WT = g_wgT; K = HID;    N = HID2;   base = (long)(blk - WT_B1) * 256; il = 1; }
    else if (blk < WT_B3) { W = w_out;   WT = g_woT; K = HID;    N = DMODEL; base = (long)(blk - WT_B2) * 256; }
    else if (blk < WT_B4) { W = ffn_w1;  WT = g_f1T; K = DMODEL; N = INNER;  base = (long)(blk - WT_B3) * 256; }
    else                  { W = ffn_w2;  WT = g_f2T; K = INNER;  N = DMODEL; base = (long)(blk - WT_B4) * 256; }
    const long i = base + t;
    const int k = (int)(i % K);
    const int n = (int)(i / K);
    const int col = il ? ((n >> 1) + (n & 1) * HID) : n;
    WT[i] = __float2half_rn(W[(long)k * N + col]);
}

// ---------------------------------------------------------------------------
// Sliding-window causal depthwise conv (K=4) + bias + silu.
// ---------------------------------------------------------------------------
__global__ __launch_bounds__(256)
void conv_silu_kernel(const float* __restrict__ conv_w,
                      const float* __restrict__ conv_b)
{
    const int h2 = threadIdx.x;              // half2 index: h = 2*h2
    const int b  = blockIdx.y;
    const int t0 = blockIdx.x * CONV_CHUNK;
    const int h  = h2 << 1;

    const float4 wa = *(const float4*)&conv_w[h * 4];
    const float4 wb = *(const float4*)&conv_w[h * 4 + 4];
    const float  ca = conv_b[h], cb = conv_b[h + 1];

    const __half2* xz = (const __half2*)g_xzh;
    const long rs = HID2 / 2;
    long base = ((long)b * SEQ + t0) * rs + h2;

    float a0 = 0.f, a1 = 0.f, a2 = 0.f;
    float b0 = 0.f, b1 = 0.f, b2 = 0.f;
    if (t0 >= 3) {
        __half2 p;
        p = xz[base - 3*rs]; a0 = __low2float(p); b0 = __high2float(p);
        p = xz[base - 2*rs]; a1 = __low2float(p); b1 = __high2float(p);
        p = xz[base - 1*rs]; a2 = __low2float(p); b2 = __high2float(p);
    }

    __half2* xcp = (__half2*)g_xc;
    long ob = ((long)b * SEQ + t0) * (HID / 2) + h2;

#pragma unroll 4
    for (int t = 0; t < CONV_CHUNK; t++) {
        const __half2 cur = xz[base]; base += rs;
        const float xa = __low2float(cur), xb = __high2float(cur);
        float va = ca, vb = cb;
        va = fmaf(wa.x, a0, va); va = fmaf(wa.y, a1, va);
        va = fmaf(wa.z, a2, va); va = fmaf(wa.w, xa, va);
        vb = fmaf(wb.x, b0, vb); vb = fmaf(wb.y, b1, vb);
        vb = fmaf(wb.z, b2, vb); vb = fmaf(wb.w, xb, vb);
        a0 = a1; a1 = a2; a2 = xa;
        b0 = b1; b1 = b2; b2 = xb;
        va = __fdividef(va, 1.f + __expf(-va));
        vb = __fdividef(vb, 1.f + __expf(-vb));
        xcp[ob] = __floats2half2_rn(va, vb);
        ob += HID / 2;
    }
}

// ---------------------------------------------------------------------------
// scanC: 2 channels per thread (256 threads). Carry recomputed in-block
// (same FMA sequence as the old scanB), then CLEN serial steps.
// ---------------------------------------------------------------------------
__global__ __launch_bounds__(256)
void scanC_kernel()
{
    const int tid = threadIdx.x;
    const int c = blockIdx.x % NC;
    const int b = blockIdx.x / NC;
    const int h = tid << 1;

    float hx = 0.f, hy = 0.f;
    for (int j = 0; j < c; j++) {
        const int i = (b*NC + j)*HID + h;
        const float2 a  = *(const float2*)&g_cA[i];
        const float2 bb = *(const float2*)&g_cB[i];
        hx = fmaf(a.x, hx, bb.x);
        hy = fmaf(a.y, hy, bb.y);
    }

    long base  = ((long)b*SEQ + c*CLEN)*HID  + h;     // g_ab / g_y index
    long zbase = ((long)b*SEQ + c*CLEN)*HID2 + HID + h;
    for (int t = 0; t < CLEN; t++) {
        const uint2 pk2 = *(const uint2*)&g_ab[base];
        const __half2 p0 = *(const __half2*)&pk2.x;   // (om, bp) ch h
        const __half2 p1 = *(const __half2*)&pk2.y;   // (om, bp) ch h+1
        const float om0 = __low2float(p0), bp0 = __high2float(p0);
        const float om1 = __low2float(p1), bp1 = __high2float(p1);
        hx = fmaf(-om0, hx, hx) + bp0;
        hy = fmaf(-om1, hy, hy) + bp1;
        const __half2 zz = *(const __half2*)&g_xzh[zbase];
        const float z0 = __low2float(zz), z1 = __high2float(zz);
        const float s0 = __fdividef(z0, 1.f + __expf(-z0));
        const float s1 = __fdividef(z1, 1.f + __expf(-z1));
        *(__half2*)&g_y[base] = __floats2half2_rn(s0 * hx, s1 * hy);
        base  += HID;
        zbase += HID2;
    }
}

// ---------------------------------------------------------------------------
// Launch
// ---------------------------------------------------------------------------
extern "C" void kernel_launch(void* const* d_in, const int* in_sizes, int n_in,
                              void* d_out, int out_size)
{
    const float* x      = (const float*)d_in[0];
    const float* w_in   = (const float*)d_in[1];
    const float* conv_w = (const float*)d_in[2];
    const float* conv_b = (const float*)d_in[3];
    const float* w_gates= (const float*)d_in[4];
    const float* b_gates= (const float*)d_in[5];
    const float* Lambda = (const float*)d_in[6];
    const float* w_out  = (const float*)d_in[7];
    const float* ln1_g  = (const float*)d_in[8];
    const float* ln1_b  = (const float*)d_in[9];
    const float* ffn_w1 = (const float*)d_in[10];
    const float* ffn_b1 = (const float*)d_in[11];
    const float* ffn_w2 = (const float*)d_in[12];
    const float* ffn_b2 = (const float*)d_in[13];
    const float* ln2_g  = (const float*)d_in[14];
    const float* ln2_b  = (const float*)d_in[15];

    static cudaStream_t s2 = nullptr;
    static cudaEvent_t  evFork = nullptr, evJoin = nullptr;
    static bool init_done = false;
    if (!init_done) {
        cudaFuncSetAttribute(mma_gemm,    cudaFuncAttributeMaxDynamicSharedMemorySize, GEMM_SMEM);
        cudaFuncSetAttribute(mma_gemm_ln, cudaFuncAttributeMaxDynamicSharedMemorySize, LN_SMEM);
        cudaStreamCreateWithFlags(&s2, cudaStreamNonBlocking);
        cudaEventCreateWithFlags(&evFork, cudaEventDisableTiming);
        cudaEventCreateWithFlags(&evJoin, cudaEventDisableTiming);
        init_done = true;
    }

    float *hs;
    __half *xzh, *xr, *xc, *y, *hsh, *ff1, *wiT, *wgT, *woT, *f1T, *f2T;
    cudaGetSymbolAddress((void**)&hs,  g_hs);
    cudaGetSymbolAddress((void**)&xzh, g_xzh);
    cudaGetSymbolAddress((void**)&xr,  g_xr);
    cudaGetSymbolAddress((void**)&xc,  g_xc);
    cudaGetSymbolAddress((void**)&y,   g_y);
    cudaGetSymbolAddress((void**)&hsh, g_hsh);
    cudaGetSymbolAddress((void**)&ff1, g_ff1);
    cudaGetSymbolAddress((void**)&wiT, g_wiT);
    cudaGetSymbolAddress((void**)&wgT, g_wgT);
    cudaGetSymbolAddress((void**)&woT, g_woT);
    cudaGetSymbolAddress((void**)&f1T, g_f1T);
    cudaGetSymbolAddress((void**)&f2T, g_f2T);

    // 0. prep: splam/bias, weight transposes, x->fp16 (one launch)
    prep_kernel<<<WT_B6, 256>>>(Lambda, b_gates, w_in, w_gates, w_out,
                                ffn_w1, ffn_w2, x);

    // fork: z-half of gemm1 runs on side stream, overlapping conv + gates
    cudaEventRecord(evFork, 0);
    cudaStreamWaitEvent(s2, evFork, 0);
    // 1b. xz cols 512..1023 (z) on side stream
    mma_gemm<<<dim3(4, NTOK/128), 256, GEMM_SMEM, s2>>>(
        xr, wiT, NTOK, HID2, DMODEL, 512, nullptr, 0, nullptr, xzh);
    cudaEventRecord(evJoin, s2);

    // 1a. xz cols 0..511 (xh) on main stream
    mma_gemm<<<dim3(4, NTOK/128), 256, GEMM_SMEM>>>(
        xr, wiT, NTOK, HID2, DMODEL, 0, nullptr, 0, nullptr, xzh);
    // 2. sliding-window conv + silu -> xc (fp16)   [needs only xh]
    conv_silu_kernel<<<dim3(SEQ/CONV_CHUNK, BATCH), 256>>>(conv_w, conv_b);
    // 3. gates GEMM + fused (1-alpha, beta') + 2x chunk scanA per tile
    mma_gemm<<<dim3(HID2/128, NTOK/128), 256, GEMM_SMEM>>>(
        xc, wgT, NTOK, HID2, HID, 0, nullptr, 2, nullptr, nullptr);

    // join: scanC needs z (side stream) and g_ab (main stream)
    cudaStreamWaitEvent(0, evJoin, 0);
    // 4. scan (carry recomputed in-block) + y = silu(z)*h (fp16)
    scanC_kernel<<<BATCH*NC, 256>>>();
    // 5. hs = LN(y @ w_out + x)  (fp32 + fp16 copy)
    mma_gemm_ln<<<dim3(1, NTOK/128), 512, LN_SMEM>>>(
        y, woT, HID, nullptr, x, ln1_g, ln1_b, hs, hsh);
    // 6. ff1 = silu(hs @ ffn_w1 + b1)  (fp16)
    mma_gemm<<<dim3(INNER/128, NTOK/128), 256, GEMM_SMEM>>>(
        hsh, f1T, NTOK, INNER, DMODEL, 0, ffn_b1, 1, nullptr, ff1);
    // 7. out = LN(ff1 @ ffn_w2 + b2 + hs)
    mma_gemm_ln<<<dim3(1, NTOK/128), 512, LN_SMEM>>>(
        ff1, f2T, INNER, ffn_b2, hs, ln2_g, ln2_b, (float*)d_out, nullptr);
}

// round 12
// speedup vs baseline: 4.7528x; 1.0157x over previous
#include <cuda_runtime.h>
#include <cuda_fp16.h>
#include <math.h>
#include <stdint.h>

#define BATCH  32
#define SEQ    2048
#define DMODEL 256
#define HID    512
#define HID2   1024
#define INNER  1024
#define NTOK   (BATCH*SEQ)   // 65536
#define NC     32
#define CLEN   (SEQ/NC)      // 64
#define CONV_CHUNK 32
#define HBATCH (BATCH/2)
#define HROWS  (NTOK/2)      // 32768

// ---------------------------------------------------------------------------
// Scratch
// ---------------------------------------------------------------------------
__device__ float g_hs   [(size_t)NTOK*DMODEL]; // fp32 residual for LN2
__device__ float g_cA   [BATCH*NC*HID];
__device__ float g_cB   [BATCH*NC*HID];
__device__ float g_splam[HID];
__device__ float g_bil  [HID2];
// packed per-step scan coefficients: (1-alpha, beta') per (token, channel)
__device__ __align__(256) __half2 g_ab[(size_t)NTOK*HID];   // 134 MB
// fp16 buffers
__device__ __align__(256) __half g_xzh[(size_t)NTOK*HID2];  // [xh | z]
__device__ __align__(256) __half g_xr [(size_t)NTOK*DMODEL];
__device__ __align__(256) __half g_xc [(size_t)NTOK*HID];
__device__ __align__(256) __half g_y  [(size_t)NTOK*HID];
__device__ __align__(256) __half g_hsh[(size_t)NTOK*DMODEL];
__device__ __align__(256) __half g_ff1[(size_t)NTOK*INNER];
// transposed fp16 weights [N,K]
__device__ __align__(256) __half g_wiT[HID2*DMODEL];
__device__ __align__(256) __half g_wgT[HID2*HID];   // interleaved rec/inp cols
__device__ __align__(256) __half g_woT[DMODEL*HID];
__device__ __align__(256) __half g_f1T[INNER*DMODEL];
__device__ __align__(256) __half g_f2T[DMODEL*INNER];

// ---------------------------------------------------------------------------
// helpers
// ---------------------------------------------------------------------------
__device__ __forceinline__ uint32_t smem_u32(const void* p){
    uint32_t a;
    asm("{ .reg .u64 t; cvta.to.shared.u64 t, %1; cvt.u32.u64 %0, t; }"
        : "=r"(a) : "l"(p));
    return a;
}
__device__ __forceinline__ void cp_async16(uint32_t dst, const void* src){
    asm volatile("cp.async.cg.shared.global [%0], [%1], 16;" :: "r"(dst), "l"(src));
}
__device__ __forceinline__ void cp_commit(){ asm volatile("cp.async.commit_group;"); }

#define LDSM4(R, A) \
    asm volatile("ldmatrix.sync.aligned.m8n8.x4.shared.b16 {%0,%1,%2,%3}, [%4];" \
        : "=r"((R)[0]),"=r"((R)[1]),"=r"((R)[2]),"=r"((R)[3]) : "r"(A))

#define MMA_F16(C, A, B0, B1) \
    asm volatile("mma.sync.aligned.m16n8k16.row.col.f32.f16.f16.f32 " \
        "{%0,%1,%2,%3},{%4,%5,%6,%7},{%8,%9},{%0,%1,%2,%3};" \
        : "+f"((C)[0]),"+f"((C)[1]),"+f"((C)[2]),"+f"((C)[3]) \
        : "r"((A)[0]),"r"((A)[1]),"r"((A)[2]),"r"((A)[3]),"r"(B0),"r"(B1))

// ---------------------------------------------------------------------------
// fp16 GEMM (128x128 tile, 256 thr, BK=32, PROW=80)
// mode: 0 = plain, 1 = silu, 2 = fused gates epilogue (+2 chunk scanA's)
// col0: column offset of this launch's first tile (for split-N launches)
// output: Ch (fp16) if non-null, else Cf (fp32)
// ---------------------------------------------------------------------------
#define BK    32
#define PROW  80
#define SZ_T  (128*PROW)           // 10240
#define OFF_B SZ_T
#define STAGE (2*SZ_T)             // 20480
// pipeline 2*STAGE = 40960 ; mode-2 overlay = 128*64*4 + 2048 = 34816 -> fits
#define GEMM_SMEM (2*STAGE)

__global__ __launch_bounds__(256)
void mma_gemm(const __half* __restrict__ A, const __half* __restrict__ Bt,
              int M, int N, int K, int col0,
              const float* __restrict__ bias, int mode,
              float* __restrict__ Cf, __half* __restrict__ Ch)
{
    extern __shared__ __align__(128) char smem[];
    const uint32_t sb = smem_u32(smem);
    const int tid = threadIdx.x;
    const int wid = tid >> 5, lane = tid & 31;
    const long brow = (long)blockIdx.y * 128;
    const long bcol = (long)col0 + (long)blockIdx.x * 128;

    const int rowBase = (wid >> 2) * 64;
    const int colBase = (wid & 3) * 32;

    float acc[4][4][4];
#pragma unroll
    for (int a = 0; a < 4; a++)
#pragma unroll
        for (int b = 0; b < 4; b++)
#pragma unroll
            for (int c = 0; c < 4; c++) acc[a][b][c] = 0.f;

    const int nch = K / BK;

    auto load_stage = [&](int s, int cidx){
        const uint32_t base = sb + s * STAGE;
        const long kc = (long)cidx * BK;
#pragma unroll
        for (int i = tid; i < 512; i += 256) {
            const int row = i >> 2, ch = i & 3;
            const uint32_t d = row * PROW + ch * 16;
            cp_async16(base + d,         A  + (brow + row) * (long)K + kc + ch * 8);
            cp_async16(base + OFF_B + d, Bt + (bcol + row) * (long)K + kc + ch * 8);
        }
        cp_commit();
    };

    load_stage(0, 0);

    const int g = lane >> 3, r = lane & 7;

    for (int c = 0; c < nch; c++) {
        if (c + 1 < nch) { load_stage((c + 1) & 1, c + 1);
                           asm volatile("cp.async.wait_group 1;" ::: "memory"); }
        else             { asm volatile("cp.async.wait_group 0;" ::: "memory"); }
        __syncthreads();

        const uint32_t st = sb + (c & 1) * STAGE;
#pragma unroll
        for (int ks = 0; ks < 2; ks++) {
            const int k0 = ks * 16;
            uint32_t bf[2][4];
#pragma unroll
            for (int p = 0; p < 2; p++) {
                const uint32_t boff =
                    (uint32_t)(colBase + p*16 + ((g >> 1) << 3) + r) * PROW
                    + (uint32_t)(k0 + ((g & 1) << 3)) * 2;
                LDSM4(bf[p], st + OFF_B + boff);
            }
#pragma unroll
            for (int mi = 0; mi < 4; mi++) {
                const uint32_t aoff =
                    (uint32_t)(rowBase + mi*16 + r + ((g & 1) << 3)) * PROW
                    + (uint32_t)(k0 + ((g >> 1) << 3)) * 2;
                uint32_t af[4];
                LDSM4(af, st + aoff);
#pragma unroll
                for (int ni = 0; ni < 4; ni++) {
                    const int p = ni >> 1, q = (ni & 1) * 2;
                    MMA_F16(acc[mi][ni], af, bf[p][q], bf[p][q+1]);
                }
            }
        }
        __syncthreads();
    }

    const int gID = lane >> 2, tig = lane & 3;

    if (mode == 2) {
        // fused gates epilogue; tile rows = 2 scan chunks of CLEN=64
        // overlay: sAB [128][64] half2 = 32768 B ; segb [64][4][2] = 2048 B
        __half2* sAB  = (__half2*)smem;
        float*   segb = (float*)(smem + 128*64*4);
#pragma unroll
        for (int mi = 0; mi < 4; mi++) {
#pragma unroll
            for (int ni = 0; ni < 4; ni++) {
                const long col = bcol + colBase + ni*8 + tig*2;
                const int hloc = (colBase >> 1) + ni*4 + tig;
                const int h    = (int)(col >> 1);
#pragma unroll
                for (int half = 0; half < 2; half++) {
                    const int  rloc = rowBase + mi*16 + gID + half*8;
                    const long row  = brow + rloc;
                    const float rec = acc[mi][ni][half*2]   + g_bil[col];
                    const float inp = acc[mi][ni][half*2+1] + g_bil[col + 1];
                    const float sp = g_splam[h];
                    const float sr = __fdividef(1.f, 1.f + __expf(-rec));
                    const float om = -expm1f(-sp * sr);          // 1 - alpha
                    const float a  = 1.f - om;
                    const float si = __fdividef(1.f, 1.f + __expf(-inp));
                    const float xc = __half2float(g_xc[row * HID + h]);
                    const float bp = sqrtf(1.f - a*a + 1e-8f) * si * xc;
                    const __half2 pk = __floats2half2_rn(om, bp);
                    g_ab[row * HID + h] = pk;
                    sAB[rloc * 64 + hloc] = pk;
                }
            }
        }
        __syncthreads();
        // per-chunk (64-row) segmented scan: 4 segments x 16 steps
        const int ch  = tid & 63;
        const int seg = tid >> 6;                 // 0..3
        const int b   = (int)(brow >> 11);        // /SEQ
        const int cc0 = (int)((brow >> 6) & (NC - 1));
#pragma unroll
        for (int sub = 0; sub < 2; sub++) {
            float Aprod = 1.f, Bacc = 0.f;
            int rr = sub * 64 + seg * 16;
#pragma unroll 8
            for (int t = 0; t < 16; t++, rr++) {
                const __half2 pk = sAB[rr * 64 + ch];
                const float a = 1.f - __low2float(pk);
                const float p = __high2float(pk);
                Bacc = fmaf(a, Bacc, p);
                Aprod *= a;
            }
            segb[(ch * 4 + seg) * 2]     = Aprod;
            segb[(ch * 4 + seg) * 2 + 1] = Bacc;
            __syncthreads();
            if (tid < 64) {
                float At = 1.f, Bv = 0.f;
#pragma unroll
                for (int s2 = 0; s2 < 4; s2++) {
                    const float a = segb[(tid * 4 + s2) * 2];
                    const float p = segb[(tid * 4 + s2) * 2 + 1];
                    Bv = fmaf(a, Bv, p);
                    At *= a;
                }
                const int h = (int)(bcol >> 1) + tid;
                g_cA[(b*NC + cc0 + sub)*HID + h] = At;
                g_cB[(b*NC + cc0 + sub)*HID + h] = Bv;
            }
            __syncthreads();
        }
        return;
    }

#pragma unroll
    for (int mi = 0; mi < 4; mi++) {
#pragma unroll
        for (int ni = 0; ni < 4; ni++) {
            const long col = bcol + colBase + ni*8 + tig*2;
            float b0 = 0.f, b1 = 0.f;
            if (bias) { b0 = __ldg(&bias[col]); b1 = __ldg(&bias[col+1]); }
#pragma unroll
            for (int half = 0; half < 2; half++) {
                const long row = brow + rowBase + mi*16 + gID + half*8;
                float v0 = acc[mi][ni][half*2]   + b0;
                float v1 = acc[mi][ni][half*2+1] + b1;
                if (mode == 1) {
                    v0 = __fdividef(v0, 1.f + __expf(-v0));
                    v1 = __fdividef(v1, 1.f + __expf(-v1));
                }
                if (Ch) *(__half2*)&Ch[row * N + col] = __floats2half2_rn(v0, v1);
                else    *(float2*)&Cf[row * N + col] = make_float2(v0, v1);
            }
        }
    }
}

// ---------------------------------------------------------------------------
// fp16 GEMM + fused residual/LayerNorm. tile 128x256, 512 thr (2x8 warps).
// ---------------------------------------------------------------------------
#define TILE_A2 (128*PROW)           // 10240
#define TILE_B2 (256*PROW)           // 20480
#define OFF_B2  TILE_A2
#define STAGE2  (TILE_A2 + TILE_B2)  // 30720
#define LN_SMEM (2*STAGE2 + 2*128*4) // 62464

__global__ __launch_bounds__(512)
void mma_gemm_ln(const __half* __restrict__ A, const __half* __restrict__ Bt,
                 int K,
                 const float* __restrict__ bias,
                 const float* __restrict__ R,
                 const float* __restrict__ gamma, const float* __restrict__ beta,
                 float* __restrict__ Cf, __half* __restrict__ Ch)
{
    extern __shared__ __align__(128) char smem[];
    const uint32_t sb = smem_u32(smem);
    float* srow  = (float*)(smem + 2*STAGE2);
    float* srow2 = srow + 128;
    const int tid = threadIdx.x;
    const int wid = tid >> 5, lane = tid & 31;
    const long brow = (long)blockIdx.y * 128;

    const int rowBase = (wid >> 3) * 64;
    const int colBase = (wid & 7) * 32;

    float acc[4][4][4];
#pragma unroll
    for (int a = 0; a < 4; a++)
#pragma unroll
        for (int b = 0; b < 4; b++)
#pragma unroll
            for (int c = 0; c < 4; c++) acc[a][b][c] = 0.f;

    const int nch = K / BK;

    auto load_stage = [&](int s, int cidx){
        const uint32_t base = sb + s * STAGE2;
        const long kc = (long)cidx * BK;
#pragma unroll
        for (int i = tid; i < 1536; i += 512) {
            const int row = i >> 2, ch = i & 3;
            if (row < 128) {
                cp_async16(base + row * PROW + ch * 16,
                           A + (brow + row) * (long)K + kc + ch * 8);
            } else {
                const int br = row - 128;
                cp_async16(base + OFF_B2 + br * PROW + ch * 16,
                           Bt + br * (long)K + kc + ch * 8);
            }
        }
        cp_commit();
    };

    load_stage(0, 0);

    const int g = lane >> 3, r = lane & 7;

    for (int c = 0; c < nch; c++) {
        if (c + 1 < nch) { load_stage((c + 1) & 1, c + 1);
                           asm volatile("cp.async.wait_group 1;" ::: "memory"); }
        else             { asm volatile("cp.async.wait_group 0;" ::: "memory"); }
        __syncthreads();

        const uint32_t st = sb + (c & 1) * STAGE2;
#pragma unroll
        for (int ks = 0; ks < 2; ks++) {
            const int k0 = ks * 16;
            uint32_t bf[2][4];
#pragma unroll
            for (int p = 0; p < 2; p++) {
                const uint32_t boff =
                    (uint32_t)(colBase + p*16 + ((g >> 1) << 3) + r) * PROW
                    + (uint32_t)(k0 + ((g & 1) << 3)) * 2;
                LDSM4(bf[p], st + OFF_B2 + boff);
            }
#pragma unroll
            for (int mi = 0; mi < 4; mi++) {
                const uint32_t aoff =
                    (uint32_t)(rowBase + mi*16 + r + ((g & 1) << 3)) * PROW
                    + (uint32_t)(k0 + ((g >> 1) << 3)) * 2;
                uint32_t af[4];
                LDSM4(af, st + aoff);
#pragma unroll
                for (int ni = 0; ni < 4; ni++) {
                    const int p = ni >> 1, q = (ni & 1) * 2;
                    MMA_F16(acc[mi][ni], af, bf[p][q], bf[p][q+1]);
                }
            }
        }
        __syncthreads();
    }

    if (tid < 128) { srow[tid] = 0.f; srow2[tid] = 0.f; }
    __syncthreads();

    const int gID = lane >> 2, tig = lane & 3;

#pragma unroll
    for (int mi = 0; mi < 4; mi++) {
#pragma unroll
        for (int half = 0; half < 2; half++) {
            const int  rloc = rowBase + mi*16 + gID + half*8;
            const long row  = brow + rloc;
            float s = 0.f, s2 = 0.f;
#pragma unroll
            for (int ni = 0; ni < 4; ni++) {
                const int col = colBase + ni*8 + tig*2;
                float2 rv = *(const float2*)&R[row * DMODEL + col];
                float v0 = acc[mi][ni][half*2]   + rv.x;
                float v1 = acc[mi][ni][half*2+1] + rv.y;
                if (bias) { v0 += __ldg(&bias[col]); v1 += __ldg(&bias[col+1]); }
                acc[mi][ni][half*2]   = v0;
                acc[mi][ni][half*2+1] = v1;
                s  += v0 + v1;
                s2 += v0*v0 + v1*v1;
            }
            atomicAdd(&srow[rloc],  s);
            atomicAdd(&srow2[rloc], s2);
        }
    }
    __syncthreads();

#pragma unroll
    for (int mi = 0; mi < 4; mi++) {
#pragma unroll
        for (int half = 0; half < 2; half++) {
            const int  rloc = rowBase + mi*16 + gID + half*8;
            const long row  = brow + rloc;
            const float mean = srow[rloc] * (1.f / DMODEL);
            float var = srow2[rloc] * (1.f / DMODEL) - mean * mean;
            const float rs = rsqrtf(var + 1e-12f);
#pragma unroll
            for (int ni = 0; ni < 4; ni++) {
                const int col = colBase + ni*8 + tig*2;
                float2 gv = *(const float2*)&gamma[col];
                float2 bv = *(const float2*)&beta[col];
                float v0 = (acc[mi][ni][half*2]   - mean) * rs * gv.x + bv.x;
                float v1 = (acc[mi][ni][half*2+1] - mean) * rs * gv.y + bv.y;
                *(float2*)&Cf[row * DMODEL + col] = make_float2(v0, v1);
                if (Ch) *(__half2*)&Ch[row * DMODEL + col] = __floats2half2_rn(v0, v1);
            }
        }
    }
}

// ---------------------------------------------------------------------------
// Prep: splam/bias + all weight transposes + x->fp16 in ONE launch
// ---------------------------------------------------------------------------
#define WT_B0 1
#define WT_B1 (WT_B0 + (DMODEL*HID2)/256)
#define WT_B2 (WT_B1 + (HID*HID2)/256)
#define WT_B3 (WT_B2 + (HID*DMODEL)/256)
#define WT_B4 (WT_B3 + (DMODEL*INNER)/256)
#define WT_B5 (WT_B4 + (INNER*DMODEL)/256)
#define XH_BLKS ((NTOK*DMODEL/4)/256)     // 16384 blocks, float4 granularity
#define WT_B6 (WT_B5 + XH_BLKS)

__global__ __launch_bounds__(256)
void prep_kernel(const float* __restrict__ Lambda, const float* __restrict__ b_gates,
                 const float* __restrict__ w_in, const float* __restrict__ w_gates,
                 const float* __restrict__ w_out, const float* __restrict__ ffn_w1,
                 const float* __restrict__ ffn_w2, const float* __restrict__ x)
{
    const int blk = blockIdx.x;
    const int t = threadIdx.x;
    if (blk == 0) {
#pragma unroll
        for (int q = 0; q < 2; q++) {
            int h = t + q * 256;
            g_splam[h] = log1pf(expf(Lambda[h]));
            g_bil[2*h]     = b_gates[h];
            g_bil[2*h + 1] = b_gates[HID + h];
        }
        return;
    }
    if (blk >= WT_B5) {
        const long i = (long)(blk - WT_B5) * 256 + t;   // float4 index
        float4 v = ((const float4*)x)[i];
        ((__half2*)g_xr)[2*i]   = __floats2half2_rn(v.x, v.y);
        ((__half2*)g_xr)[2*i+1] = __floats2half2_rn(v.z, v.w);
        return;
    }
    const float* W; __half* WT; int K, N, il = 0; long base;
    if (blk < WT_B1)      { W = w_in;    WT = g_wiT; K = DMODEL; N = HID2;   base = (long)(blk - WT_B0) * 256; }
    else if (blk < WT_B2) { W = w_gates; WT = g_wgT; K = HID;    N = HID2;   base = (long)(blk - WT_B1) * 256; il = 1; }
    else if (blk < WT_B3) { W = w_out;   WT = g_woT; K = HID;    N = DMODEL; base = (long)(blk - WT_B2) * 256; }
    else if (blk < WT_B4) { W = ffn_w1;  WT = g_f1T; K = DMODEL; N = INNER;  base = (long)(blk - WT_B3) * 256; }
    else                  { W = ffn_w2;  WT = g_f2T; K = INNER;  N = DMODEL; base = (long)(blk - WT_B4) * 256; }
    const long i = base + t;
    const int k = (int)(i % K);
    const int n = (int)(i / K);
    const int col = il ? ((n >> 1) + (n & 1) * HID) : n;
    WT[i] = __float2half_rn(W[(long)k * N + col]);
}

// ---------------------------------------------------------------------------
// Sliding-window causal depthwise conv (K=4) + bias + silu.
// ---------------------------------------------------------------------------
__global__ __launch_bounds__(256)
void conv_silu_kernel(const float* __restrict__ conv_w,
                      const float* __restrict__ conv_b)
{
    const int h2 = threadIdx.x;              // half2 index: h = 2*h2
    const int b  = blockIdx.y;
    const int t0 = blockIdx.x * CONV_CHUNK;
    const int h  = h2 << 1;

    const float4 wa = *(const float4*)&conv_w[h * 4];
    const float4 wb = *(const float4*)&conv_w[h * 4 + 4];
    const float  ca = conv_b[h], cb = conv_b[h + 1];

    const __half2* xz = (const __half2*)g_xzh;
    const long rs = HID2 / 2;
    long base = ((long)b * SEQ + t0) * rs + h2;

    float a0 = 0.f, a1 = 0.f, a2 = 0.f;
    float b0 = 0.f, b1 = 0.f, b2 = 0.f;
    if (t0 >= 3) {
        __half2 p;
        p = xz[base - 3*rs]; a0 = __low2float(p); b0 = __high2float(p);
        p = xz[base - 2*rs]; a1 = __low2float(p); b1 = __high2float(p);
        p = xz[base - 1*rs]; a2 = __low2float(p); b2 = __high2float(p);
    }

    __half2* xcp = (__half2*)g_xc;
    long ob = ((long)b * SEQ + t0) * (HID / 2) + h2;

#pragma unroll 4
    for (int t = 0; t < CONV_CHUNK; t++) {
        const __half2 cur = xz[base]; base += rs;
        const float xa = __low2float(cur), xb = __high2float(cur);
        float va = ca, vb = cb;
        va = fmaf(wa.x, a0, va); va = fmaf(wa.y, a1, va);
        va = fmaf(wa.z, a2, va); va = fmaf(wa.w, xa, va);
        vb = fmaf(wb.x, b0, vb); vb = fmaf(wb.y, b1, vb);
        vb = fmaf(wb.z, b2, vb); vb = fmaf(wb.w, xb, vb);
        a0 = a1; a1 = a2; a2 = xa;
        b0 = b1; b1 = b2; b2 = xb;
        va = __fdividef(va, 1.f + __expf(-va));
        vb = __fdividef(vb, 1.f + __expf(-vb));
        xcp[ob] = __floats2half2_rn(va, vb);
        ob += HID / 2;
    }
}

// ---------------------------------------------------------------------------
// scanC: 2 channels per thread (256 threads). Carry recomputed in-block,
// then CLEN serial steps. b0 = batch offset for split launches.
// ---------------------------------------------------------------------------
__global__ __launch_bounds__(256)
void scanC_kernel(int b0)
{
    const int tid = threadIdx.x;
    const int c = blockIdx.x % NC;
    const int b = b0 + blockIdx.x / NC;
    const int h = tid << 1;

    float hx = 0.f, hy = 0.f;
    for (int j = 0; j < c; j++) {
        const int i = (b*NC + j)*HID + h;
        const float2 a  = *(const float2*)&g_cA[i];
        const float2 bb = *(const float2*)&g_cB[i];
        hx = fmaf(a.x, hx, bb.x);
        hy = fmaf(a.y, hy, bb.y);
    }

    long base  = ((long)b*SEQ + c*CLEN)*HID  + h;     // g_ab / g_y index
    long zbase = ((long)b*SEQ + c*CLEN)*HID2 + HID + h;
    for (int t = 0; t < CLEN; t++) {
        const uint2 pk2 = *(const uint2*)&g_ab[base];
        const __half2 p0 = *(const __half2*)&pk2.x;   // (om, bp) ch h
        const __half2 p1 = *(const __half2*)&pk2.y;   // (om, bp) ch h+1
        const float om0 = __low2float(p0), bp0 = __high2float(p0);
        const float om1 = __low2float(p1), bp1 = __high2float(p1);
        hx = fmaf(-om0, hx, hx) + bp0;
        hy = fmaf(-om1, hy, hy) + bp1;
        const __half2 zz = *(const __half2*)&g_xzh[zbase];
        const float z0 = __low2float(zz), z1 = __high2float(zz);
        const float s0 = __fdividef(z0, 1.f + __expf(-z0));
        const float s1 = __fdividef(z1, 1.f + __expf(-z1));
        *(__half2*)&g_y[base] = __floats2half2_rn(s0 * hx, s1 * hy);
        base  += HID;
        zbase += HID2;
    }
}

// ---------------------------------------------------------------------------
// Launch
// ---------------------------------------------------------------------------
extern "C" void kernel_launch(void* const* d_in, const int* in_sizes, int n_in,
                              void* d_out, int out_size)
{
    const float* x      = (const float*)d_in[0];
    const float* w_in   = (const float*)d_in[1];
    const float* conv_w = (const float*)d_in[2];
    const float* conv_b = (const float*)d_in[3];
    const float* w_gates= (const float*)d_in[4];
    const float* b_gates= (const float*)d_in[5];
    const float* Lambda = (const float*)d_in[6];
    const float* w_out  = (const float*)d_in[7];
    const float* ln1_g  = (const float*)d_in[8];
    const float* ln1_b  = (const float*)d_in[9];
    const float* ffn_w1 = (const float*)d_in[10];
    const float* ffn_b1 = (const float*)d_in[11];
    const float* ffn_w2 = (const float*)d_in[12];
    const float* ffn_b2 = (const float*)d_in[13];
    const float* ln2_g  = (const float*)d_in[14];
    const float* ln2_b  = (const float*)d_in[15];
    float* dout = (float*)d_out;

    static cudaStream_t s2 = nullptr;
    static cudaEvent_t evFork = nullptr, evJoin = nullptr, evA = nullptr, evB = nullptr;
    static bool init_done = false;
    if (!init_done) {
        cudaFuncSetAttribute(mma_gemm,    cudaFuncAttributeMaxDynamicSharedMemorySize, GEMM_SMEM);
        cudaFuncSetAttribute(mma_gemm_ln, cudaFuncAttributeMaxDynamicSharedMemorySize, LN_SMEM);
        cudaStreamCreateWithFlags(&s2, cudaStreamNonBlocking);
        cudaEventCreateWithFlags(&evFork, cudaEventDisableTiming);
        cudaEventCreateWithFlags(&evJoin, cudaEventDisableTiming);
        cudaEventCreateWithFlags(&evA,    cudaEventDisableTiming);
        cudaEventCreateWithFlags(&evB,    cudaEventDisableTiming);
        init_done = true;
    }

    float *hs;
    __half *xzh, *xr, *xc, *y, *hsh, *ff1, *wiT, *wgT, *woT, *f1T, *f2T;
    cudaGetSymbolAddress((void**)&hs,  g_hs);
    cudaGetSymbolAddress((void**)&xzh, g_xzh);
    cudaGetSymbolAddress((void**)&xr,  g_xr);
    cudaGetSymbolAddress((void**)&xc,  g_xc);
    cudaGetSymbolAddress((void**)&y,   g_y);
    cudaGetSymbolAddress((void**)&hsh, g_hsh);
    cudaGetSymbolAddress((void**)&ff1, g_ff1);
    cudaGetSymbolAddress((void**)&wiT, g_wiT);
    cudaGetSymbolAddress((void**)&wgT, g_wgT);
    cudaGetSymbolAddress((void**)&woT, g_woT);
    cudaGetSymbolAddress((void**)&f1T, g_f1T);
    cudaGetSymbolAddress((void**)&f2T, g_f2T);

    // 0. prep: splam/bias, weight transposes, x->fp16 (one launch)
    prep_kernel<<<WT_B6, 256>>>(Lambda, b_gates, w_in, w_gates, w_out,
                                ffn_w1, ffn_w2, x);

    // fork: z-half of gemm1 on side stream, overlapping conv + gates
    cudaEventRecord(evFork, 0);
    cudaStreamWaitEvent(s2, evFork, 0);
    mma_gemm<<<dim3(4, NTOK/128), 256, GEMM_SMEM, s2>>>(
        xr, wiT, NTOK, HID2, DMODEL, 512, nullptr, 0, nullptr, xzh);   // z cols
    cudaEventRecord(evJoin, s2);

    // main: xh cols, conv, gates GEMM (+fused alpha/beta + chunk scans)
    mma_gemm<<<dim3(4, NTOK/128), 256, GEMM_SMEM>>>(
        xr, wiT, NTOK, HID2, DMODEL, 0, nullptr, 0, nullptr, xzh);
    conv_silu_kernel<<<dim3(SEQ/CONV_CHUNK, BATCH), 256>>>(conv_w, conv_b);
    mma_gemm<<<dim3(HID2/128, NTOK/128), 256, GEMM_SMEM>>>(
        xc, wgT, NTOK, HID2, HID, 0, nullptr, 2, nullptr, nullptr);

    // join z, then split the tail into two half-batch pipelines
    cudaStreamWaitEvent(0, evJoin, 0);

    // ---- half A (batches 0..15, rows 0..HROWS) on main stream ----
    scanC_kernel<<<HBATCH*NC, 256>>>(0);
    cudaEventRecord(evA, 0);
    mma_gemm_ln<<<dim3(1, HROWS/128), 512, LN_SMEM>>>(
        y, woT, HID, nullptr, x, ln1_g, ln1_b, hs, hsh);
    mma_gemm<<<dim3(INNER/128, HROWS/128), 256, GEMM_SMEM>>>(
        hsh, f1T, HROWS, INNER, DMODEL, 0, ffn_b1, 1, nullptr, ff1);
    mma_gemm_ln<<<dim3(1, HROWS/128), 512, LN_SMEM>>>(
        ff1, f2T, INNER, ffn_b2, hs, ln2_g, ln2_b, dout, nullptr);

    // ---- half B (batches 16..31) on side stream, staggered after scanC_A ----
    cudaStreamWaitEvent(s2, evA, 0);
    scanC_kernel<<<HBATCH*NC, 256, 0, s2>>>(HBATCH);
    mma_gemm_ln<<<dim3(1, HROWS/128), 512, LN_SMEM, s2>>>(
        y + (size_t)HROWS*HID, woT, HID, nullptr, x + (size_t)HROWS*DMODEL,
        ln1_g, ln1_b, hs + (size_t)HROWS*DMODEL, hsh + (size_t)HROWS*DMODEL);
    mma_gemm<<<dim3(INNER/128, HROWS/128), 256, GEMM_SMEM, s2>>>(
        hsh + (size_t)HROWS*DMODEL, f1T, HROWS, INNER, DMODEL, 0, ffn_b1, 1,
        nullptr, ff1 + (size_t)HROWS*INNER);
    mma_gemm_ln<<<dim3(1, HROWS/128), 512, LN_SMEM, s2>>>(
        ff1 + (size_t)HROWS*INNER, f2T, INNER, ffn_b2,
        hs + (size_t)HROWS*DMODEL, ln2_g, ln2_b,
        dout + (size_t)HROWS*DMODEL, nullptr);
    cudaEventRecord(evB, s2);

    // final join
    cudaStreamWaitEvent(0, evB, 0);
}

// round 13
// speedup vs baseline: 4.8037x; 1.0107x over previous
#include <cuda_runtime.h>
#include <cuda_fp16.h>
#include <math.h>
#include <stdint.h>

#define BATCH  32
#define SEQ    2048
#define DMODEL 256
#define HID    512
#define HID2   1024
#define INNER  1024
#define NTOK   (BATCH*SEQ)   // 65536
#define NC     32
#define CLEN   (SEQ/NC)      // 64
#define CONV_CHUNK 32
#define HBATCH (BATCH/2)
#define HROWS  (NTOK/2)      // 32768

// ---------------------------------------------------------------------------
// Scratch
// ---------------------------------------------------------------------------
__device__ float g_hs   [(size_t)NTOK*DMODEL];
__device__ float g_cA   [BATCH*NC*HID];
__device__ float g_cB   [BATCH*NC*HID];
__device__ float g_splam[HID];
__device__ float g_bil  [HID2];
__device__ __align__(256) __half2 g_ab[(size_t)NTOK*HID];
__device__ __align__(256) __half g_xzh[(size_t)NTOK*HID2];  // [xh | z]
__device__ __align__(256) __half g_xr [(size_t)NTOK*DMODEL];
__device__ __align__(256) __half g_xc [(size_t)NTOK*HID];
__device__ __align__(256) __half g_y  [(size_t)NTOK*HID];
__device__ __align__(256) __half g_hsh[(size_t)NTOK*DMODEL];
__device__ __align__(256) __half g_ff1[(size_t)NTOK*INNER];
__device__ __align__(256) __half g_wiT[HID2*DMODEL];
__device__ __align__(256) __half g_wgT[HID2*HID];
__device__ __align__(256) __half g_woT[DMODEL*HID];
__device__ __align__(256) __half g_f1T[INNER*DMODEL];
__device__ __align__(256) __half g_f2T[DMODEL*INNER];

// ---------------------------------------------------------------------------
// helpers
// ---------------------------------------------------------------------------
__device__ __forceinline__ uint32_t smem_u32(const void* p){
    uint32_t a;
    asm("{ .reg .u64 t; cvta.to.shared.u64 t, %1; cvt.u32.u64 %0, t; }"
        : "=r"(a) : "l"(p));
    return a;
}
__device__ __forceinline__ void cp_async16(uint32_t dst, const void* src){
    asm volatile("cp.async.cg.shared.global [%0], [%1], 16;" :: "r"(dst), "l"(src));
}
__device__ __forceinline__ void cp_commit(){ asm volatile("cp.async.commit_group;"); }

#define LDSM4(R, A) \
    asm volatile("ldmatrix.sync.aligned.m8n8.x4.shared.b16 {%0,%1,%2,%3}, [%4];" \
        : "=r"((R)[0]),"=r"((R)[1]),"=r"((R)[2]),"=r"((R)[3]) : "r"(A))

#define MMA_F16(C, A, B0, B1) \
    asm volatile("mma.sync.aligned.m16n8k16.row.col.f32.f16.f16.f32 " \
        "{%0,%1,%2,%3},{%4,%5,%6,%7},{%8,%9},{%0,%1,%2,%3};" \
        : "+f"((C)[0]),"+f"((C)[1]),"+f"((C)[2]),"+f"((C)[3]) \
        : "r"((A)[0]),"r"((A)[1]),"r"((A)[2]),"r"((A)[3]),"r"(B0),"r"(B1))

// ---------------------------------------------------------------------------
// fp16 GEMM (128x128 tile, 256 thr, BK=32, PROW=80)
// mode: 0 = plain, 1 = silu, 2 = fused gates epilogue (+2 chunk scanA's)
// col0: column offset of this launch's tiles; row0: absolute row offset used
//       ONLY by the mode-2 epilogue for global-symbol indexing.
// ---------------------------------------------------------------------------
#define BK    32
#define PROW  80
#define SZ_T  (128*PROW)           // 10240
#define OFF_B SZ_T
#define STAGE (2*SZ_T)             // 20480
#define GEMM_SMEM (2*STAGE)        // 40960 >= mode-2 overlay 34816

__global__ __launch_bounds__(256)
void mma_gemm(const __half* __restrict__ A, const __half* __restrict__ Bt,
              int M, int N, int K, int col0, int row0,
              const float* __restrict__ bias, int mode,
              float* __restrict__ Cf, __half* __restrict__ Ch)
{
    extern __shared__ __align__(128) char smem[];
    const uint32_t sb = smem_u32(smem);
    const int tid = threadIdx.x;
    const int wid = tid >> 5, lane = tid & 31;
    const long brow = (long)blockIdx.y * 128;
    const long bcol = (long)col0 + (long)blockIdx.x * 128;

    const int rowBase = (wid >> 2) * 64;
    const int colBase = (wid & 3) * 32;

    float acc[4][4][4];
#pragma unroll
    for (int a = 0; a < 4; a++)
#pragma unroll
        for (int b = 0; b < 4; b++)
#pragma unroll
            for (int c = 0; c < 4; c++) acc[a][b][c] = 0.f;

    const int nch = K / BK;

    auto load_stage = [&](int s, int cidx){
        const uint32_t base = sb + s * STAGE;
        const long kc = (long)cidx * BK;
#pragma unroll
        for (int i = tid; i < 512; i += 256) {
            const int row = i >> 2, ch = i & 3;
            const uint32_t d = row * PROW + ch * 16;
            cp_async16(base + d,         A  + (brow + row) * (long)K + kc + ch * 8);
            cp_async16(base + OFF_B + d, Bt + (bcol + row) * (long)K + kc + ch * 8);
        }
        cp_commit();
    };

    load_stage(0, 0);

    const int g = lane >> 3, r = lane & 7;

    for (int c = 0; c < nch; c++) {
        if (c + 1 < nch) { load_stage((c + 1) & 1, c + 1);
                           asm volatile("cp.async.wait_group 1;" ::: "memory"); }
        else             { asm volatile("cp.async.wait_group 0;" ::: "memory"); }
        __syncthreads();

        const uint32_t st = sb + (c & 1) * STAGE;
#pragma unroll
        for (int ks = 0; ks < 2; ks++) {
            const int k0 = ks * 16;
            uint32_t bf[2][4];
#pragma unroll
            for (int p = 0; p < 2; p++) {
                const uint32_t boff =
                    (uint32_t)(colBase + p*16 + ((g >> 1) << 3) + r) * PROW
                    + (uint32_t)(k0 + ((g & 1) << 3)) * 2;
                LDSM4(bf[p], st + OFF_B + boff);
            }
#pragma unroll
            for (int mi = 0; mi < 4; mi++) {
                const uint32_t aoff =
                    (uint32_t)(rowBase + mi*16 + r + ((g & 1) << 3)) * PROW
                    + (uint32_t)(k0 + ((g >> 1) << 3)) * 2;
                uint32_t af[4];
                LDSM4(af, st + aoff);
#pragma unroll
                for (int ni = 0; ni < 4; ni++) {
                    const int p = ni >> 1, q = (ni & 1) * 2;
                    MMA_F16(acc[mi][ni], af, bf[p][q], bf[p][q+1]);
                }
            }
        }
        __syncthreads();
    }

    const int gID = lane >> 2, tig = lane & 3;

    if (mode == 2) {
        // fused gates epilogue; tile rows = 2 scan chunks of CLEN=64
        __half2* sAB  = (__half2*)smem;
        float*   segb = (float*)(smem + 128*64*4);
#pragma unroll
        for (int mi = 0; mi < 4; mi++) {
#pragma unroll
            for (int ni = 0; ni < 4; ni++) {
                const long col = bcol + colBase + ni*8 + tig*2;
                const int hloc = (colBase >> 1) + ni*4 + tig;
                const int h    = (int)(col >> 1);
#pragma unroll
                for (int half = 0; half < 2; half++) {
                    const int  rloc = rowBase + mi*16 + gID + half*8;
                    const long arow = (long)row0 + brow + rloc;   // absolute row
                    const float rec = acc[mi][ni][half*2]   + g_bil[col];
                    const float inp = acc[mi][ni][half*2+1] + g_bil[col + 1];
                    const float sp = g_splam[h];
                    const float sr = __fdividef(1.f, 1.f + __expf(-rec));
                    const float om = -expm1f(-sp * sr);          // 1 - alpha
                    const float a  = 1.f - om;
                    const float si = __fdividef(1.f, 1.f + __expf(-inp));
                    const float xc = __half2float(g_xc[arow * HID + h]);
                    const float bp = sqrtf(1.f - a*a + 1e-8f) * si * xc;
                    const __half2 pk = __floats2half2_rn(om, bp);
                    g_ab[arow * HID + h] = pk;
                    sAB[rloc * 64 + hloc] = pk;
                }
            }
        }
        __syncthreads();
        const int ch  = tid & 63;
        const int seg = tid >> 6;
        const long abrow = (long)row0 + brow;
        const int b   = (int)(abrow >> 11);
        const int cc0 = (int)((abrow >> 6) & (NC - 1));
#pragma unroll
        for (int sub = 0; sub < 2; sub++) {
            float Aprod = 1.f, Bacc = 0.f;
            int rr = sub * 64 + seg * 16;
#pragma unroll 8
            for (int t = 0; t < 16; t++, rr++) {
                const __half2 pk = sAB[rr * 64 + ch];
                const float a = 1.f - __low2float(pk);
                const float p = __high2float(pk);
                Bacc = fmaf(a, Bacc, p);
                Aprod *= a;
            }
            segb[(ch * 4 + seg) * 2]     = Aprod;
            segb[(ch * 4 + seg) * 2 + 1] = Bacc;
            __syncthreads();
            if (tid < 64) {
                float At = 1.f, Bv = 0.f;
#pragma unroll
                for (int s2 = 0; s2 < 4; s2++) {
                    const float a = segb[(tid * 4 + s2) * 2];
                    const float p = segb[(tid * 4 + s2) * 2 + 1];
                    Bv = fmaf(a, Bv, p);
                    At *= a;
                }
                const int h = (int)(bcol >> 1) + tid;
                g_cA[(b*NC + cc0 + sub)*HID + h] = At;
                g_cB[(b*NC + cc0 + sub)*HID + h] = Bv;
            }
            __syncthreads();
        }
        return;
    }

#pragma unroll
    for (int mi = 0; mi < 4; mi++) {
#pragma unroll
        for (int ni = 0; ni < 4; ni++) {
            const long col = bcol + colBase + ni*8 + tig*2;
            float b0 = 0.f, b1 = 0.f;
            if (bias) { b0 = __ldg(&bias[col]); b1 = __ldg(&bias[col+1]); }
#pragma unroll
            for (int half = 0; half < 2; half++) {
                const long row = brow + rowBase + mi*16 + gID + half*8;
                float v0 = acc[mi][ni][half*2]   + b0;
                float v1 = acc[mi][ni][half*2+1] + b1;
                if (mode == 1) {
                    v0 = __fdividef(v0, 1.f + __expf(-v0));
                    v1 = __fdividef(v1, 1.f + __expf(-v1));
                }
                if (Ch) *(__half2*)&Ch[row * N + col] = __floats2half2_rn(v0, v1);
                else    *(float2*)&Cf[row * N + col] = make_float2(v0, v1);
            }
        }
    }
}

// ---------------------------------------------------------------------------
// fp16 GEMM + fused residual/LayerNorm. tile 128x256, 512 thr (2x8 warps).
// ---------------------------------------------------------------------------
#define TILE_A2 (128*PROW)           // 10240
#define TILE_B2 (256*PROW)           // 20480
#define OFF_B2  TILE_A2
#define STAGE2  (TILE_A2 + TILE_B2)  // 30720
#define LN_SMEM (2*STAGE2 + 2*128*4) // 62464

__global__ __launch_bounds__(512)
void mma_gemm_ln(const __half* __restrict__ A, const __half* __restrict__ Bt,
                 int K,
                 const float* __restrict__ bias,
                 const float* __restrict__ R,
                 const float* __restrict__ gamma, const float* __restrict__ beta,
                 float* __restrict__ Cf, __half* __restrict__ Ch)
{
    extern __shared__ __align__(128) char smem[];
    const uint32_t sb = smem_u32(smem);
    float* srow  = (float*)(smem + 2*STAGE2);
    float* srow2 = srow + 128;
    const int tid = threadIdx.x;
    const int wid = tid >> 5, lane = tid & 31;
    const long brow = (long)blockIdx.y * 128;

    const int rowBase = (wid >> 3) * 64;
    const int colBase = (wid & 7) * 32;

    float acc[4][4][4];
#pragma unroll
    for (int a = 0; a < 4; a++)
#pragma unroll
        for (int b = 0; b < 4; b++)
#pragma unroll
            for (int c = 0; c < 4; c++) acc[a][b][c] = 0.f;

    const int nch = K / BK;

    auto load_stage = [&](int s, int cidx){
        const uint32_t base = sb + s * STAGE2;
        const long kc = (long)cidx * BK;
#pragma unroll
        for (int i = tid; i < 1536; i += 512) {
            const int row = i >> 2, ch = i & 3;
            if (row < 128) {
                cp_async16(base + row * PROW + ch * 16,
                           A + (brow + row) * (long)K + kc + ch * 8);
            } else {
                const int br = row - 128;
                cp_async16(base + OFF_B2 + br * PROW + ch * 16,
                           Bt + br * (long)K + kc + ch * 8);
            }
        }
        cp_commit();
    };

    load_stage(0, 0);

    const int g = lane >> 3, r = lane & 7;

    for (int c = 0; c < nch; c++) {
        if (c + 1 < nch) { load_stage((c + 1) & 1, c + 1);
                           asm volatile("cp.async.wait_group 1;" ::: "memory"); }
        else             { asm volatile("cp.async.wait_group 0;" ::: "memory"); }
        __syncthreads();

        const uint32_t st = sb + (c & 1) * STAGE2;
#pragma unroll
        for (int ks = 0; ks < 2; ks++) {
            const int k0 = ks * 16;
            uint32_t bf[2][4];
#pragma unroll
            for (int p = 0; p < 2; p++) {
                const uint32_t boff =
                    (uint32_t)(colBase + p*16 + ((g >> 1) << 3) + r) * PROW
                    + (uint32_t)(k0 + ((g & 1) << 3)) * 2;
                LDSM4(bf[p], st + OFF_B2 + boff);
            }
#pragma unroll
            for (int mi = 0; mi < 4; mi++) {
                const uint32_t aoff =
                    (uint32_t)(rowBase + mi*16 + r + ((g & 1) << 3)) * PROW
                    + (uint32_t)(k0 + ((g >> 1) << 3)) * 2;
                uint32_t af[4];
                LDSM4(af, st + aoff);
#pragma unroll
                for (int ni = 0; ni < 4; ni++) {
                    const int p = ni >> 1, q = (ni & 1) * 2;
                    MMA_F16(acc[mi][ni], af, bf[p][q], bf[p][q+1]);
                }
            }
        }
        __syncthreads();
    }

    if (tid < 128) { srow[tid] = 0.f; srow2[tid] = 0.f; }
    __syncthreads();

    const int gID = lane >> 2, tig = lane & 3;

#pragma unroll
    for (int mi = 0; mi < 4; mi++) {
#pragma unroll
        for (int half = 0; half < 2; half++) {
            const int  rloc = rowBase + mi*16 + gID + half*8;
            const long row  = brow + rloc;
            float s = 0.f, s2 = 0.f;
#pragma unroll
            for (int ni = 0; ni < 4; ni++) {
                const int col = colBase + ni*8 + tig*2;
                float2 rv = *(const float2*)&R[row * DMODEL + col];
                float v0 = acc[mi][ni][half*2]   + rv.x;
                float v1 = acc[mi][ni][half*2+1] + rv.y;
                if (bias) { v0 += __ldg(&bias[col]); v1 += __ldg(&bias[col+1]); }
                acc[mi][ni][half*2]   = v0;
                acc[mi][ni][half*2+1] = v1;
                s  += v0 + v1;
                s2 += v0*v0 + v1*v1;
            }
            atomicAdd(&srow[rloc],  s);
            atomicAdd(&srow2[rloc], s2);
        }
    }
    __syncthreads();

#pragma unroll
    for (int mi = 0; mi < 4; mi++) {
#pragma unroll
        for (int half = 0; half < 2; half++) {
            const int  rloc = rowBase + mi*16 + gID + half*8;
            const long row  = brow + rloc;
            const float mean = srow[rloc] * (1.f / DMODEL);
            float var = srow2[rloc] * (1.f / DMODEL) - mean * mean;
            const float rs = rsqrtf(var + 1e-12f);
#pragma unroll
            for (int ni = 0; ni < 4; ni++) {
                const int col = colBase + ni*8 + tig*2;
                float2 gv = *(const float2*)&gamma[col];
                float2 bv = *(const float2*)&beta[col];
                float v0 = (acc[mi][ni][half*2]   - mean) * rs * gv.x + bv.x;
                float v1 = (acc[mi][ni][half*2+1] - mean) * rs * gv.y + bv.y;
                *(float2*)&Cf[row * DMODEL + col] = make_float2(v0, v1);
                if (Ch) *(__half2*)&Ch[row * DMODEL + col] = __floats2half2_rn(v0, v1);
            }
        }
    }
}

// ---------------------------------------------------------------------------
// Prep: splam/bias + all weight transposes + x->fp16 in ONE launch
// ---------------------------------------------------------------------------
#define WT_B0 1
#define WT_B1 (WT_B0 + (DMODEL*HID2)/256)
#define WT_B2 (WT_B1 + (HID*HID2)/256)
#define WT_B3 (WT_B2 + (HID*DMODEL)/256)
#define WT_B4 (WT_B3 + (DMODEL*INNER)/256)
#define WT_B5 (WT_B4 + (INNER*DMODEL)/256)
#define XH_BLKS ((NTOK*DMODEL/4)/256)
#define WT_B6 (WT_B5 + XH_BLKS)

__global__ __launch_bounds__(256)
void prep_kernel(const float* __restrict__ Lambda, const float* __restrict__ b_gates,
                 const float* __restrict__ w_in, const float* __restrict__ w_gates,
                 const float* __restrict__ w_out, const float* __restrict__ ffn_w1,
                 const float* __restrict__ ffn_w2, const float* __restrict__ x)
{
    const int blk = blockIdx.x;
    const int t = threadIdx.x;
    if (blk == 0) {
#pragma unroll
        for (int q = 0; q < 2; q++) {
            int h = t + q * 256;
            g_splam[h] = log1pf(expf(Lambda[h]));
            g_bil[2*h]     = b_gates[h];
            g_bil[2*h + 1] = b_gates[HID + h];
        }
        return;
    }
    if (blk >= WT_B5) {
        const long i = (long)(blk - WT_B5) * 256 + t;
        float4 v = ((const float4*)x)[i];
        ((__half2*)g_xr)[2*i]   = __floats2half2_rn(v.x, v.y);
        ((__half2*)g_xr)[2*i+1] = __floats2half2_rn(v.z, v.w);
        return;
    }
    const float* W; __half* WT; int K, N, il = 0; long base;
    if (blk < WT_B1)      { W = w_in;    WT = g_wiT; K = DMODEL; N = HID2;   base = (long)(blk - WT_B0) * 256; }
    else if (blk < WT_B2) { W = w_gates; WT = g_wgT; K = HID;    N = HID2;   base = (long)(blk - WT_B1) * 256; il = 1; }
    else if (blk < WT_B3) { W = w_out;   WT = g_woT; K = HID;    N = DMODEL; base = (long)(blk - WT_B2) * 256; }
    else if (blk < WT_B4) { W = ffn_w1;  WT = g_f1T; K = DMODEL; N = INNER;  base = (long)(blk - WT_B3) * 256; }
    else                  { W = ffn_w2;  WT = g_f2T; K = INNER;  N = DMODEL; base = (long)(blk - WT_B4) * 256; }
    const long i = base + t;
    const int k = (int)(i % K);
    const int n = (int)(i / K);
    const int col = il ? ((n >> 1) + (n & 1) * HID) : n;
    WT[i] = __float2half_rn(W[(long)k * N + col]);
}

// ---------------------------------------------------------------------------
// Sliding-window causal depthwise conv (K=4) + bias + silu. b0 = batch offset
// ---------------------------------------------------------------------------
__global__ __launch_bounds__(256)
void conv_silu_kernel(const float* __restrict__ conv_w,
                      const float* __restrict__ conv_b, int b0)
{
    const int h2 = threadIdx.x;
    const int b  = b0 + blockIdx.y;
    const int t0 = blockIdx.x * CONV_CHUNK;
    const int h  = h2 << 1;

    const float4 wa = *(const float4*)&conv_w[h * 4];
    const float4 wb = *(const float4*)&conv_w[h * 4 + 4];
    const float  ca = conv_b[h], cb = conv_b[h + 1];

    const __half2* xz = (const __half2*)g_xzh;
    const long rs = HID2 / 2;
    long base = ((long)b * SEQ + t0) * rs + h2;

    float a0 = 0.f, a1 = 0.f, a2 = 0.f;
    float b0f = 0.f, b1f = 0.f, b2f = 0.f;
    if (t0 >= 3) {
        __half2 p;
        p = xz[base - 3*rs]; a0 = __low2float(p); b0f = __high2float(p);
        p = xz[base - 2*rs]; a1 = __low2float(p); b1f = __high2float(p);
        p = xz[base - 1*rs]; a2 = __low2float(p); b2f = __high2float(p);
    }

    __half2* xcp = (__half2*)g_xc;
    long ob = ((long)b * SEQ + t0) * (HID / 2) + h2;

#pragma unroll 4
    for (int t = 0; t < CONV_CHUNK; t++) {
        const __half2 cur = xz[base]; base += rs;
        const float xa = __low2float(cur), xb = __high2float(cur);
        float va = ca, vb = cb;
        va = fmaf(wa.x, a0, va); va = fmaf(wa.y, a1, va);
        va = fmaf(wa.z, a2, va); va = fmaf(wa.w, xa, va);
        vb = fmaf(wb.x, b0f, vb); vb = fmaf(wb.y, b1f, vb);
        vb = fmaf(wb.z, b2f, vb); vb = fmaf(wb.w, xb, vb);
        a0 = a1; a1 = a2; a2 = xa;
        b0f = b1f; b1f = b2f; b2f = xb;
        va = __fdividef(va, 1.f + __expf(-va));
        vb = __fdividef(vb, 1.f + __expf(-vb));
        xcp[ob] = __floats2half2_rn(va, vb);
        ob += HID / 2;
    }
}

// ---------------------------------------------------------------------------
// scanC: 2 channels per thread; carry recomputed in-block. b0 = batch offset
// ---------------------------------------------------------------------------
__global__ __launch_bounds__(256)
void scanC_kernel(int b0)
{
    const int tid = threadIdx.x;
    const int c = blockIdx.x % NC;
    const int b = b0 + blockIdx.x / NC;
    const int h = tid << 1;

    float hx = 0.f, hy = 0.f;
    for (int j = 0; j < c; j++) {
        const int i = (b*NC + j)*HID + h;
        const float2 a  = *(const float2*)&g_cA[i];
        const float2 bb = *(const float2*)&g_cB[i];
        hx = fmaf(a.x, hx, bb.x);
        hy = fmaf(a.y, hy, bb.y);
    }

    long base  = ((long)b*SEQ + c*CLEN)*HID  + h;
    long zbase = ((long)b*SEQ + c*CLEN)*HID2 + HID + h;
    for (int t = 0; t < CLEN; t++) {
        const uint2 pk2 = *(const uint2*)&g_ab[base];
        const __half2 p0 = *(const __half2*)&pk2.x;
        const __half2 p1 = *(const __half2*)&pk2.y;
        const float om0 = __low2float(p0), bp0 = __high2float(p0);
        const float om1 = __low2float(p1), bp1 = __high2float(p1);
        hx = fmaf(-om0, hx, hx) + bp0;
        hy = fmaf(-om1, hy, hy) + bp1;
        const __half2 zz = *(const __half2*)&g_xzh[zbase];
        const float z0 = __low2float(zz), z1 = __high2float(zz);
        const float s0 = __fdividef(z0, 1.f + __expf(-z0));
        const float s1 = __fdividef(z1, 1.f + __expf(-z1));
        *(__half2*)&g_y[base] = __floats2half2_rn(s0 * hx, s1 * hy);
        base  += HID;
        zbase += HID2;
    }
}

// ---------------------------------------------------------------------------
// Launch: two fully independent half-batch pipelines on two streams
// ---------------------------------------------------------------------------
extern "C" void kernel_launch(void* const* d_in, const int* in_sizes, int n_in,
                              void* d_out, int out_size)
{
    const float* x      = (const float*)d_in[0];
    const float* w_in   = (const float*)d_in[1];
    const float* conv_w = (const float*)d_in[2];
    const float* conv_b = (const float*)d_in[3];
    const float* w_gates= (const float*)d_in[4];
    const float* b_gates= (const float*)d_in[5];
    const float* Lambda = (const float*)d_in[6];
    const float* w_out  = (const float*)d_in[7];
    const float* ln1_g  = (const float*)d_in[8];
    const float* ln1_b  = (const float*)d_in[9];
    const float* ffn_w1 = (const float*)d_in[10];
    const float* ffn_b1 = (const float*)d_in[11];
    const float* ffn_w2 = (const float*)d_in[12];
    const float* ffn_b2 = (const float*)d_in[13];
    const float* ln2_g  = (const float*)d_in[14];
    const float* ln2_b  = (const float*)d_in[15];
    float* dout = (float*)d_out;

    static cudaStream_t s2 = nullptr;
    static cudaEvent_t evFork = nullptr, evB = nullptr;
    static bool init_done = false;
    if (!init_done) {
        cudaFuncSetAttribute(mma_gemm,    cudaFuncAttributeMaxDynamicSharedMemorySize, GEMM_SMEM);
        cudaFuncSetAttribute(mma_gemm_ln, cudaFuncAttributeMaxDynamicSharedMemorySize, LN_SMEM);
        cudaStreamCreateWithFlags(&s2, cudaStreamNonBlocking);
        cudaEventCreateWithFlags(&evFork, cudaEventDisableTiming);
        cudaEventCreateWithFlags(&evB,    cudaEventDisableTiming);
        init_done = true;
    }

    float *hs;
    __half *xzh, *xr, *xc, *y, *hsh, *ff1, *wiT, *wgT, *woT, *f1T, *f2T;
    cudaGetSymbolAddress((void**)&hs,  g_hs);
    cudaGetSymbolAddress((void**)&xzh, g_xzh);
    cudaGetSymbolAddress((void**)&xr,  g_xr);
    cudaGetSymbolAddress((void**)&xc,  g_xc);
    cudaGetSymbolAddress((void**)&y,   g_y);
    cudaGetSymbolAddress((void**)&hsh, g_hsh);
    cudaGetSymbolAddress((void**)&ff1, g_ff1);
    cudaGetSymbolAddress((void**)&wiT, g_wiT);
    cudaGetSymbolAddress((void**)&wgT, g_wgT);
    cudaGetSymbolAddress((void**)&woT, g_woT);
    cudaGetSymbolAddress((void**)&f1T, g_f1T);
    cudaGetSymbolAddress((void**)&f2T, g_f2T);

    // pointer offsets for half B
    const size_t oD = (size_t)HROWS * DMODEL;
    const size_t oH = (size_t)HROWS * HID;
    const size_t oZ = (size_t)HROWS * HID2;
    const size_t oI = (size_t)HROWS * INNER;

    // 0. prep (full)
    prep_kernel<<<WT_B6, 256>>>(Lambda, b_gates, w_in, w_gates, w_out,
                                ffn_w1, ffn_w2, x);
    cudaEventRecord(evFork, 0);
    cudaStreamWaitEvent(s2, evFork, 0);

    // ================= half A (batches 0..15) on main stream =================
    mma_gemm<<<dim3(4, HROWS/128), 256, GEMM_SMEM>>>(            // xh_A
        xr, wiT, HROWS, HID2, DMODEL, 0, 0, nullptr, 0, nullptr, xzh);
    conv_silu_kernel<<<dim3(SEQ/CONV_CHUNK, HBATCH), 256>>>(conv_w, conv_b, 0);
    mma_gemm<<<dim3(HID2/128, HROWS/128), 256, GEMM_SMEM>>>(     // gates_A
        xc, wgT, HROWS, HID2, HID, 0, 0, nullptr, 2, nullptr, nullptr);
    mma_gemm<<<dim3(4, HROWS/128), 256, GEMM_SMEM>>>(            // z_A
        xr, wiT, HROWS, HID2, DMODEL, 512, 0, nullptr, 0, nullptr, xzh);
    scanC_kernel<<<HBATCH*NC, 256>>>(0);
    mma_gemm_ln<<<dim3(1, HROWS/128), 512, LN_SMEM>>>(           // LN1_A
        y, woT, HID, nullptr, x, ln1_g, ln1_b, hs, hsh);
    mma_gemm<<<dim3(INNER/128, HROWS/128), 256, GEMM_SMEM>>>(    // ffn1_A
        hsh, f1T, HROWS, INNER, DMODEL, 0, 0, ffn_b1, 1, nullptr, ff1);
    mma_gemm_ln<<<dim3(1, HROWS/128), 512, LN_SMEM>>>(           // ffn2_A
        ff1, f2T, INNER, ffn_b2, hs, ln2_g, ln2_b, dout, nullptr);

    // ================= half B (batches 16..31) on side stream ================
    mma_gemm<<<dim3(4, HROWS/128), 256, GEMM_SMEM, s2>>>(        // z_B
        xr + oD, wiT, HROWS, HID2, DMODEL, 512, 0, nullptr, 0, nullptr, xzh + oZ);
    mma_gemm<<<dim3(4, HROWS/128), 256, GEMM_SMEM, s2>>>(        // xh_B
        xr + oD, wiT, HROWS, HID2, DMODEL, 0, 0, nullptr, 0, nullptr, xzh + oZ);
    conv_silu_kernel<<<dim3(SEQ/CONV_CHUNK, HBATCH), 256, 0, s2>>>(conv_w, conv_b, HBATCH);
    mma_gemm<<<dim3(HID2/128, HROWS/128), 256, GEMM_SMEM, s2>>>( // gates_B
        xc + oH, wgT, HROWS, HID2, HID, 0, HROWS, nullptr, 2, nullptr, nullptr);
    scanC_kernel<<<HBATCH*NC, 256, 0, s2>>>(HBATCH);
    mma_gemm_ln<<<dim3(1, HROWS/128), 512, LN_SMEM, s2>>>(       // LN1_B
        y + oH, woT, HID, nullptr, x + oD, ln1_g, ln1_b, hs + oD, hsh + oD);
    mma_gemm<<<dim3(INNER/128, HROWS/128), 256, GEMM_SMEM, s2>>>(// ffn1_B
        hsh + oD, f1T, HROWS, INNER, DMODEL, 0, 0, ffn_b1, 1, nullptr, ff1 + oI);
    mma_gemm_ln<<<dim3(1, HROWS/128), 512, LN_SMEM, s2>>>(       // ffn2_B
        ff1 + oI, f2T, INNER, ffn_b2, hs + oD, ln2_g, ln2_b, dout + oD, nullptr);
    cudaEventRecord(evB, s2);

    // join
    cudaStreamWaitEvent(0, evB, 0);
}

// round 14
// speedup vs baseline: 5.5648x; 1.1584x over previous
#include <cuda_runtime.h>
#include <cuda_fp16.h>
#include <math.h>
#include <stdint.h>

#define BATCH  32
#define SEQ    2048
#define DMODEL 256
#define HID    512
#define HID2   1024
#define INNER  1024
#define NTOK   (BATCH*SEQ)   // 65536
#define NC     32
#define CLEN   (SEQ/NC)      // 64
#define CONV_CHUNK 32
#define HBATCH (BATCH/2)
#define HROWS  (NTOK/2)      // 32768

// ---------------------------------------------------------------------------
// Scratch
// ---------------------------------------------------------------------------
__device__ float g_hs   [(size_t)NTOK*DMODEL];
__device__ float g_cA   [BATCH*NC*HID];
__device__ float g_cB   [BATCH*NC*HID];
__device__ float g_splam[HID];
__device__ float g_bil  [HID2];
__device__ __align__(256) __half2 g_ab[(size_t)NTOK*HID];
__device__ __align__(256) __half g_xzh[(size_t)NTOK*HID2];  // [xh | z]
__device__ __align__(256) __half g_xr [(size_t)NTOK*DMODEL];
__device__ __align__(256) __half g_xc [(size_t)NTOK*HID];
__device__ __align__(256) __half g_y  [(size_t)NTOK*HID];
__device__ __align__(256) __half g_hsh[(size_t)NTOK*DMODEL];
__device__ __align__(256) __half g_ff1[(size_t)NTOK*INNER];
__device__ __align__(256) __half g_wiT[HID2*DMODEL];
__device__ __align__(256) __half g_wgT[HID2*HID];
__device__ __align__(256) __half g_woT[DMODEL*HID];
__device__ __align__(256) __half g_f1T[INNER*DMODEL];
__device__ __align__(256) __half g_f2T[DMODEL*INNER];

// ---------------------------------------------------------------------------
// helpers
// ---------------------------------------------------------------------------
__device__ __forceinline__ uint32_t smem_u32(const void* p){
    uint32_t a;
    asm("{ .reg .u64 t; cvta.to.shared.u64 t, %1; cvt.u32.u64 %0, t; }"
        : "=r"(a) : "l"(p));
    return a;
}
__device__ __forceinline__ void cp_async16(uint32_t dst, const void* src){
    asm volatile("cp.async.cg.shared.global [%0], [%1], 16;" :: "r"(dst), "l"(src));
}
__device__ __forceinline__ void cp_commit(){ asm volatile("cp.async.commit_group;"); }

#define LDSM4(R, A) \
    asm volatile("ldmatrix.sync.aligned.m8n8.x4.shared.b16 {%0,%1,%2,%3}, [%4];" \
        : "=r"((R)[0]),"=r"((R)[1]),"=r"((R)[2]),"=r"((R)[3]) : "r"(A))

#define MMA_F16(C, A, B0, B1) \
    asm volatile("mma.sync.aligned.m16n8k16.row.col.f32.f16.f16.f32 " \
        "{%0,%1,%2,%3},{%4,%5,%6,%7},{%8,%9},{%0,%1,%2,%3};" \
        : "+f"((C)[0]),"+f"((C)[1]),"+f"((C)[2]),"+f"((C)[3]) \
        : "r"((A)[0]),"r"((A)[1]),"r"((A)[2]),"r"((A)[3]),"r"(B0),"r"(B1))

// ---------------------------------------------------------------------------
// fp16 GEMM (128x128 tile, 256 thr, BK=64, PROW=144)
// mode: 0 = plain, 1 = silu, 2 = fused gates epilogue (+2 chunk scanA's)
// ---------------------------------------------------------------------------
#define BK    64
#define PROW  144                  // 128 data bytes + 16 pad
#define SZ_T  (128*PROW)           // 18432
#define OFF_B SZ_T
#define STAGE (2*SZ_T)             // 36864
#define GEMM_SMEM (2*STAGE)        // 73728 >= mode-2 overlay 34816

__global__ __launch_bounds__(256)
void mma_gemm(const __half* __restrict__ A, const __half* __restrict__ Bt,
              int M, int N, int K, int col0, int row0,
              const float* __restrict__ bias, int mode,
              float* __restrict__ Cf, __half* __restrict__ Ch)
{
    extern __shared__ __align__(128) char smem[];
    const uint32_t sb = smem_u32(smem);
    const int tid = threadIdx.x;
    const int wid = tid >> 5, lane = tid & 31;
    const long brow = (long)blockIdx.y * 128;
    const long bcol = (long)col0 + (long)blockIdx.x * 128;

    const int rowBase = (wid >> 2) * 64;
    const int colBase = (wid & 3) * 32;

    float acc[4][4][4];
#pragma unroll
    for (int a = 0; a < 4; a++)
#pragma unroll
        for (int b = 0; b < 4; b++)
#pragma unroll
            for (int c = 0; c < 4; c++) acc[a][b][c] = 0.f;

    const int nch = K / BK;

    auto load_stage = [&](int s, int cidx){
        const uint32_t base = sb + s * STAGE;
        const long kc = (long)cidx * BK;
#pragma unroll
        for (int i = tid; i < 1024; i += 256) {
            const int row = i >> 3, ch = i & 7;
            const uint32_t d = row * PROW + ch * 16;
            cp_async16(base + d,         A  + (brow + row) * (long)K + kc + ch * 8);
            cp_async16(base + OFF_B + d, Bt + (bcol + row) * (long)K + kc + ch * 8);
        }
        cp_commit();
    };

    load_stage(0, 0);

    const int g = lane >> 3, r = lane & 7;

    for (int c = 0; c < nch; c++) {
        if (c + 1 < nch) { load_stage((c + 1) & 1, c + 1);
                           asm volatile("cp.async.wait_group 1;" ::: "memory"); }
        else             { asm volatile("cp.async.wait_group 0;" ::: "memory"); }
        __syncthreads();

        const uint32_t st = sb + (c & 1) * STAGE;
#pragma unroll
        for (int ks = 0; ks < 4; ks++) {
            const int k0 = ks * 16;
            uint32_t bf[2][4];
#pragma unroll
            for (int p = 0; p < 2; p++) {
                const uint32_t boff =
                    (uint32_t)(colBase + p*16 + ((g >> 1) << 3) + r) * PROW
                    + (uint32_t)(k0 + ((g & 1) << 3)) * 2;
                LDSM4(bf[p], st + OFF_B + boff);
            }
#pragma unroll
            for (int mi = 0; mi < 4; mi++) {
                const uint32_t aoff =
                    (uint32_t)(rowBase + mi*16 + r + ((g & 1) << 3)) * PROW
                    + (uint32_t)(k0 + ((g >> 1) << 3)) * 2;
                uint32_t af[4];
                LDSM4(af, st + aoff);
#pragma unroll
                for (int ni = 0; ni < 4; ni++) {
                    const int p = ni >> 1, q = (ni & 1) * 2;
                    MMA_F16(acc[mi][ni], af, bf[p][q], bf[p][q+1]);
                }
            }
        }
        __syncthreads();
    }

    const int gID = lane >> 2, tig = lane & 3;

    if (mode == 2) {
        // fused gates epilogue; tile rows = 2 scan chunks of CLEN=64
        __half2* sAB  = (__half2*)smem;
        float*   segb = (float*)(smem + 128*64*4);
#pragma unroll
        for (int mi = 0; mi < 4; mi++) {
#pragma unroll
            for (int ni = 0; ni < 4; ni++) {
                const long col = bcol + colBase + ni*8 + tig*2;
                const int hloc = (colBase >> 1) + ni*4 + tig;
                const int h    = (int)(col >> 1);
#pragma unroll
                for (int half = 0; half < 2; half++) {
                    const int  rloc = rowBase + mi*16 + gID + half*8;
                    const long arow = (long)row0 + brow + rloc;
                    const float rec = acc[mi][ni][half*2]   + g_bil[col];
                    const float inp = acc[mi][ni][half*2+1] + g_bil[col + 1];
                    const float sp = g_splam[h];
                    const float sr = __fdividef(1.f, 1.f + __expf(-rec));
                    const float om = -expm1f(-sp * sr);          // 1 - alpha
                    const float a  = 1.f - om;
                    const float si = __fdividef(1.f, 1.f + __expf(-inp));
                    const float xc = __half2float(g_xc[arow * HID + h]);
                    const float bp = sqrtf(1.f - a*a + 1e-8f) * si * xc;
                    const __half2 pk = __floats2half2_rn(om, bp);
                    g_ab[arow * HID + h] = pk;
                    sAB[rloc * 64 + hloc] = pk;
                }
            }
        }
        __syncthreads();
        const int ch  = tid & 63;
        const int seg = tid >> 6;
        const long abrow = (long)row0 + brow;
        const int b   = (int)(abrow >> 11);
        const int cc0 = (int)((abrow >> 6) & (NC - 1));
#pragma unroll
        for (int sub = 0; sub < 2; sub++) {
            float Aprod = 1.f, Bacc = 0.f;
            int rr = sub * 64 + seg * 16;
#pragma unroll 8
            for (int t = 0; t < 16; t++, rr++) {
                const __half2 pk = sAB[rr * 64 + ch];
                const float a = 1.f - __low2float(pk);
                const float p = __high2float(pk);
                Bacc = fmaf(a, Bacc, p);
                Aprod *= a;
            }
            segb[(ch * 4 + seg) * 2]     = Aprod;
            segb[(ch * 4 + seg) * 2 + 1] = Bacc;
            __syncthreads();
            if (tid < 64) {
                float At = 1.f, Bv = 0.f;
#pragma unroll
                for (int s2 = 0; s2 < 4; s2++) {
                    const float a = segb[(tid * 4 + s2) * 2];
                    const float p = segb[(tid * 4 + s2) * 2 + 1];
                    Bv = fmaf(a, Bv, p);
                    At *= a;
                }
                const int h = (int)(bcol >> 1) + tid;
                g_cA[(b*NC + cc0 + sub)*HID + h] = At;
                g_cB[(b*NC + cc0 + sub)*HID + h] = Bv;
            }
            __syncthreads();
        }
        return;
    }

#pragma unroll
    for (int mi = 0; mi < 4; mi++) {
#pragma unroll
        for (int ni = 0; ni < 4; ni++) {
            const long col = bcol + colBase + ni*8 + tig*2;
            float b0 = 0.f, b1 = 0.f;
            if (bias) { b0 = __ldg(&bias[col]); b1 = __ldg(&bias[col+1]); }
#pragma unroll
            for (int half = 0; half < 2; half++) {
                const long row = brow + rowBase + mi*16 + gID + half*8;
                float v0 = acc[mi][ni][half*2]   + b0;
                float v1 = acc[mi][ni][half*2+1] + b1;
                if (mode == 1) {
                    v0 = __fdividef(v0, 1.f + __expf(-v0));
                    v1 = __fdividef(v1, 1.f + __expf(-v1));
                }
                if (Ch) *(__half2*)&Ch[row * N + col] = __floats2half2_rn(v0, v1);
                else    *(float2*)&Cf[row * N + col] = make_float2(v0, v1);
            }
        }
    }
}

// ---------------------------------------------------------------------------
// fp16 GEMM + fused residual/LayerNorm. tile 128x256, 512 thr, BK=64.
// ---------------------------------------------------------------------------
#define TILE_A2 (128*PROW)           // 18432
#define TILE_B2 (256*PROW)           // 36864
#define OFF_B2  TILE_A2
#define STAGE2  (TILE_A2 + TILE_B2)  // 55296
#define LN_SMEM (2*STAGE2 + 2*128*4) // 111616

__global__ __launch_bounds__(512)
void mma_gemm_ln(const __half* __restrict__ A, const __half* __restrict__ Bt,
                 int K,
                 const float* __restrict__ bias,
                 const float* __restrict__ R,
                 const float* __restrict__ gamma, const float* __restrict__ beta,
                 float* __restrict__ Cf, __half* __restrict__ Ch)
{
    extern __shared__ __align__(128) char smem[];
    const uint32_t sb = smem_u32(smem);
    float* srow  = (float*)(smem + 2*STAGE2);
    float* srow2 = srow + 128;
    const int tid = threadIdx.x;
    const int wid = tid >> 5, lane = tid & 31;
    const long brow = (long)blockIdx.y * 128;

    const int rowBase = (wid >> 3) * 64;
    const int colBase = (wid & 7) * 32;

    float acc[4][4][4];
#pragma unroll
    for (int a = 0; a < 4; a++)
#pragma unroll
        for (int b = 0; b < 4; b++)
#pragma unroll
            for (int c = 0; c < 4; c++) acc[a][b][c] = 0.f;

    const int nch = K / BK;

    auto load_stage = [&](int s, int cidx){
        const uint32_t base = sb + s * STAGE2;
        const long kc = (long)cidx * BK;
#pragma unroll
        for (int i = tid; i < 3072; i += 512) {
            const int row = i >> 3, ch = i & 7;
            if (row < 128) {
                cp_async16(base + row * PROW + ch * 16,
                           A + (brow + row) * (long)K + kc + ch * 8);
            } else {
                const int br = row - 128;
                cp_async16(base + OFF_B2 + br * PROW + ch * 16,
                           Bt + br * (long)K + kc + ch * 8);
            }
        }
        cp_commit();
    };

    load_stage(0, 0);

    const int g = lane >> 3, r = lane & 7;

    for (int c = 0; c < nch; c++) {
        if (c + 1 < nch) { load_stage((c + 1) & 1, c + 1);
                           asm volatile("cp.async.wait_group 1;" ::: "memory"); }
        else             { asm volatile("cp.async.wait_group 0;" ::: "memory"); }
        __syncthreads();

        const uint32_t st = sb + (c & 1) * STAGE2;
#pragma unroll
        for (int ks = 0; ks < 4; ks++) {
            const int k0 = ks * 16;
            uint32_t bf[2][4];
#pragma unroll
            for (int p = 0; p < 2; p++) {
                const uint32_t boff =
                    (uint32_t)(colBase + p*16 + ((g >> 1) << 3) + r) * PROW
                    + (uint32_t)(k0 + ((g & 1) << 3)) * 2;
                LDSM4(bf[p], st + OFF_B2 + boff);
            }
#pragma unroll
            for (int mi = 0; mi < 4; mi++) {
                const uint32_t aoff =
                    (uint32_t)(rowBase + mi*16 + r + ((g & 1) << 3)) * PROW
                    + (uint32_t)(k0 + ((g >> 1) << 3)) * 2;
                uint32_t af[4];
                LDSM4(af, st + aoff);
#pragma unroll
                for (int ni = 0; ni < 4; ni++) {
                    const int p = ni >> 1, q = (ni & 1) * 2;
                    MMA_F16(acc[mi][ni], af, bf[p][q], bf[p][q+1]);
                }
            }
        }
        __syncthreads();
    }

    if (tid < 128) { srow[tid] = 0.f; srow2[tid] = 0.f; }
    __syncthreads();

    const int gID = lane >> 2, tig = lane & 3;

#pragma unroll
    for (int mi = 0; mi < 4; mi++) {
#pragma unroll
        for (int half = 0; half < 2; half++) {
            const int  rloc = rowBase + mi*16 + gID + half*8;
            const long row  = brow + rloc;
            float s = 0.f, s2 = 0.f;
#pragma unroll
            for (int ni = 0; ni < 4; ni++) {
                const int col = colBase + ni*8 + tig*2;
                float2 rv = *(const float2*)&R[row * DMODEL + col];
                float v0 = acc[mi][ni][half*2]   + rv.x;
                float v1 = acc[mi][ni][half*2+1] + rv.y;
                if (bias) { v0 += __ldg(&bias[col]); v1 += __ldg(&bias[col+1]); }
                acc[mi][ni][half*2]   = v0;
                acc[mi][ni][half*2+1] = v1;
                s  += v0 + v1;
                s2 += v0*v0 + v1*v1;
            }
            atomicAdd(&srow[rloc],  s);
            atomicAdd(&srow2[rloc], s2);
        }
    }
    __syncthreads();

#pragma unroll
    for (int mi = 0; mi < 4; mi++) {
#pragma unroll
        for (int half = 0; half < 2; half++) {
            const int  rloc = rowBase + mi*16 + gID + half*8;
            const long row  = brow + rloc;
            const float mean = srow[rloc] * (1.f / DMODEL);
            float var = srow2[rloc] * (1.f / DMODEL) - mean * mean;
            const float rs = rsqrtf(var + 1e-12f);
#pragma unroll
            for (int ni = 0; ni < 4; ni++) {
                const int col = colBase + ni*8 + tig*2;
                float2 gv = *(const float2*)&gamma[col];
                float2 bv = *(const float2*)&beta[col];
                float v0 = (acc[mi][ni][half*2]   - mean) * rs * gv.x + bv.x;
                float v1 = (acc[mi][ni][half*2+1] - mean) * rs * gv.y + bv.y;
                *(float2*)&Cf[row * DMODEL + col] = make_float2(v0, v1);
                if (Ch) *(__half2*)&Ch[row * DMODEL + col] = __floats2half2_rn(v0, v1);
            }
        }
    }
}

// ---------------------------------------------------------------------------
// Prep: splam/bias + all weight transposes + x->fp16 in ONE launch
// ---------------------------------------------------------------------------
#define WT_B0 1
#define WT_B1 (WT_B0 + (DMODEL*HID2)/256)
#define WT_B2 (WT_B1 + (HID*HID2)/256)
#define WT_B3 (WT_B2 + (HID*DMODEL)/256)
#define WT_B4 (WT_B3 + (DMODEL*INNER)/256)
#define WT_B5 (WT_B4 + (INNER*DMODEL)/256)
#define XH_BLKS ((NTOK*DMODEL/4)/256)
#define WT_B6 (WT_B5 + XH_BLKS)

__global__ __launch_bounds__(256)
void prep_kernel(const float* __restrict__ Lambda, const float* __restrict__ b_gates,
                 const float* __restrict__ w_in, const float* __restrict__ w_gates,
                 const float* __restrict__ w_out, const float* __restrict__ ffn_w1,
                 const float* __restrict__ ffn_w2, const float* __restrict__ x)
{
    const int blk = blockIdx.x;
    const int t = threadIdx.x;
    if (blk == 0) {
#pragma unroll
        for (int q = 0; q < 2; q++) {
            int h = t + q * 256;
            g_splam[h] = log1pf(expf(Lambda[h]));
            g_bil[2*h]     = b_gates[h];
            g_bil[2*h + 1] = b_gates[HID + h];
        }
        return;
    }
    if (blk >= WT_B5) {
        const long i = (long)(blk - WT_B5) * 256 + t;
        float4 v = ((const float4*)x)[i];
        ((__half2*)g_xr)[2*i]   = __floats2half2_rn(v.x, v.y);
        ((__half2*)g_xr)[2*i+1] = __floats2half2_rn(v.z, v.w);
        return;
    }
    const float* W; __half* WT; int K, N, il = 0; long base;
    if (blk < WT_B1)      { W = w_in;    WT = g_wiT; K = DMODEL; N = HID2;   base = (long)(blk - WT_B0) * 256; }
    else if (blk < WT_B2) { W = w_gates; WT = g_wgT; K = HID;    N = HID2;   base = (long)(blk - WT_B1) * 256; il = 1; }
    else if (blk < WT_B3) { W = w_out;   WT = g_woT; K = HID;    N = DMODEL; base = (long)(blk - WT_B2) * 256; }
    else if (blk < WT_B4) { W = ffn_w1;  WT = g_f1T; K = DMODEL; N = INNER;  base = (long)(blk - WT_B3) * 256; }
    else                  { W = ffn_w2;  WT = g_f2T; K = INNER;  N = DMODEL; base = (long)(blk - WT_B4) * 256; }
    const long i = base + t;
    const int k = (int)(i % K);
    const int n = (int)(i / K);
    const int col = il ? ((n >> 1) + (n & 1) * HID) : n;
    WT[i] = __float2half_rn(W[(long)k * N + col]);
}

// ---------------------------------------------------------------------------
// Sliding-window causal depthwise conv (K=4) + bias + silu. b0 = batch offset
// ---------------------------------------------------------------------------
__global__ __launch_bounds__(256)
void conv_silu_kernel(const float* __restrict__ conv_w,
                      const float* __restrict__ conv_b, int b0)
{
    const int h2 = threadIdx.x;
    const int b  = b0 + blockIdx.y;
    const int t0 = blockIdx.x * CONV_CHUNK;
    const int h  = h2 << 1;

    const float4 wa = *(const float4*)&conv_w[h * 4];
    const float4 wb = *(const float4*)&conv_w[h * 4 + 4];
    const float  ca = conv_b[h], cb = conv_b[h + 1];

    const __half2* xz = (const __half2*)g_xzh;
    const long rs = HID2 / 2;
    long base = ((long)b * SEQ + t0) * rs + h2;

    float a0 = 0.f, a1 = 0.f, a2 = 0.f;
    float b0f = 0.f, b1f = 0.f, b2f = 0.f;
    if (t0 >= 3) {
        __half2 p;
        p = xz[base - 3*rs]; a0 = __low2float(p); b0f = __high2float(p);
        p = xz[base - 2*rs]; a1 = __low2float(p); b1f = __high2float(p);
        p = xz[base - 1*rs]; a2 = __low2float(p); b2f = __high2float(p);
    }

    __half2* xcp = (__half2*)g_xc;
    long ob = ((long)b * SEQ + t0) * (HID / 2) + h2;

#pragma unroll 4
    for (int t = 0; t < CONV_CHUNK; t++) {
        const __half2 cur = xz[base]; base += rs;
        const float xa = __low2float(cur), xb = __high2float(cur);
        float va = ca, vb = cb;
        va = fmaf(wa.x, a0, va); va = fmaf(wa.y, a1, va);
        va = fmaf(wa.z, a2, va); va = fmaf(wa.w, xa, va);
        vb = fmaf(wb.x, b0f, vb); vb = fmaf(wb.y, b1f, vb);
        vb = fmaf(wb.z, b2f, vb); vb = fmaf(wb.w, xb, vb);
        a0 = a1; a1 = a2; a2 = xa;
        b0f = b1f; b1f = b2f; b2f = xb;
        va = __fdividef(va, 1.f + __expf(-va));
        vb = __fdividef(vb, 1.f + __expf(-vb));
        xcp[ob] = __floats2half2_rn(va, vb);
        ob += HID / 2;
    }
}

// ---------------------------------------------------------------------------
// scanC: 2 channels per thread; carry recomputed in-block. b0 = batch offset
// ---------------------------------------------------------------------------
__global__ __launch_bounds__(256)
void scanC_kernel(int b0)
{
    const int tid = threadIdx.x;
    const int c = blockIdx.x % NC;
    const int b = b0 + blockIdx.x / NC;
    const int h = tid << 1;

    float hx = 0.f, hy = 0.f;
    for (int j = 0; j < c; j++) {
        const int i = (b*NC + j)*HID + h;
        const float2 a  = *(const float2*)&g_cA[i];
        const float2 bb = *(const float2*)&g_cB[i];
        hx = fmaf(a.x, hx, bb.x);
        hy = fmaf(a.y, hy, bb.y);
    }

    long base  = ((long)b*SEQ + c*CLEN)*HID  + h;
    long zbase = ((long)b*SEQ + c*CLEN)*HID2 + HID + h;
    for (int t = 0; t < CLEN; t++) {
        const uint2 pk2 = *(const uint2*)&g_ab[base];
        const __half2 p0 = *(const __half2*)&pk2.x;
        const __half2 p1 = *(const __half2*)&pk2.y;
        const float om0 = __low2float(p0), bp0 = __high2float(p0);
        const float om1 = __low2float(p1), bp1 = __high2float(p1);
        hx = fmaf(-om0, hx, hx) + bp0;
        hy = fmaf(-om1, hy, hy) + bp1;
        const __half2 zz = *(const __half2*)&g_xzh[zbase];
        const float z0 = __low2float(zz), z1 = __high2float(zz);
        const float s0 = __fdividef(z0, 1.f + __expf(-z0));
        const float s1 = __fdividef(z1, 1.f + __expf(-z1));
        *(__half2*)&g_y[base] = __floats2half2_rn(s0 * hx, s1 * hy);
        base  += HID;
        zbase += HID2;
    }
}

// ---------------------------------------------------------------------------
// Launch: two fully independent half-batch pipelines on two streams
// ---------------------------------------------------------------------------
extern "C" void kernel_launch(void* const* d_in, const int* in_sizes, int n_in,
                              void* d_out, int out_size)
{
    const float* x      = (const float*)d_in[0];
    const float* w_in   = (const float*)d_in[1];
    const float* conv_w = (const float*)d_in[2];
    const float* conv_b = (const float*)d_in[3];
    const float* w_gates= (const float*)d_in[4];
    const float* b_gates= (const float*)d_in[5];
    const float* Lambda = (const float*)d_in[6];
    const float* w_out  = (const float*)d_in[7];
    const float* ln1_g  = (const float*)d_in[8];
    const float* ln1_b  = (const float*)d_in[9];
    const float* ffn_w1 = (const float*)d_in[10];
    const float* ffn_b1 = (const float*)d_in[11];
    const float* ffn_w2 = (const float*)d_in[12];
    const float* ffn_b2 = (const float*)d_in[13];
    const float* ln2_g  = (const float*)d_in[14];
    const float* ln2_b  = (const float*)d_in[15];
    float* dout = (float*)d_out;

    static cudaStream_t s2 = nullptr;
    static cudaEvent_t evFork = nullptr, evB = nullptr;
    static bool init_done = false;
    if (!init_done) {
        cudaFuncSetAttribute(mma_gemm,    cudaFuncAttributeMaxDynamicSharedMemorySize, GEMM_SMEM);
        cudaFuncSetAttribute(mma_gemm_ln, cudaFuncAttributeMaxDynamicSharedMemorySize, LN_SMEM);
        cudaStreamCreateWithFlags(&s2, cudaStreamNonBlocking);
        cudaEventCreateWithFlags(&evFork, cudaEventDisableTiming);
        cudaEventCreateWithFlags(&evB,    cudaEventDisableTiming);
        init_done = true;
    }

    float *hs;
    __half *xzh, *xr, *xc, *y, *hsh, *ff1, *wiT, *wgT, *woT, *f1T, *f2T;
    cudaGetSymbolAddress((void**)&hs,  g_hs);
    cudaGetSymbolAddress((void**)&xzh, g_xzh);
    cudaGetSymbolAddress((void**)&xr,  g_xr);
    cudaGetSymbolAddress((void**)&xc,  g_xc);
    cudaGetSymbolAddress((void**)&y,   g_y);
    cudaGetSymbolAddress((void**)&hsh, g_hsh);
    cudaGetSymbolAddress((void**)&ff1, g_ff1);
    cudaGetSymbolAddress((void**)&wiT, g_wiT);
    cudaGetSymbolAddress((void**)&wgT, g_wgT);
    cudaGetSymbolAddress((void**)&woT, g_woT);
    cudaGetSymbolAddress((void**)&f1T, g_f1T);
    cudaGetSymbolAddress((void**)&f2T, g_f2T);

    const size_t oD = (size_t)HROWS * DMODEL;
    const size_t oH = (size_t)HROWS * HID;
    const size_t oZ = (size_t)HROWS * HID2;
    const size_t oI = (size_t)HROWS * INNER;

    prep_kernel<<<WT_B6, 256>>>(Lambda, b_gates, w_in, w_gates, w_out,
                                ffn_w1, ffn_w2, x);
    cudaEventRecord(evFork, 0);
    cudaStreamWaitEvent(s2, evFork, 0);

    // ================= half A (batches 0..15) on main stream =================
    mma_gemm<<<dim3(4, HROWS/128), 256, GEMM_SMEM>>>(            // xh_A
        xr, wiT, HROWS, HID2, DMODEL, 0, 0, nullptr, 0, nullptr, xzh);
    conv_silu_kernel<<<dim3(SEQ/CONV_CHUNK, HBATCH), 256>>>(conv_w, conv_b, 0);
    mma_gemm<<<dim3(HID2/128, HROWS/128), 256, GEMM_SMEM>>>(     // gates_A
        xc, wgT, HROWS, HID2, HID, 0, 0, nullptr, 2, nullptr, nullptr);
    mma_gemm<<<dim3(4, HROWS/128), 256, GEMM_SMEM>>>(            // z_A
        xr, wiT, HROWS, HID2, DMODEL, 512, 0, nullptr, 0, nullptr, xzh);
    scanC_kernel<<<HBATCH*NC, 256>>>(0);
    mma_gemm_ln<<<dim3(1, HROWS/128), 512, LN_SMEM>>>(           // LN1_A
        y, woT, HID, nullptr, x, ln1_g, ln1_b, hs, hsh);
    mma_gemm<<<dim3(INNER/128, HROWS/128), 256, GEMM_SMEM>>>(    // ffn1_A
        hsh, f1T, HROWS, INNER, DMODEL, 0, 0, ffn_b1, 1, nullptr, ff1);
    mma_gemm_ln<<<dim3(1, HROWS/128), 512, LN_SMEM>>>(           // ffn2_A
        ff1, f2T, INNER, ffn_b2, hs, ln2_g, ln2_b, dout, nullptr);

    // ================= half B (batches 16..31) on side stream ================
    mma_gemm<<<dim3(4, HROWS/128), 256, GEMM_SMEM, s2>>>(        // z_B
        xr + oD, wiT, HROWS, HID2, DMODEL, 512, 0, nullptr, 0, nullptr, xzh + oZ);
    mma_gemm<<<dim3(4, HROWS/128), 256, GEMM_SMEM, s2>>>(        // xh_B
        xr + oD, wiT, HROWS, HID2, DMODEL, 0, 0, nullptr, 0, nullptr, xzh + oZ);
    conv_silu_kernel<<<dim3(SEQ/CONV_CHUNK, HBATCH), 256, 0, s2>>>(conv_w, conv_b, HBATCH);
    mma_gemm<<<dim3(HID2/128, HROWS/128), 256, GEMM_SMEM, s2>>>( // gates_B
        xc + oH, wgT, HROWS, HID2, HID, 0, HROWS, nullptr, 2, nullptr, nullptr);
    scanC_kernel<<<HBATCH*NC, 256, 0, s2>>>(HBATCH);
    mma_gemm_ln<<<dim3(1, HROWS/128), 512, LN_SMEM, s2>>>(       // LN1_B
        y + oH, woT, HID, nullptr, x + oD, ln1_g, ln1_b, hs + oD, hsh + oD);
    mma_gemm<<<dim3(INNER/128, HROWS/128), 256, GEMM_SMEM, s2>>>(// ffn1_B
        hsh + oD, f1T, HROWS, INNER, DMODEL, 0, 0, ffn_b1, 1, nullptr, ff1 + oI);
    mma_gemm_ln<<<dim3(1, HROWS/128), 512, LN_SMEM, s2>>>(       // ffn2_B
        ff1 + oI, f2T, INNER, ffn_b2, hs + oD, ln2_g, ln2_b, dout + oD, nullptr);
    cudaEventRecord(evB, s2);

    cudaStreamWaitEvent(0, evB, 0);
}